// round 1
// baseline (speedup 1.0000x reference)
#include <cuda_runtime.h>
#include <math.h>

// Problem constants
constexpr int Bc = 16, Nc = 512, Dc = 512, Hc = 8, DKc = 64;
constexpr int Mrows = Bc * Nc;          // 8192
constexpr float SCALE = 0.125f;          // DK^-0.5
constexpr float LN_EPS = 1e-5f;

// Scratch (static device arrays; no allocation allowed)
__device__ float g_h[Mrows * Dc];
__device__ float g_q[Mrows * Dc];
__device__ float g_k[Mrows * Dc];
__device__ float g_v[Mrows * Dc];
__device__ float g_ctx[Mrows * Dc];
__device__ float g_h2[Mrows * Dc];

// ---------------------------------------------------------------------------
// GEMM: C[M,512] = A[M,512] @ W[512,512] + bias, optional relu.
// Tile 128x64, BK=16, 256 threads, 8x4 per-thread micro-tile, reg prefetch.
// ---------------------------------------------------------------------------
template<bool RELU>
__global__ void __launch_bounds__(256, 2) gemm_bias_kernel(
    const float* __restrict__ A, const float* __restrict__ W,
    const float* __restrict__ bias, float* __restrict__ C)
{
    constexpr int K = 512, Nout = 512;
    __shared__ float As[16][128];   // k-major
    __shared__ float Bs[16][64];    // k-major

    const int tid = threadIdx.x;
    const int tx = tid & 15;        // col group
    const int ty = tid >> 4;        // row group
    const int m0 = blockIdx.y * 128;
    const int n0 = blockIdx.x * 64;

    const int arow = tid >> 2;             // 0..63
    const int ak4  = (tid & 3) << 2;       // 0,4,8,12
    const int brow = tid >> 4;             // 0..15
    const int bn4  = (tid & 15) << 2;      // 0..60

    const float* Ag = A + (size_t)m0 * K;
    const float* Wg = W + n0;

    float4 pa0 = *(const float4*)(Ag + (size_t)arow * K + ak4);
    float4 pa1 = *(const float4*)(Ag + (size_t)(arow + 64) * K + ak4);
    float4 pb  = *(const float4*)(Wg + (size_t)brow * Nout + bn4);

    float acc[8][4] = {};

    constexpr int NK = K / 16;
    for (int kt = 0; kt < NK; kt++) {
        As[ak4 + 0][arow] = pa0.x;
        As[ak4 + 1][arow] = pa0.y;
        As[ak4 + 2][arow] = pa0.z;
        As[ak4 + 3][arow] = pa0.w;
        As[ak4 + 0][arow + 64] = pa1.x;
        As[ak4 + 1][arow + 64] = pa1.y;
        As[ak4 + 2][arow + 64] = pa1.z;
        As[ak4 + 3][arow + 64] = pa1.w;
        *(float4*)&Bs[brow][bn4] = pb;
        __syncthreads();

        if (kt + 1 < NK) {
            const float* Ag2 = Ag + (kt + 1) * 16;
            pa0 = *(const float4*)(Ag2 + (size_t)arow * K + ak4);
            pa1 = *(const float4*)(Ag2 + (size_t)(arow + 64) * K + ak4);
            pb  = *(const float4*)(Wg + (size_t)((kt + 1) * 16 + brow) * Nout + bn4);
        }

        #pragma unroll
        for (int kk = 0; kk < 16; kk++) {
            float a[8];
            #pragma unroll
            for (int i = 0; i < 8; i++) a[i] = As[kk][ty * 8 + i];
            float4 b4 = *(const float4*)&Bs[kk][tx * 4];
            float bb[4] = {b4.x, b4.y, b4.z, b4.w};
            #pragma unroll
            for (int i = 0; i < 8; i++)
                #pragma unroll
                for (int j = 0; j < 4; j++)
                    acc[i][j] += a[i] * bb[j];
        }
        __syncthreads();
    }

    float4 bvv = *(const float4*)(bias + n0 + tx * 4);
    float bb[4] = {bvv.x, bvv.y, bvv.z, bvv.w};
    #pragma unroll
    for (int i = 0; i < 8; i++) {
        int m = m0 + ty * 8 + i;
        float4 o;
        o.x = acc[i][0] + bb[0];
        o.y = acc[i][1] + bb[1];
        o.z = acc[i][2] + bb[2];
        o.w = acc[i][3] + bb[3];
        if (RELU) {
            o.x = fmaxf(o.x, 0.f); o.y = fmaxf(o.y, 0.f);
            o.z = fmaxf(o.z, 0.f); o.w = fmaxf(o.w, 0.f);
        }
        *(float4*)(C + (size_t)m * Nout + n0 + tx * 4) = o;
    }
}

// ---------------------------------------------------------------------------
// In-place LayerNorm over rows of length 512. One warp per row.
// ---------------------------------------------------------------------------
__global__ void ln_kernel(float* __restrict__ h,
                          const float* __restrict__ g, const float* __restrict__ b)
{
    int warp = (blockIdx.x * blockDim.x + threadIdx.x) >> 5;
    int lane = threadIdx.x & 31;
    if (warp >= Mrows) return;
    float* row = h + (size_t)warp * Dc;

    float vals[16];
    float s = 0.f;
    #pragma unroll
    for (int i = 0; i < 16; i++) { vals[i] = row[lane + i * 32]; s += vals[i]; }
    #pragma unroll
    for (int o = 16; o > 0; o >>= 1) s += __shfl_xor_sync(0xffffffffu, s, o);
    float mu = s * (1.f / 512.f);

    float vsum = 0.f;
    #pragma unroll
    for (int i = 0; i < 16; i++) { float d = vals[i] - mu; vsum += d * d; }
    #pragma unroll
    for (int o = 16; o > 0; o >>= 1) vsum += __shfl_xor_sync(0xffffffffu, vsum, o);
    float inv = rsqrtf(vsum * (1.f / 512.f) + LN_EPS);

    #pragma unroll
    for (int i = 0; i < 16; i++) {
        int c = lane + i * 32;
        row[c] = (vals[i] - mu) * inv * g[c] + b[c];
    }
}

// ---------------------------------------------------------------------------
// Flash-style attention. Block = (b, h, 64-row q tile). 256 threads.
// IMPORTANT semantic: reference does where(adj>0, s, NEG)*adj, so a masked
// entry's logit is exactly 0.0, NOT -inf. We replicate that.
// ---------------------------------------------------------------------------
__global__ void __launch_bounds__(256, 2) attn_kernel(
    const float* __restrict__ q, const float* __restrict__ k, const float* __restrict__ v,
    const float* __restrict__ adj, const int* __restrict__ use_adj_p,
    float* __restrict__ ctx)
{
    extern __shared__ float sm[];
    float* Qs   = sm;             // [64][64], d-major: Qs[d*64 + r]
    float* Ks   = Qs + 4096;      // d-major:  Ks[d*64 + c]
    float* Vs   = Ks + 4096;      // row-major: Vs[kv*64 + d]
    float* Ss   = Vs + 4096;      // [64][65] padded
    float* mrow = Ss + 64 * 65;   // [64]
    float* lrow = mrow + 64;      // [64]
    float* arow = lrow + 64;      // [64]

    const int b = blockIdx.z, h = blockIdx.y;
    const int q0 = blockIdx.x * 64;
    const int tid = threadIdx.x;
    const int tx = tid & 15, ty = tid >> 4;
    const bool mask = (*use_adj_p) != 0;

    // Load Q tile transposed to d-major
    for (int i = tid; i < 1024; i += 256) {
        int d4 = (i >> 6) << 2;
        int r = i & 63;
        float4 t = *(const float4*)(q + ((size_t)(b * Nc + q0 + r)) * Dc + h * DKc + d4);
        Qs[(d4 + 0) * 64 + r] = t.x;
        Qs[(d4 + 1) * 64 + r] = t.y;
        Qs[(d4 + 2) * 64 + r] = t.z;
        Qs[(d4 + 3) * 64 + r] = t.w;
    }
    if (tid < 64) { mrow[tid] = -INFINITY; lrow[tid] = 0.f; }
    __syncthreads();

    float O[4][4] = {};
    const int row = tid >> 2, lq = tid & 3;

    for (int kt = 0; kt < 8; kt++) {
        const int k0 = kt * 64;
        // K transposed (d-major), V row-major
        for (int i = tid; i < 1024; i += 256) {
            int d4 = (i >> 6) << 2;
            int r = i & 63;
            float4 tk = *(const float4*)(k + ((size_t)(b * Nc + k0 + r)) * Dc + h * DKc + d4);
            Ks[(d4 + 0) * 64 + r] = tk.x;
            Ks[(d4 + 1) * 64 + r] = tk.y;
            Ks[(d4 + 2) * 64 + r] = tk.z;
            Ks[(d4 + 3) * 64 + r] = tk.w;
        }
        for (int i = tid; i < 1024; i += 256) {
            int r = i >> 4;
            int d4 = (i & 15) << 2;
            *(float4*)&Vs[r * 64 + d4] =
                *(const float4*)(v + ((size_t)(b * Nc + k0 + r)) * Dc + h * DKc + d4);
        }
        __syncthreads();

        // S = Q @ K^T (4x4 per-thread tile)
        float s[4][4] = {};
        #pragma unroll
        for (int d = 0; d < 64; d++) {
            float a[4];
            #pragma unroll
            for (int i = 0; i < 4; i++) a[i] = Qs[d * 64 + ty * 4 + i];
            float4 b4 = *(const float4*)&Ks[d * 64 + tx * 4];
            float bb[4] = {b4.x, b4.y, b4.z, b4.w};
            #pragma unroll
            for (int i = 0; i < 4; i++)
                #pragma unroll
                for (int j = 0; j < 4; j++)
                    s[i][j] += a[i] * bb[j];
        }

        // Scale + "mask" (masked logit = 0.0, matching reference NEG*0 = -0.0)
        #pragma unroll
        for (int i = 0; i < 4; i++) {
            int gq = q0 + ty * 4 + i;
            float4 av = make_float4(1.f, 1.f, 1.f, 1.f);
            if (mask)
                av = *(const float4*)(adj + ((size_t)b * Nc + gq) * Nc + k0 + tx * 4);
            float* srow = &Ss[(ty * 4 + i) * 65 + tx * 4];
            srow[0] = (av.x > 0.f) ? s[i][0] * SCALE : 0.f;
            srow[1] = (av.y > 0.f) ? s[i][1] * SCALE : 0.f;
            srow[2] = (av.z > 0.f) ? s[i][2] * SCALE : 0.f;
            srow[3] = (av.w > 0.f) ? s[i][3] * SCALE : 0.f;
        }
        __syncthreads();

        // Online softmax update: 4 threads per row
        float sv[16];
        float mloc = -INFINITY;
        #pragma unroll
        for (int c = 0; c < 16; c++) {
            sv[c] = Ss[row * 65 + lq + c * 4];
            mloc = fmaxf(mloc, sv[c]);
        }
        mloc = fmaxf(mloc, __shfl_xor_sync(0xffffffffu, mloc, 1));
        mloc = fmaxf(mloc, __shfl_xor_sync(0xffffffffu, mloc, 2));
        float mprev = mrow[row];
        float mnew = fmaxf(mprev, mloc);
        float psum = 0.f;
        #pragma unroll
        for (int c = 0; c < 16; c++) {
            float p = __expf(sv[c] - mnew);
            Ss[row * 65 + lq + c * 4] = p;
            psum += p;
        }
        psum += __shfl_xor_sync(0xffffffffu, psum, 1);
        psum += __shfl_xor_sync(0xffffffffu, psum, 2);
        if (lq == 0) {
            float al = __expf(mprev - mnew);
            arow[row] = al;
            lrow[row] = lrow[row] * al + psum;
            mrow[row] = mnew;
        }
        __syncthreads();

        // O = O*alpha + P @ V
        float alpha[4];
        #pragma unroll
        for (int i = 0; i < 4; i++) alpha[i] = arow[ty * 4 + i];
        #pragma unroll
        for (int i = 0; i < 4; i++)
            #pragma unroll
            for (int j = 0; j < 4; j++)
                O[i][j] *= alpha[i];
        #pragma unroll
        for (int kv = 0; kv < 64; kv++) {
            float p[4];
            #pragma unroll
            for (int i = 0; i < 4; i++) p[i] = Ss[(ty * 4 + i) * 65 + kv];
            float4 v4 = *(const float4*)&Vs[kv * 64 + tx * 4];
            float vv[4] = {v4.x, v4.y, v4.z, v4.w};
            #pragma unroll
            for (int i = 0; i < 4; i++)
                #pragma unroll
                for (int j = 0; j < 4; j++)
                    O[i][j] += p[i] * vv[j];
        }
        __syncthreads();
    }

    // Normalize and store ctx
    #pragma unroll
    for (int i = 0; i < 4; i++) {
        float inv = 1.f / lrow[ty * 4 + i];
        int gq = q0 + ty * 4 + i;
        float4 o;
        o.x = O[i][0] * inv;
        o.y = O[i][1] * inv;
        o.z = O[i][2] * inv;
        o.w = O[i][3] * inv;
        *(float4*)(ctx + ((size_t)(b * Nc + gq)) * Dc + h * DKc + tx * 4) = o;
    }
}

// ---------------------------------------------------------------------------
// Gate: coeff = sigmoid([x,h2] . gate_w + gate_b); out = c*x + (1-c)*h2.
// One warp per token.
// ---------------------------------------------------------------------------
__global__ void gate_kernel(const float* __restrict__ x, const float* __restrict__ h2,
                            const float* __restrict__ gw, const float* __restrict__ gb,
                            float* __restrict__ out)
{
    int warp = (blockIdx.x * blockDim.x + threadIdx.x) >> 5;
    int lane = threadIdx.x & 31;
    if (warp >= Mrows) return;
    const float* xr = x + (size_t)warp * Dc;
    const float* hr = h2 + (size_t)warp * Dc;

    float dot = 0.f;
    #pragma unroll
    for (int i = 0; i < 16; i++) {
        int c = lane + i * 32;
        dot += xr[c] * gw[c] + hr[c] * gw[Dc + c];
    }
    #pragma unroll
    for (int o = 16; o > 0; o >>= 1) dot += __shfl_xor_sync(0xffffffffu, dot, o);

    float z = dot + gb[0];
    float cf = 1.f / (1.f + __expf(-z));
    #pragma unroll
    for (int i = 0; i < 16; i++) {
        int c = lane + i * 32;
        out[(size_t)warp * Dc + c] = cf * xr[c] + (1.f - cf) * hr[c];
    }
}

// ---------------------------------------------------------------------------
extern "C" void kernel_launch(void* const* d_in, const int* in_sizes, int n_in,
                              void* d_out, int out_size)
{
    const float* x    = (const float*)d_in[0];
    const float* adj  = (const float*)d_in[1];
    const float* W_w  = (const float*)d_in[2];
    const float* W_b  = (const float*)d_in[3];
    const float* ln_g = (const float*)d_in[4];
    const float* ln_b = (const float*)d_in[5];
    const float* Wq   = (const float*)d_in[6];
    const float* bq   = (const float*)d_in[7];
    const float* Wk   = (const float*)d_in[8];
    const float* bk   = (const float*)d_in[9];
    const float* Wv   = (const float*)d_in[10];
    const float* bv   = (const float*)d_in[11];
    const float* Wo   = (const float*)d_in[12];
    const float* bo   = (const float*)d_in[13];
    const float* gw   = (const float*)d_in[14];
    const float* gb   = (const float*)d_in[15];
    const int* use_adj = (const int*)d_in[16];
    float* out = (float*)d_out;

    float *h, *q, *k, *v, *ctx, *h2;
    cudaGetSymbolAddress((void**)&h,   g_h);
    cudaGetSymbolAddress((void**)&q,   g_q);
    cudaGetSymbolAddress((void**)&k,   g_k);
    cudaGetSymbolAddress((void**)&v,   g_v);
    cudaGetSymbolAddress((void**)&ctx, g_ctx);
    cudaGetSymbolAddress((void**)&h2,  g_h2);

    const int ATTN_SMEM = (4096 * 3 + 64 * 65 + 3 * 64) * (int)sizeof(float); // 66560 B
    cudaFuncSetAttribute(attn_kernel, cudaFuncAttributeMaxDynamicSharedMemorySize, ATTN_SMEM);

    dim3 ggrid(Dc / 64, Mrows / 128);   // (8, 64)

    // 1) h = x @ W_w + W_b
    gemm_bias_kernel<false><<<ggrid, 256>>>(x, W_w, W_b, h);
    // 2) h = LN(h)
    ln_kernel<<<Mrows / 8, 256>>>(h, ln_g, ln_b);
    // 3) q, k, v
    gemm_bias_kernel<false><<<ggrid, 256>>>(h, Wq, bq, q);
    gemm_bias_kernel<false><<<ggrid, 256>>>(h, Wk, bk, k);
    gemm_bias_kernel<false><<<ggrid, 256>>>(h, Wv, bv, v);
    // 4) attention -> ctx
    dim3 agrid(Nc / 64, Hc, Bc);        // (8, 8, 16)
    attn_kernel<<<agrid, 256, ATTN_SMEM>>>(q, k, v, adj, use_adj, ctx);
    // 5) h2 = relu(ctx @ Wo + bo)
    gemm_bias_kernel<true><<<ggrid, 256>>>(ctx, Wo, bo, h2);
    // 6) gated residual output
    gate_kernel<<<Mrows / 8, 256>>>(x, h2, gw, gb, out);
}

// round 3
// speedup vs baseline: 1.4794x; 1.4794x over previous
#include <cuda_runtime.h>
#include <cuda_bf16.h>
#include <math.h>
#include <cstdint>

// Problem constants
constexpr int Bc = 16, Nc = 512, Dc = 512, Hc = 8, DKc = 64;
constexpr int Mrows = Bc * Nc;          // 8192
constexpr int QKV_LD = 3 * Dc;          // 1536
constexpr float SCALE = 0.125f;         // DK^-0.5
constexpr float LN_EPS = 1e-5f;

// ---------------------------------------------------------------------------
// Scratch (static device arrays; no allocation allowed)
// ---------------------------------------------------------------------------
__device__ float g_h[Mrows * Dc];
__device__ float g_h2[Mrows * Dc];
__device__ float g_qkv[Mrows * QKV_LD];
__device__ __nv_bfloat16 g_ahi[Mrows * Dc];
__device__ __nv_bfloat16 g_alo[Mrows * Dc];
__device__ __nv_bfloat16 g_whi[3 * Dc * Dc];   // transposed weights [N][K], up to 3 packed
__device__ __nv_bfloat16 g_wlo[3 * Dc * Dc];
__device__ float g_bias3[QKV_LD];

// ---------------------------------------------------------------------------
// fp32 -> bf16 hi/lo split (elementwise, vectorized)
// ---------------------------------------------------------------------------
__global__ void split_kernel(const float* __restrict__ x,
                             __nv_bfloat16* __restrict__ hi, __nv_bfloat16* __restrict__ lo,
                             int n4) {
    int i = blockIdx.x * blockDim.x + threadIdx.x;
    if (i >= n4) return;
    float4 v = ((const float4*)x)[i];
    __nv_bfloat16 h0 = __float2bfloat16(v.x), h1 = __float2bfloat16(v.y);
    __nv_bfloat16 h2 = __float2bfloat16(v.z), h3 = __float2bfloat16(v.w);
    __nv_bfloat16 l0 = __float2bfloat16(v.x - __bfloat162float(h0));
    __nv_bfloat16 l1 = __float2bfloat16(v.y - __bfloat162float(h1));
    __nv_bfloat16 l2 = __float2bfloat16(v.z - __bfloat162float(h2));
    __nv_bfloat16 l3 = __float2bfloat16(v.w - __bfloat162float(h3));
    ((__nv_bfloat162*)hi)[2 * i]     = __nv_bfloat162(h0, h1);
    ((__nv_bfloat162*)hi)[2 * i + 1] = __nv_bfloat162(h2, h3);
    ((__nv_bfloat162*)lo)[2 * i]     = __nv_bfloat162(l0, l1);
    ((__nv_bfloat162*)lo)[2 * i + 1] = __nv_bfloat162(l2, l3);
}

// ---------------------------------------------------------------------------
// W [K=512, N=512] row-major -> transposed hi/lo bf16 [N, K]
// ---------------------------------------------------------------------------
__global__ void tsplit_kernel(const float* __restrict__ W,
                              __nv_bfloat16* __restrict__ hi, __nv_bfloat16* __restrict__ lo) {
    __shared__ float t[32][33];
    const int bx = blockIdx.x * 32;   // n block
    const int by = blockIdx.y * 32;   // k block
    const int tx = threadIdx.x, ty = threadIdx.y;   // 32 x 8
    #pragma unroll
    for (int j = 0; j < 32; j += 8)
        t[ty + j][tx] = W[(size_t)(by + ty + j) * Dc + bx + tx];
    __syncthreads();
    #pragma unroll
    for (int j = 0; j < 32; j += 8) {
        float v = t[tx][ty + j];
        __nv_bfloat16 h = __float2bfloat16(v);
        size_t o = (size_t)(bx + ty + j) * Dc + by + tx;
        hi[o] = h;
        lo[o] = __float2bfloat16(v - __bfloat162float(h));
    }
}

__global__ void pack_bias3(const float* __restrict__ bq, const float* __restrict__ bk,
                           const float* __restrict__ bv, float* __restrict__ b3) {
    int i = blockIdx.x * blockDim.x + threadIdx.x;
    if (i < Dc) b3[i] = bq[i];
    else if (i < 2 * Dc) b3[i] = bk[i - Dc];
    else if (i < 3 * Dc) b3[i] = bv[i - 2 * Dc];
}

// ---------------------------------------------------------------------------
// mma.sync bf16 split GEMM:  C[8192, Ntot] = A[8192,512] @ Wt^T + bias
// A given as hi/lo bf16 [M,512]; Wt as hi/lo bf16 [Ntot,512] (k contiguous).
// 3-pass: hi*hi + hi*lo + lo*hi, fp32 accum. CTA tile 128x128, BK=32.
// 256 threads = 8 warps, warp tile 64x32 (4 m-tiles x 4 n-tiles of 16x8).
// ---------------------------------------------------------------------------
constexpr int GPAD = 40;                          // smem row stride (bf16 elems)
constexpr int GTILE_B = 128 * GPAD * 2;           // 10240 bytes per operand tile
constexpr int GSTAGE_B = 4 * GTILE_B;             // Ahi,Alo,Bhi,Blo = 40960
constexpr int GEMM_SMEM = 2 * GSTAGE_B;           // 81920

__device__ __forceinline__ uint32_t smem_u32(const void* p) {
    uint32_t a;
    asm("{ .reg .u64 t; cvta.to.shared.u64 t, %1; cvt.u32.u64 %0, t; }" : "=r"(a) : "l"(p));
    return a;
}
__device__ __forceinline__ void ldmx4(uint32_t* r, uint32_t addr) {
    asm volatile("ldmatrix.sync.aligned.m8n8.x4.shared.b16 {%0,%1,%2,%3}, [%4];"
                 : "=r"(r[0]), "=r"(r[1]), "=r"(r[2]), "=r"(r[3]) : "r"(addr));
}
__device__ __forceinline__ void ldmx2(uint32_t* r, uint32_t addr) {
    asm volatile("ldmatrix.sync.aligned.m8n8.x2.shared.b16 {%0,%1}, [%2];"
                 : "=r"(r[0]), "=r"(r[1]) : "r"(addr));
}
__device__ __forceinline__ void mma16816(float* c, const uint32_t* a, const uint32_t* b) {
    asm volatile("mma.sync.aligned.m16n8k16.row.col.f32.bf16.bf16.f32 "
                 "{%0,%1,%2,%3}, {%4,%5,%6,%7}, {%8,%9}, {%0,%1,%2,%3};"
                 : "+f"(c[0]), "+f"(c[1]), "+f"(c[2]), "+f"(c[3])
                 : "r"(a[0]), "r"(a[1]), "r"(a[2]), "r"(a[3]), "r"(b[0]), "r"(b[1]));
}

template<bool RELU>
__global__ void __launch_bounds__(256, 1) mma_gemm_kernel(
    const __nv_bfloat16* __restrict__ Ahi, const __nv_bfloat16* __restrict__ Alo,
    const __nv_bfloat16* __restrict__ Bhi, const __nv_bfloat16* __restrict__ Blo,
    const float* __restrict__ bias, float* __restrict__ C, int ldc)
{
    extern __shared__ char smem[];
    const uint32_t sbase = smem_u32(smem);
    const int tid = threadIdx.x, wid = tid >> 5, lane = tid & 31;
    const int m0 = blockIdx.y * 128, n0 = blockIdx.x * 128;
    const int wm = wid & 1, wn = wid >> 1;          // 2 x 4 warp grid

    const __nv_bfloat16* srcs[4] = {Ahi, Alo, Bhi, Blo};

    // Per-lane ldmatrix base addresses (byte offsets inside a stage)
    // A: row = wm*64 + (lane&15) [+ itile*16], col = (lane<16?0:8) [+ kstep]
    const uint32_t aRow = wm * 64 + (lane & 15);
    const uint32_t aCol = (lane < 16) ? 0 : 8;
    const uint32_t aOffB = (aRow * GPAD + aCol) * 2;
    // B: row(n) = wn*32 + (lane&7) [+ jtile*8], col = ((lane>>3)&1)*8 [+ kstep]
    const uint32_t bRow = wn * 32 + (lane & 7);
    const uint32_t bCol = ((lane >> 3) & 1) * 8;
    const uint32_t bOffB = (bRow * GPAD + bCol) * 2;

    float acc[4][4][4] = {};
    uint4 pf[4][2];

    // prefetch chunk 0
    #pragma unroll
    for (int t = 0; t < 4; t++) {
        const __nv_bfloat16* src = srcs[t];
        const int base = (t < 2) ? m0 : n0;
        #pragma unroll
        for (int j = 0; j < 2; j++) {
            int s = tid + j * 256;
            int row = s >> 2, seg = s & 3;
            pf[t][j] = *(const uint4*)(src + (size_t)(base + row) * Dc + seg * 8);
        }
    }

    constexpr int NCH = Dc / 32;    // 16
    for (int c = 0; c < NCH; c++) {
        const int stage = c & 1;
        const uint32_t stOff = stage * GSTAGE_B;

        // store prefetched chunk to smem
        #pragma unroll
        for (int t = 0; t < 4; t++) {
            #pragma unroll
            for (int j = 0; j < 2; j++) {
                int s = tid + j * 256;
                int row = s >> 2, seg = s & 3;
                *(uint4*)(smem + stOff + t * GTILE_B + (row * GPAD + seg * 8) * 2) = pf[t][j];
            }
        }
        __syncthreads();

        // prefetch next chunk
        if (c + 1 < NCH) {
            const int k0 = (c + 1) * 32;
            #pragma unroll
            for (int t = 0; t < 4; t++) {
                const __nv_bfloat16* src = srcs[t];
                const int base = (t < 2) ? m0 : n0;
                #pragma unroll
                for (int j = 0; j < 2; j++) {
                    int s = tid + j * 256;
                    int row = s >> 2, seg = s & 3;
                    pf[t][j] = *(const uint4*)(src + (size_t)(base + row) * Dc + k0 + seg * 8);
                }
            }
        }

        // compute on this stage: 2 k-steps of 16
        const uint32_t sAhi = sbase + stOff + 0 * GTILE_B;
        const uint32_t sAlo = sbase + stOff + 1 * GTILE_B;
        const uint32_t sBhi = sbase + stOff + 2 * GTILE_B;
        const uint32_t sBlo = sbase + stOff + 3 * GTILE_B;

        #pragma unroll
        for (int ks = 0; ks < 2; ks++) {
            const uint32_t kOffB = ks * 16 * 2;
            uint32_t ahi[4][4], alo[4][4], bhi[4][2], blo[4][2];
            #pragma unroll
            for (int i = 0; i < 4; i++) {
                uint32_t ao = aOffB + kOffB + i * 16 * GPAD * 2;
                ldmx4(ahi[i], sAhi + ao);
                ldmx4(alo[i], sAlo + ao);
            }
            #pragma unroll
            for (int j = 0; j < 4; j++) {
                uint32_t bo = bOffB + kOffB + j * 8 * GPAD * 2;
                ldmx2(bhi[j], sBhi + bo);
                ldmx2(blo[j], sBlo + bo);
            }
            #pragma unroll
            for (int i = 0; i < 4; i++)
                #pragma unroll
                for (int j = 0; j < 4; j++) {
                    mma16816(acc[i][j], ahi[i], bhi[j]);
                    mma16816(acc[i][j], ahi[i], blo[j]);
                    mma16816(acc[i][j], alo[i], bhi[j]);
                }
        }
        __syncthreads();
    }

    // epilogue: c0,c1 -> (row lr, col lc..lc+1); c2,c3 -> row lr+8
    const int lr = lane >> 2, lc = (lane & 3) * 2;
    #pragma unroll
    for (int i = 0; i < 4; i++) {
        const int row0 = m0 + wm * 64 + i * 16 + lr;
        #pragma unroll
        for (int j = 0; j < 4; j++) {
            const int col = n0 + wn * 32 + j * 8 + lc;
            float b0 = bias[col], b1 = bias[col + 1];
            float2 o0 = make_float2(acc[i][j][0] + b0, acc[i][j][1] + b1);
            float2 o1 = make_float2(acc[i][j][2] + b0, acc[i][j][3] + b1);
            if (RELU) {
                o0.x = fmaxf(o0.x, 0.f); o0.y = fmaxf(o0.y, 0.f);
                o1.x = fmaxf(o1.x, 0.f); o1.y = fmaxf(o1.y, 0.f);
            }
            *(float2*)(C + (size_t)row0 * ldc + col) = o0;
            *(float2*)(C + (size_t)(row0 + 8) * ldc + col) = o1;
        }
    }
}

// ---------------------------------------------------------------------------
// LayerNorm over rows of 512, writing bf16 hi/lo split directly.
// ---------------------------------------------------------------------------
__global__ void ln_split_kernel(const float* __restrict__ hsrc,
                                const float* __restrict__ g, const float* __restrict__ b,
                                __nv_bfloat16* __restrict__ hi, __nv_bfloat16* __restrict__ lo)
{
    int warp = (blockIdx.x * blockDim.x + threadIdx.x) >> 5;
    int lane = threadIdx.x & 31;
    if (warp >= Mrows) return;
    const float* row = hsrc + (size_t)warp * Dc;

    float vals[16];
    float s = 0.f;
    #pragma unroll
    for (int i = 0; i < 16; i++) { vals[i] = row[lane + i * 32]; s += vals[i]; }
    #pragma unroll
    for (int o = 16; o > 0; o >>= 1) s += __shfl_xor_sync(0xffffffffu, s, o);
    float mu = s * (1.f / 512.f);

    float vsum = 0.f;
    #pragma unroll
    for (int i = 0; i < 16; i++) { float d = vals[i] - mu; vsum += d * d; }
    #pragma unroll
    for (int o = 16; o > 0; o >>= 1) vsum += __shfl_xor_sync(0xffffffffu, vsum, o);
    float inv = rsqrtf(vsum * (1.f / 512.f) + LN_EPS);

    #pragma unroll
    for (int i = 0; i < 16; i++) {
        int c = lane + i * 32;
        float v = (vals[i] - mu) * inv * g[c] + b[c];
        __nv_bfloat16 h = __float2bfloat16(v);
        hi[(size_t)warp * Dc + c] = h;
        lo[(size_t)warp * Dc + c] = __float2bfloat16(v - __bfloat162float(h));
    }
}

// ---------------------------------------------------------------------------
// Flash-style attention on packed qkv (row stride 1536). Writes ctx hi/lo split.
// Masked logit = exactly 0.0 (matching reference where(adj>0,s,NEG)*adj).
// ---------------------------------------------------------------------------
__global__ void __launch_bounds__(256, 2) attn_kernel(
    const float* __restrict__ qkv, const float* __restrict__ adj,
    const int* __restrict__ use_adj_p,
    __nv_bfloat16* __restrict__ chi, __nv_bfloat16* __restrict__ clo)
{
    extern __shared__ float sm[];
    float* Qs   = sm;
    float* Ks   = Qs + 4096;
    float* Vs   = Ks + 4096;
    float* Ss   = Vs + 4096;
    float* mrow = Ss + 64 * 65;
    float* lrow = mrow + 64;
    float* arow = lrow + 64;

    const int b = blockIdx.z, h = blockIdx.y;
    const int q0 = blockIdx.x * 64;
    const int tid = threadIdx.x;
    const int tx = tid & 15, ty = tid >> 4;
    const bool mask = (*use_adj_p) != 0;

    const float* qp = qkv + h * DKc;
    const float* kp = qkv + Dc + h * DKc;
    const float* vp = qkv + 2 * Dc + h * DKc;

    for (int i = tid; i < 1024; i += 256) {
        int d4 = (i >> 6) << 2;
        int r = i & 63;
        float4 t = *(const float4*)(qp + (size_t)(b * Nc + q0 + r) * QKV_LD + d4);
        Qs[(d4 + 0) * 64 + r] = t.x;
        Qs[(d4 + 1) * 64 + r] = t.y;
        Qs[(d4 + 2) * 64 + r] = t.z;
        Qs[(d4 + 3) * 64 + r] = t.w;
    }
    if (tid < 64) { mrow[tid] = -INFINITY; lrow[tid] = 0.f; }
    __syncthreads();

    float O[4][4] = {};
    const int row = tid >> 2, lq = tid & 3;

    for (int kt = 0; kt < 8; kt++) {
        const int k0 = kt * 64;
        for (int i = tid; i < 1024; i += 256) {
            int d4 = (i >> 6) << 2;
            int r = i & 63;
            float4 tk = *(const float4*)(kp + (size_t)(b * Nc + k0 + r) * QKV_LD + d4);
            Ks[(d4 + 0) * 64 + r] = tk.x;
            Ks[(d4 + 1) * 64 + r] = tk.y;
            Ks[(d4 + 2) * 64 + r] = tk.z;
            Ks[(d4 + 3) * 64 + r] = tk.w;
        }
        for (int i = tid; i < 1024; i += 256) {
            int r = i >> 4;
            int d4 = (i & 15) << 2;
            *(float4*)&Vs[r * 64 + d4] =
                *(const float4*)(vp + (size_t)(b * Nc + k0 + r) * QKV_LD + d4);
        }
        __syncthreads();

        float s[4][4] = {};
        #pragma unroll
        for (int d = 0; d < 64; d++) {
            float a[4];
            #pragma unroll
            for (int i = 0; i < 4; i++) a[i] = Qs[d * 64 + ty * 4 + i];
            float4 b4 = *(const float4*)&Ks[d * 64 + tx * 4];
            float bb[4] = {b4.x, b4.y, b4.z, b4.w};
            #pragma unroll
            for (int i = 0; i < 4; i++)
                #pragma unroll
                for (int j = 0; j < 4; j++)
                    s[i][j] += a[i] * bb[j];
        }

        #pragma unroll
        for (int i = 0; i < 4; i++) {
            int gq = q0 + ty * 4 + i;
            float4 av = make_float4(1.f, 1.f, 1.f, 1.f);
            if (mask)
                av = *(const float4*)(adj + ((size_t)b * Nc + gq) * Nc + k0 + tx * 4);
            float* srow = &Ss[(ty * 4 + i) * 65 + tx * 4];
            srow[0] = (av.x > 0.f) ? s[i][0] * SCALE : 0.f;
            srow[1] = (av.y > 0.f) ? s[i][1] * SCALE : 0.f;
            srow[2] = (av.z > 0.f) ? s[i][2] * SCALE : 0.f;
            srow[3] = (av.w > 0.f) ? s[i][3] * SCALE : 0.f;
        }
        __syncthreads();

        float sv[16];
        float mloc = -INFINITY;
        #pragma unroll
        for (int c = 0; c < 16; c++) {
            sv[c] = Ss[row * 65 + lq + c * 4];
            mloc = fmaxf(mloc, sv[c]);
        }
        mloc = fmaxf(mloc, __shfl_xor_sync(0xffffffffu, mloc, 1));
        mloc = fmaxf(mloc, __shfl_xor_sync(0xffffffffu, mloc, 2));
        float mprev = mrow[row];
        float mnew = fmaxf(mprev, mloc);
        float psum = 0.f;
        #pragma unroll
        for (int c = 0; c < 16; c++) {
            float p = __expf(sv[c] - mnew);
            Ss[row * 65 + lq + c * 4] = p;
            psum += p;
        }
        psum += __shfl_xor_sync(0xffffffffu, psum, 1);
        psum += __shfl_xor_sync(0xffffffffu, psum, 2);
        if (lq == 0) {
            float al = __expf(mprev - mnew);
            arow[row] = al;
            lrow[row] = lrow[row] * al + psum;
            mrow[row] = mnew;
        }
        __syncthreads();

        float alpha[4];
        #pragma unroll
        for (int i = 0; i < 4; i++) alpha[i] = arow[ty * 4 + i];
        #pragma unroll
        for (int i = 0; i < 4; i++)
            #pragma unroll
            for (int j = 0; j < 4; j++)
                O[i][j] *= alpha[i];
        #pragma unroll
        for (int kv = 0; kv < 64; kv++) {
            float p[4];
            #pragma unroll
            for (int i = 0; i < 4; i++) p[i] = Ss[(ty * 4 + i) * 65 + kv];
            float4 v4 = *(const float4*)&Vs[kv * 64 + tx * 4];
            float vv[4] = {v4.x, v4.y, v4.z, v4.w};
            #pragma unroll
            for (int i = 0; i < 4; i++)
                #pragma unroll
                for (int j = 0; j < 4; j++)
                    O[i][j] += p[i] * vv[j];
        }
        __syncthreads();
    }

    #pragma unroll
    for (int i = 0; i < 4; i++) {
        float inv = 1.f / lrow[ty * 4 + i];
        int gq = q0 + ty * 4 + i;
        size_t o = ((size_t)(b * Nc + gq)) * Dc + h * DKc + tx * 4;
        float ov[4] = {O[i][0] * inv, O[i][1] * inv, O[i][2] * inv, O[i][3] * inv};
        __nv_bfloat16 hv[4], lv[4];
        #pragma unroll
        for (int u = 0; u < 4; u++) {
            hv[u] = __float2bfloat16(ov[u]);
            lv[u] = __float2bfloat16(ov[u] - __bfloat162float(hv[u]));
        }
        *(__nv_bfloat162*)(chi + o)     = __nv_bfloat162(hv[0], hv[1]);
        *(__nv_bfloat162*)(chi + o + 2) = __nv_bfloat162(hv[2], hv[3]);
        *(__nv_bfloat162*)(clo + o)     = __nv_bfloat162(lv[0], lv[1]);
        *(__nv_bfloat162*)(clo + o + 2) = __nv_bfloat162(lv[2], lv[3]);
    }
}

// ---------------------------------------------------------------------------
// Gate: coeff = sigmoid([x,h2] . gate_w + gate_b); out = c*x + (1-c)*h2.
// ---------------------------------------------------------------------------
__global__ void gate_kernel(const float* __restrict__ x, const float* __restrict__ h2,
                            const float* __restrict__ gw, const float* __restrict__ gb,
                            float* __restrict__ out)
{
    int warp = (blockIdx.x * blockDim.x + threadIdx.x) >> 5;
    int lane = threadIdx.x & 31;
    if (warp >= Mrows) return;
    const float* xr = x + (size_t)warp * Dc;
    const float* hr = h2 + (size_t)warp * Dc;

    float dot = 0.f;
    #pragma unroll
    for (int i = 0; i < 16; i++) {
        int c = lane + i * 32;
        dot += xr[c] * gw[c] + hr[c] * gw[Dc + c];
    }
    #pragma unroll
    for (int o = 16; o > 0; o >>= 1) dot += __shfl_xor_sync(0xffffffffu, dot, o);

    float z = dot + gb[0];
    float cf = 1.f / (1.f + __expf(-z));
    #pragma unroll
    for (int i = 0; i < 16; i++) {
        int c = lane + i * 32;
        out[(size_t)warp * Dc + c] = cf * xr[c] + (1.f - cf) * hr[c];
    }
}

// ---------------------------------------------------------------------------
extern "C" void kernel_launch(void* const* d_in, const int* in_sizes, int n_in,
                              void* d_out, int out_size)
{
    const float* x    = (const float*)d_in[0];
    const float* adj  = (const float*)d_in[1];
    const float* W_w  = (const float*)d_in[2];
    const float* W_b  = (const float*)d_in[3];
    const float* ln_g = (const float*)d_in[4];
    const float* ln_b = (const float*)d_in[5];
    const float* Wq   = (const float*)d_in[6];
    const float* bq   = (const float*)d_in[7];
    const float* Wk   = (const float*)d_in[8];
    const float* bk   = (const float*)d_in[9];
    const float* Wv   = (const float*)d_in[10];
    const float* bv   = (const float*)d_in[11];
    const float* Wo   = (const float*)d_in[12];
    const float* bo   = (const float*)d_in[13];
    const float* gw   = (const float*)d_in[14];
    const float* gb   = (const float*)d_in[15];
    const int* use_adj = (const int*)d_in[16];
    float* out = (float*)d_out;

    float *h, *h2, *qkv, *bias3;
    __nv_bfloat16 *ahi, *alo, *whi, *wlo;
    cudaGetSymbolAddress((void**)&h,    g_h);
    cudaGetSymbolAddress((void**)&h2,   g_h2);
    cudaGetSymbolAddress((void**)&qkv,  g_qkv);
    cudaGetSymbolAddress((void**)&ahi,  g_ahi);
    cudaGetSymbolAddress((void**)&alo,  g_alo);
    cudaGetSymbolAddress((void**)&whi,  g_whi);
    cudaGetSymbolAddress((void**)&wlo,  g_wlo);
    cudaGetSymbolAddress((void**)&bias3, g_bias3);

    const int ATTN_SMEM = (4096 * 3 + 64 * 65 + 3 * 64) * (int)sizeof(float);
    cudaFuncSetAttribute(attn_kernel, cudaFuncAttributeMaxDynamicSharedMemorySize, ATTN_SMEM);
    cudaFuncSetAttribute(mma_gemm_kernel<false>, cudaFuncAttributeMaxDynamicSharedMemorySize, GEMM_SMEM);
    cudaFuncSetAttribute(mma_gemm_kernel<true>,  cudaFuncAttributeMaxDynamicSharedMemorySize, GEMM_SMEM);

    const int n4 = Mrows * Dc / 4;
    dim3 tgrid(16, 16), tblk(32, 8);
    dim3 g1(Dc / 128, Mrows / 128);        // (4, 64)
    dim3 gq(QKV_LD / 128, Mrows / 128);    // (12, 64)
    dim3 agrid(Nc / 64, Hc, Bc);           // (8, 8, 16)

    // 1) h = x @ W_w + W_b
    split_kernel<<<n4 / 256, 256>>>(x, ahi, alo, n4);
    tsplit_kernel<<<tgrid, tblk>>>(W_w, whi, wlo);
    mma_gemm_kernel<false><<<g1, 256, GEMM_SMEM>>>(ahi, alo, whi, wlo, W_b, h, Dc);
    // 2) LN(h) -> split
    ln_split_kernel<<<Mrows / 8, 256>>>(h, ln_g, ln_b, ahi, alo);
    // 3) fused QKV GEMM
    tsplit_kernel<<<tgrid, tblk>>>(Wq, whi,                wlo);
    tsplit_kernel<<<tgrid, tblk>>>(Wk, whi + Dc * Dc,      wlo + Dc * Dc);
    tsplit_kernel<<<tgrid, tblk>>>(Wv, whi + 2 * Dc * Dc,  wlo + 2 * Dc * Dc);
    pack_bias3<<<6, 256>>>(bq, bk, bv, bias3);
    mma_gemm_kernel<false><<<gq, 256, GEMM_SMEM>>>(ahi, alo, whi, wlo, bias3, qkv, QKV_LD);
    // 4) attention -> ctx hi/lo
    attn_kernel<<<agrid, 256, ATTN_SMEM>>>(qkv, adj, use_adj, ahi, alo);
    // 5) h2 = relu(ctx @ Wo + bo)
    tsplit_kernel<<<tgrid, tblk>>>(Wo, whi, wlo);
    mma_gemm_kernel<true><<<g1, 256, GEMM_SMEM>>>(ahi, alo, whi, wlo, bo, h2, Dc);
    // 6) gated residual output
    gate_kernel<<<Mrows / 8, 256>>>(x, h2, gw, gb, out);
}

// round 4
// speedup vs baseline: 2.0171x; 1.3635x over previous
#include <cuda_runtime.h>
#include <cuda_bf16.h>
#include <math.h>
#include <cstdint>

// Problem constants
constexpr int Bc = 16, Nc = 512, Dc = 512, Hc = 8, DKc = 64;
constexpr int Mrows = Bc * Nc;          // 8192
constexpr int QKV_LD = 3 * Dc;          // 1536
constexpr float SCALE = 0.125f;         // DK^-0.5
constexpr float LN_EPS = 1e-5f;

// ---------------------------------------------------------------------------
// Scratch (static device arrays; no allocation allowed)
// ---------------------------------------------------------------------------
__device__ float g_h[Mrows * Dc];
__device__ float g_h2[Mrows * Dc];
__device__ float g_qkv[Mrows * QKV_LD];
__device__ __nv_bfloat16 g_ahi[Mrows * Dc];
__device__ __nv_bfloat16 g_alo[Mrows * Dc];
__device__ __nv_bfloat16 g_whi[3 * Dc * Dc];
__device__ __nv_bfloat16 g_wlo[3 * Dc * Dc];
__device__ float g_bias3[QKV_LD];

// ---------------------------------------------------------------------------
// mma.sync helpers (validated in R3)
// ---------------------------------------------------------------------------
__device__ __forceinline__ uint32_t smem_u32(const void* p) {
    uint32_t a;
    asm("{ .reg .u64 t; cvta.to.shared.u64 t, %1; cvt.u32.u64 %0, t; }" : "=r"(a) : "l"(p));
    return a;
}
__device__ __forceinline__ void ldmx4(uint32_t* r, uint32_t addr) {
    asm volatile("ldmatrix.sync.aligned.m8n8.x4.shared.b16 {%0,%1,%2,%3}, [%4];"
                 : "=r"(r[0]), "=r"(r[1]), "=r"(r[2]), "=r"(r[3]) : "r"(addr));
}
__device__ __forceinline__ void ldmx2(uint32_t* r, uint32_t addr) {
    asm volatile("ldmatrix.sync.aligned.m8n8.x2.shared.b16 {%0,%1}, [%2];"
                 : "=r"(r[0]), "=r"(r[1]) : "r"(addr));
}
__device__ __forceinline__ void mma16816(float* c, const uint32_t* a, const uint32_t* b) {
    asm volatile("mma.sync.aligned.m16n8k16.row.col.f32.bf16.bf16.f32 "
                 "{%0,%1,%2,%3}, {%4,%5,%6,%7}, {%8,%9}, {%0,%1,%2,%3};"
                 : "+f"(c[0]), "+f"(c[1]), "+f"(c[2]), "+f"(c[3])
                 : "r"(a[0]), "r"(a[1]), "r"(a[2]), "r"(a[3]), "r"(b[0]), "r"(b[1]));
}
// float pair -> bf16x2 hi and lo (split)
__device__ __forceinline__ void pack_hilo(float x, float y, uint32_t& hi, uint32_t& lo) {
    __nv_bfloat16 hx = __float2bfloat16(x), hy = __float2bfloat16(y);
    __nv_bfloat16 lx = __float2bfloat16(x - __bfloat162float(hx));
    __nv_bfloat16 ly = __float2bfloat16(y - __bfloat162float(hy));
    __nv_bfloat162 H(hx, hy), L(lx, ly);
    hi = *(uint32_t*)&H;
    lo = *(uint32_t*)&L;
}

// ---------------------------------------------------------------------------
// fp32 -> bf16 hi/lo split (elementwise, vectorized)
// ---------------------------------------------------------------------------
__global__ void split_kernel(const float* __restrict__ x,
                             __nv_bfloat16* __restrict__ hi, __nv_bfloat16* __restrict__ lo,
                             int n4) {
    int i = blockIdx.x * blockDim.x + threadIdx.x;
    if (i >= n4) return;
    float4 v = ((const float4*)x)[i];
    uint32_t h0, l0, h1, l1;
    pack_hilo(v.x, v.y, h0, l0);
    pack_hilo(v.z, v.w, h1, l1);
    ((uint32_t*)hi)[2 * i] = h0; ((uint32_t*)hi)[2 * i + 1] = h1;
    ((uint32_t*)lo)[2 * i] = l0; ((uint32_t*)lo)[2 * i + 1] = l1;
}

// ---------------------------------------------------------------------------
// W [K=512, N=512] row-major -> transposed hi/lo bf16 [N, K]
// ---------------------------------------------------------------------------
__global__ void tsplit_kernel(const float* __restrict__ W,
                              __nv_bfloat16* __restrict__ hi, __nv_bfloat16* __restrict__ lo) {
    __shared__ float t[32][33];
    const int bx = blockIdx.x * 32;
    const int by = blockIdx.y * 32;
    const int tx = threadIdx.x, ty = threadIdx.y;   // 32 x 8
    #pragma unroll
    for (int j = 0; j < 32; j += 8)
        t[ty + j][tx] = W[(size_t)(by + ty + j) * Dc + bx + tx];
    __syncthreads();
    #pragma unroll
    for (int j = 0; j < 32; j += 8) {
        float v = t[tx][ty + j];
        __nv_bfloat16 h = __float2bfloat16(v);
        size_t o = (size_t)(bx + ty + j) * Dc + by + tx;
        hi[o] = h;
        lo[o] = __float2bfloat16(v - __bfloat162float(h));
    }
}

__global__ void pack_bias3(const float* __restrict__ bq, const float* __restrict__ bk,
                           const float* __restrict__ bv, float* __restrict__ b3) {
    int i = blockIdx.x * blockDim.x + threadIdx.x;
    if (i < Dc) b3[i] = bq[i];
    else if (i < 2 * Dc) b3[i] = bk[i - Dc];
    else if (i < 3 * Dc) b3[i] = bv[i - 2 * Dc];
}

// ---------------------------------------------------------------------------
// mma.sync bf16 split GEMM (unchanged from R3, validated)
// ---------------------------------------------------------------------------
constexpr int GPAD = 40;
constexpr int GTILE_B = 128 * GPAD * 2;
constexpr int GSTAGE_B = 4 * GTILE_B;
constexpr int GEMM_SMEM = 2 * GSTAGE_B;           // 81920

template<bool RELU>
__global__ void __launch_bounds__(256, 1) mma_gemm_kernel(
    const __nv_bfloat16* __restrict__ Ahi, const __nv_bfloat16* __restrict__ Alo,
    const __nv_bfloat16* __restrict__ Bhi, const __nv_bfloat16* __restrict__ Blo,
    const float* __restrict__ bias, float* __restrict__ C, int ldc)
{
    extern __shared__ char smem[];
    const uint32_t sbase = smem_u32(smem);
    const int tid = threadIdx.x, wid = tid >> 5, lane = tid & 31;
    const int m0 = blockIdx.y * 128, n0 = blockIdx.x * 128;
    const int wm = wid & 1, wn = wid >> 1;

    const __nv_bfloat16* srcs[4] = {Ahi, Alo, Bhi, Blo};

    const uint32_t aRow = wm * 64 + (lane & 15);
    const uint32_t aCol = (lane < 16) ? 0 : 8;
    const uint32_t aOffB = (aRow * GPAD + aCol) * 2;
    const uint32_t bRow = wn * 32 + (lane & 7);
    const uint32_t bCol = ((lane >> 3) & 1) * 8;
    const uint32_t bOffB = (bRow * GPAD + bCol) * 2;

    float acc[4][4][4] = {};
    uint4 pf[4][2];

    #pragma unroll
    for (int t = 0; t < 4; t++) {
        const __nv_bfloat16* src = srcs[t];
        const int base = (t < 2) ? m0 : n0;
        #pragma unroll
        for (int j = 0; j < 2; j++) {
            int s = tid + j * 256;
            int row = s >> 2, seg = s & 3;
            pf[t][j] = *(const uint4*)(src + (size_t)(base + row) * Dc + seg * 8);
        }
    }

    constexpr int NCH = Dc / 32;
    for (int c = 0; c < NCH; c++) {
        const int stage = c & 1;
        const uint32_t stOff = stage * GSTAGE_B;

        #pragma unroll
        for (int t = 0; t < 4; t++) {
            #pragma unroll
            for (int j = 0; j < 2; j++) {
                int s = tid + j * 256;
                int row = s >> 2, seg = s & 3;
                *(uint4*)(smem + stOff + t * GTILE_B + (row * GPAD + seg * 8) * 2) = pf[t][j];
            }
        }
        __syncthreads();

        if (c + 1 < NCH) {
            const int k0 = (c + 1) * 32;
            #pragma unroll
            for (int t = 0; t < 4; t++) {
                const __nv_bfloat16* src = srcs[t];
                const int base = (t < 2) ? m0 : n0;
                #pragma unroll
                for (int j = 0; j < 2; j++) {
                    int s = tid + j * 256;
                    int row = s >> 2, seg = s & 3;
                    pf[t][j] = *(const uint4*)(src + (size_t)(base + row) * Dc + k0 + seg * 8);
                }
            }
        }

        const uint32_t sAhi = sbase + stOff + 0 * GTILE_B;
        const uint32_t sAlo = sbase + stOff + 1 * GTILE_B;
        const uint32_t sBhi = sbase + stOff + 2 * GTILE_B;
        const uint32_t sBlo = sbase + stOff + 3 * GTILE_B;

        #pragma unroll
        for (int ks = 0; ks < 2; ks++) {
            const uint32_t kOffB = ks * 16 * 2;
            uint32_t ahi[4][4], alo[4][4], bhi[4][2], blo[4][2];
            #pragma unroll
            for (int i = 0; i < 4; i++) {
                uint32_t ao = aOffB + kOffB + i * 16 * GPAD * 2;
                ldmx4(ahi[i], sAhi + ao);
                ldmx4(alo[i], sAlo + ao);
            }
            #pragma unroll
            for (int j = 0; j < 4; j++) {
                uint32_t bo = bOffB + kOffB + j * 8 * GPAD * 2;
                ldmx2(bhi[j], sBhi + bo);
                ldmx2(blo[j], sBlo + bo);
            }
            #pragma unroll
            for (int i = 0; i < 4; i++)
                #pragma unroll
                for (int j = 0; j < 4; j++) {
                    mma16816(acc[i][j], ahi[i], bhi[j]);
                    mma16816(acc[i][j], ahi[i], blo[j]);
                    mma16816(acc[i][j], alo[i], bhi[j]);
                }
        }
        __syncthreads();
    }

    const int lr = lane >> 2, lc = (lane & 3) * 2;
    #pragma unroll
    for (int i = 0; i < 4; i++) {
        const int row0 = m0 + wm * 64 + i * 16 + lr;
        #pragma unroll
        for (int j = 0; j < 4; j++) {
            const int col = n0 + wn * 32 + j * 8 + lc;
            float b0 = bias[col], b1 = bias[col + 1];
            float2 o0 = make_float2(acc[i][j][0] + b0, acc[i][j][1] + b1);
            float2 o1 = make_float2(acc[i][j][2] + b0, acc[i][j][3] + b1);
            if (RELU) {
                o0.x = fmaxf(o0.x, 0.f); o0.y = fmaxf(o0.y, 0.f);
                o1.x = fmaxf(o1.x, 0.f); o1.y = fmaxf(o1.y, 0.f);
            }
            *(float2*)(C + (size_t)row0 * ldc + col) = o0;
            *(float2*)(C + (size_t)(row0 + 8) * ldc + col) = o1;
        }
    }
}

// ---------------------------------------------------------------------------
// LayerNorm over rows of 512, writing bf16 hi/lo split directly.
// ---------------------------------------------------------------------------
__global__ void ln_split_kernel(const float* __restrict__ hsrc,
                                const float* __restrict__ g, const float* __restrict__ b,
                                __nv_bfloat16* __restrict__ hi, __nv_bfloat16* __restrict__ lo)
{
    int warp = (blockIdx.x * blockDim.x + threadIdx.x) >> 5;
    int lane = threadIdx.x & 31;
    if (warp >= Mrows) return;
    const float* row = hsrc + (size_t)warp * Dc;

    float vals[16];
    float s = 0.f;
    #pragma unroll
    for (int i = 0; i < 16; i++) { vals[i] = row[lane + i * 32]; s += vals[i]; }
    #pragma unroll
    for (int o = 16; o > 0; o >>= 1) s += __shfl_xor_sync(0xffffffffu, s, o);
    float mu = s * (1.f / 512.f);

    float vsum = 0.f;
    #pragma unroll
    for (int i = 0; i < 16; i++) { float d = vals[i] - mu; vsum += d * d; }
    #pragma unroll
    for (int o = 16; o > 0; o >>= 1) vsum += __shfl_xor_sync(0xffffffffu, vsum, o);
    float inv = rsqrtf(vsum * (1.f / 512.f) + LN_EPS);

    #pragma unroll
    for (int i = 0; i < 16; i++) {
        int c = lane + i * 32;
        float v = (vals[i] - mu) * inv * g[c] + b[c];
        __nv_bfloat16 h = __float2bfloat16(v);
        hi[(size_t)warp * Dc + c] = h;
        lo[(size_t)warp * Dc + c] = __float2bfloat16(v - __bfloat162float(h));
    }
}

// ---------------------------------------------------------------------------
// mma.sync flash attention.
// CTA = (128-row q tile, head, batch); 8 warps, warp = 16 q-rows.
// S = Q·K^T and ctx = P·V via bf16 hi/lo 3-pass mma. Online softmax in regs.
// Masked logit = exactly 0.0 (reference: where(adj>0,s,NEG)*adj).
// Writes ctx hi/lo bf16 split for the following GEMM.
// ---------------------------------------------------------------------------
constexpr int APAD = 72;      // Q/K smem row stride (bf16)
constexpr int VPAD = 136;     // Vt smem row stride (bf16)
constexpr int ATTN_SMEM = (4 * 128 * APAD + 2 * 64 * VPAD) * 2;   // 108544 B

__global__ void __launch_bounds__(256, 1) attn_mma_kernel(
    const float* __restrict__ qkv, const float* __restrict__ adj,
    const int* __restrict__ use_adj_p,
    __nv_bfloat16* __restrict__ chi, __nv_bfloat16* __restrict__ clo)
{
    extern __shared__ __nv_bfloat16 smb[];
    __nv_bfloat16* Qhi = smb;
    __nv_bfloat16* Qlo = smb + 128 * APAD;
    __nv_bfloat16* Khi = smb + 2 * 128 * APAD;
    __nv_bfloat16* Klo = smb + 3 * 128 * APAD;
    __nv_bfloat16* Vthi = smb + 4 * 128 * APAD;
    __nv_bfloat16* Vtlo = Vthi + 64 * VPAD;

    const uint32_t sQhi = smem_u32(Qhi), sQlo = smem_u32(Qlo);
    const uint32_t sKhi = smem_u32(Khi), sKlo = smem_u32(Klo);
    const uint32_t sVthi = smem_u32(Vthi), sVtlo = smem_u32(Vtlo);

    const int b = blockIdx.z, h = blockIdx.y;
    const int q0 = blockIdx.x * 128;
    const int tid = threadIdx.x, wid = tid >> 5, lane = tid & 31;
    const bool mask = (*use_adj_p) != 0;

    const float* qp = qkv + h * DKc;
    const float* kp = qkv + Dc + h * DKc;
    const float* vp = qkv + 2 * Dc + h * DKc;

    // ---- load Q tile [128 x 64] -> hi/lo smem ----
    #pragma unroll
    for (int i = 0; i < 8; i++) {
        int lin = tid + i * 256;
        int r = lin >> 4, c4 = (lin & 15) * 4;
        float4 t = *(const float4*)(qp + (size_t)(b * Nc + q0 + r) * QKV_LD + c4);
        uint32_t h0, l0, h1, l1;
        pack_hilo(t.x, t.y, h0, l0);
        pack_hilo(t.z, t.w, h1, l1);
        uint32_t o = r * APAD + c4;
        *(uint32_t*)(Qhi + o) = h0; *(uint32_t*)(Qhi + o + 2) = h1;
        *(uint32_t*)(Qlo + o) = l0; *(uint32_t*)(Qlo + o + 2) = l1;
    }

    // fragment addressing constants (same scheme as GEMM)
    const uint32_t aRow = wid * 16 + (lane & 15);
    const uint32_t aCol = (lane < 16) ? 0 : 8;
    const uint32_t aOff = (aRow * APAD + aCol) * 2;
    const uint32_t bRowBase = lane & 7;
    const uint32_t bColSel = ((lane >> 3) & 1) * 8;

    const int lr = lane >> 2, lc2 = (lane & 3) * 2;
    const int grow0 = q0 + wid * 16 + lr;        // global q row (and +8)

    float O[8][4] = {};
    float m0r = -INFINITY, m1r = -INFINITY, l0r = 0.f, l1r = 0.f;

    for (int kt = 0; kt < 4; kt++) {
        const int k0 = kt * 128;
        __syncthreads();   // protect K/V smem from previous iteration's readers

        // ---- load K tile [128 x 64] -> hi/lo smem (row = kv, col = d) ----
        #pragma unroll
        for (int i = 0; i < 8; i++) {
            int lin = tid + i * 256;
            int r = lin >> 4, c4 = (lin & 15) * 4;
            float4 t = *(const float4*)(kp + (size_t)(b * Nc + k0 + r) * QKV_LD + c4);
            uint32_t h0, l0, h1, l1;
            pack_hilo(t.x, t.y, h0, l0);
            pack_hilo(t.z, t.w, h1, l1);
            uint32_t o = r * APAD + c4;
            *(uint32_t*)(Khi + o) = h0; *(uint32_t*)(Khi + o + 2) = h1;
            *(uint32_t*)(Klo + o) = l0; *(uint32_t*)(Klo + o + 2) = l1;
        }
        // ---- load V tile [128 x 64] -> TRANSPOSED hi/lo smem [64 x 128] ----
        #pragma unroll
        for (int i = 0; i < 8; i++) {
            int lin = tid + i * 256;
            int r = lin >> 4, c4 = (lin & 15) * 4;
            float4 t = *(const float4*)(vp + (size_t)(b * Nc + k0 + r) * QKV_LD + c4);
            float vv[4] = {t.x, t.y, t.z, t.w};
            #pragma unroll
            for (int u = 0; u < 4; u++) {
                __nv_bfloat16 hv = __float2bfloat16(vv[u]);
                Vthi[(c4 + u) * VPAD + r] = hv;
                Vtlo[(c4 + u) * VPAD + r] = __float2bfloat16(vv[u] - __bfloat162float(hv));
            }
        }
        __syncthreads();

        // ---- S = Q @ K^T : warp computes [16 x 128] ----
        float s[16][4];
        #pragma unroll
        for (int j = 0; j < 16; j++)
            #pragma unroll
            for (int u = 0; u < 4; u++) s[j][u] = 0.f;

        #pragma unroll
        for (int ks = 0; ks < 4; ks++) {
            const uint32_t kOff = ks * 16 * 2;
            uint32_t ahi[4], alo[4];
            ldmx4(ahi, sQhi + aOff + kOff);
            ldmx4(alo, sQlo + aOff + kOff);
            #pragma unroll
            for (int j = 0; j < 16; j++) {
                uint32_t bo = ((j * 8 + bRowBase) * APAD + bColSel) * 2 + kOff;
                uint32_t bhi[2], blo[2];
                ldmx2(bhi, sKhi + bo);
                ldmx2(blo, sKlo + bo);
                mma16816(s[j], ahi, bhi);
                mma16816(s[j], ahi, blo);
                mma16816(s[j], alo, bhi);
            }
        }

        // ---- scale + mask ----
        if (mask) {
            const float* arow0 = adj + ((size_t)(b * Nc + grow0)) * Nc + k0 + lc2;
            const float* arow1 = arow0 + 8 * Nc;
            #pragma unroll
            for (int j = 0; j < 16; j++) {
                float2 a0 = *(const float2*)(arow0 + j * 8);
                float2 a1 = *(const float2*)(arow1 + j * 8);
                s[j][0] = (a0.x > 0.f) ? s[j][0] * SCALE : 0.f;
                s[j][1] = (a0.y > 0.f) ? s[j][1] * SCALE : 0.f;
                s[j][2] = (a1.x > 0.f) ? s[j][2] * SCALE : 0.f;
                s[j][3] = (a1.y > 0.f) ? s[j][3] * SCALE : 0.f;
            }
        } else {
            #pragma unroll
            for (int j = 0; j < 16; j++)
                #pragma unroll
                for (int u = 0; u < 4; u++) s[j][u] *= SCALE;
        }

        // ---- online softmax (rows lr and lr+8, reduce over quad lanes) ----
        float rm0 = -INFINITY, rm1 = -INFINITY;
        #pragma unroll
        for (int j = 0; j < 16; j++) {
            rm0 = fmaxf(rm0, fmaxf(s[j][0], s[j][1]));
            rm1 = fmaxf(rm1, fmaxf(s[j][2], s[j][3]));
        }
        rm0 = fmaxf(rm0, __shfl_xor_sync(0xffffffffu, rm0, 1));
        rm0 = fmaxf(rm0, __shfl_xor_sync(0xffffffffu, rm0, 2));
        rm1 = fmaxf(rm1, __shfl_xor_sync(0xffffffffu, rm1, 1));
        rm1 = fmaxf(rm1, __shfl_xor_sync(0xffffffffu, rm1, 2));

        float mn0 = fmaxf(m0r, rm0), mn1 = fmaxf(m1r, rm1);
        float al0 = __expf(m0r - mn0), al1 = __expf(m1r - mn1);
        m0r = mn0; m1r = mn1;

        float ps0 = 0.f, ps1 = 0.f;
        #pragma unroll
        for (int j = 0; j < 16; j++) {
            s[j][0] = __expf(s[j][0] - mn0);
            s[j][1] = __expf(s[j][1] - mn0);
            s[j][2] = __expf(s[j][2] - mn1);
            s[j][3] = __expf(s[j][3] - mn1);
            ps0 += s[j][0] + s[j][1];
            ps1 += s[j][2] + s[j][3];
        }
        ps0 += __shfl_xor_sync(0xffffffffu, ps0, 1);
        ps0 += __shfl_xor_sync(0xffffffffu, ps0, 2);
        ps1 += __shfl_xor_sync(0xffffffffu, ps1, 1);
        ps1 += __shfl_xor_sync(0xffffffffu, ps1, 2);
        l0r = l0r * al0 + ps0;
        l1r = l1r * al1 + ps1;

        #pragma unroll
        for (int jd = 0; jd < 8; jd++) {
            O[jd][0] *= al0; O[jd][1] *= al0;
            O[jd][2] *= al1; O[jd][3] *= al1;
        }

        // ---- O += P @ V  (P from s regs, V^T in smem as B operand) ----
        #pragma unroll
        for (int kk = 0; kk < 8; kk++) {
            uint32_t aHi[4], aLo[4];
            pack_hilo(s[2 * kk][0],     s[2 * kk][1],     aHi[0], aLo[0]);
            pack_hilo(s[2 * kk][2],     s[2 * kk][3],     aHi[1], aLo[1]);
            pack_hilo(s[2 * kk + 1][0], s[2 * kk + 1][1], aHi[2], aLo[2]);
            pack_hilo(s[2 * kk + 1][2], s[2 * kk + 1][3], aHi[3], aLo[3]);
            const uint32_t kOff = kk * 16 * 2;
            #pragma unroll
            for (int jd = 0; jd < 8; jd++) {
                uint32_t bo = ((jd * 8 + bRowBase) * VPAD + bColSel) * 2 + kOff;
                uint32_t bhi[2], blo[2];
                ldmx2(bhi, sVthi + bo);
                ldmx2(blo, sVtlo + bo);
                mma16816(O[jd], aHi, bhi);
                mma16816(O[jd], aHi, blo);
                mma16816(O[jd], aLo, bhi);
            }
        }
    }

    // ---- epilogue: normalize, split to bf16 hi/lo, store ctx ----
    const float inv0 = 1.f / l0r, inv1 = 1.f / l1r;
    #pragma unroll
    for (int jd = 0; jd < 8; jd++) {
        size_t o0 = ((size_t)(b * Nc + grow0)) * Dc + h * DKc + jd * 8 + lc2;
        size_t o1 = o0 + 8 * (size_t)Dc;
        uint32_t h0, l0, h1, l1;
        pack_hilo(O[jd][0] * inv0, O[jd][1] * inv0, h0, l0);
        pack_hilo(O[jd][2] * inv1, O[jd][3] * inv1, h1, l1);
        *(uint32_t*)(chi + o0) = h0;
        *(uint32_t*)(clo + o0) = l0;
        *(uint32_t*)(chi + o1) = h1;
        *(uint32_t*)(clo + o1) = l1;
    }
}

// ---------------------------------------------------------------------------
// Gate: coeff = sigmoid([x,h2] . gate_w + gate_b); out = c*x + (1-c)*h2.
// ---------------------------------------------------------------------------
__global__ void gate_kernel(const float* __restrict__ x, const float* __restrict__ h2,
                            const float* __restrict__ gw, const float* __restrict__ gb,
                            float* __restrict__ out)
{
    int warp = (blockIdx.x * blockDim.x + threadIdx.x) >> 5;
    int lane = threadIdx.x & 31;
    if (warp >= Mrows) return;
    const float* xr = x + (size_t)warp * Dc;
    const float* hr = h2 + (size_t)warp * Dc;

    float dot = 0.f;
    #pragma unroll
    for (int i = 0; i < 16; i++) {
        int c = lane + i * 32;
        dot += xr[c] * gw[c] + hr[c] * gw[Dc + c];
    }
    #pragma unroll
    for (int o = 16; o > 0; o >>= 1) dot += __shfl_xor_sync(0xffffffffu, dot, o);

    float z = dot + gb[0];
    float cf = 1.f / (1.f + __expf(-z));
    #pragma unroll
    for (int i = 0; i < 16; i++) {
        int c = lane + i * 32;
        out[(size_t)warp * Dc + c] = cf * xr[c] + (1.f - cf) * hr[c];
    }
}

// ---------------------------------------------------------------------------
extern "C" void kernel_launch(void* const* d_in, const int* in_sizes, int n_in,
                              void* d_out, int out_size)
{
    const float* x    = (const float*)d_in[0];
    const float* adj  = (const float*)d_in[1];
    const float* W_w  = (const float*)d_in[2];
    const float* W_b  = (const float*)d_in[3];
    const float* ln_g = (const float*)d_in[4];
    const float* ln_b = (const float*)d_in[5];
    const float* Wq   = (const float*)d_in[6];
    const float* bq   = (const float*)d_in[7];
    const float* Wk   = (const float*)d_in[8];
    const float* bk   = (const float*)d_in[9];
    const float* Wv   = (const float*)d_in[10];
    const float* bv   = (const float*)d_in[11];
    const float* Wo   = (const float*)d_in[12];
    const float* bo   = (const float*)d_in[13];
    const float* gw   = (const float*)d_in[14];
    const float* gb   = (const float*)d_in[15];
    const int* use_adj = (const int*)d_in[16];
    float* out = (float*)d_out;

    float *h, *h2, *qkv, *bias3;
    __nv_bfloat16 *ahi, *alo, *whi, *wlo;
    cudaGetSymbolAddress((void**)&h,    g_h);
    cudaGetSymbolAddress((void**)&h2,   g_h2);
    cudaGetSymbolAddress((void**)&qkv,  g_qkv);
    cudaGetSymbolAddress((void**)&ahi,  g_ahi);
    cudaGetSymbolAddress((void**)&alo,  g_alo);
    cudaGetSymbolAddress((void**)&whi,  g_whi);
    cudaGetSymbolAddress((void**)&wlo,  g_wlo);
    cudaGetSymbolAddress((void**)&bias3, g_bias3);

    cudaFuncSetAttribute(attn_mma_kernel, cudaFuncAttributeMaxDynamicSharedMemorySize, ATTN_SMEM);
    cudaFuncSetAttribute(mma_gemm_kernel<false>, cudaFuncAttributeMaxDynamicSharedMemorySize, GEMM_SMEM);
    cudaFuncSetAttribute(mma_gemm_kernel<true>,  cudaFuncAttributeMaxDynamicSharedMemorySize, GEMM_SMEM);

    const int n4 = Mrows * Dc / 4;
    dim3 tgrid(16, 16), tblk(32, 8);
    dim3 g1(Dc / 128, Mrows / 128);        // (4, 64)
    dim3 gq(QKV_LD / 128, Mrows / 128);    // (12, 64)
    dim3 agrid(Nc / 128, Hc, Bc);          // (4, 8, 16)

    // 1) h = x @ W_w + W_b
    split_kernel<<<n4 / 256, 256>>>(x, ahi, alo, n4);
    tsplit_kernel<<<tgrid, tblk>>>(W_w, whi, wlo);
    mma_gemm_kernel<false><<<g1, 256, GEMM_SMEM>>>(ahi, alo, whi, wlo, W_b, h, Dc);
    // 2) LN(h) -> split
    ln_split_kernel<<<Mrows / 8, 256>>>(h, ln_g, ln_b, ahi, alo);
    // 3) fused QKV GEMM
    tsplit_kernel<<<tgrid, tblk>>>(Wq, whi,                wlo);
    tsplit_kernel<<<tgrid, tblk>>>(Wk, whi + Dc * Dc,      wlo + Dc * Dc);
    tsplit_kernel<<<tgrid, tblk>>>(Wv, whi + 2 * Dc * Dc,  wlo + 2 * Dc * Dc);
    pack_bias3<<<6, 256>>>(bq, bk, bv, bias3);
    mma_gemm_kernel<false><<<gq, 256, GEMM_SMEM>>>(ahi, alo, whi, wlo, bias3, qkv, QKV_LD);
    // 4) mma flash attention -> ctx hi/lo
    attn_mma_kernel<<<agrid, 256, ATTN_SMEM>>>(qkv, adj, use_adj, ahi, alo);
    // 5) h2 = relu(ctx @ Wo + bo)
    tsplit_kernel<<<tgrid, tblk>>>(Wo, whi, wlo);
    mma_gemm_kernel<true><<<g1, 256, GEMM_SMEM>>>(ahi, alo, whi, wlo, bo, h2, Dc);
    // 6) gated residual output
    gate_kernel<<<Mrows / 8, 256>>>(x, h2, gw, gb, out);
}

// round 5
// speedup vs baseline: 2.0650x; 1.0237x over previous
#include <cuda_runtime.h>
#include <cuda_bf16.h>
#include <math.h>
#include <cstdint>

// Problem constants
constexpr int Bc = 16, Nc = 512, Dc = 512, Hc = 8, DKc = 64;
constexpr int Mrows = Bc * Nc;          // 8192
constexpr int QKV_LD = 3 * Dc;          // 1536
constexpr float SCALE = 0.125f;         // DK^-0.5 (exact power of 2)
constexpr float LN_EPS = 1e-5f;
constexpr int DD = Dc * Dc;

// ---------------------------------------------------------------------------
// Scratch (static device arrays; no allocation allowed)
// ---------------------------------------------------------------------------
__device__ float g_h[Mrows * Dc];
__device__ float g_h2[Mrows * Dc];
__device__ float g_qkv[Mrows * QKV_LD];
__device__ __nv_bfloat16 g_ahi[Mrows * Dc];
__device__ __nv_bfloat16 g_alo[Mrows * Dc];
__device__ __nv_bfloat16 g_whi[5 * DD];   // transposed weights [N][K], 5 slots
__device__ __nv_bfloat16 g_wlo[5 * DD];
__device__ float g_bias3[QKV_LD];

// ---------------------------------------------------------------------------
// mma.sync helpers (validated R3/R4)
// ---------------------------------------------------------------------------
__device__ __forceinline__ uint32_t smem_u32(const void* p) {
    uint32_t a;
    asm("{ .reg .u64 t; cvta.to.shared.u64 t, %1; cvt.u32.u64 %0, t; }" : "=r"(a) : "l"(p));
    return a;
}
__device__ __forceinline__ void ldmx4(uint32_t* r, uint32_t addr) {
    asm volatile("ldmatrix.sync.aligned.m8n8.x4.shared.b16 {%0,%1,%2,%3}, [%4];"
                 : "=r"(r[0]), "=r"(r[1]), "=r"(r[2]), "=r"(r[3]) : "r"(addr));
}
__device__ __forceinline__ void mma16816(float* c, const uint32_t* a, const uint32_t* b) {
    asm volatile("mma.sync.aligned.m16n8k16.row.col.f32.bf16.bf16.f32 "
                 "{%0,%1,%2,%3}, {%4,%5,%6,%7}, {%8,%9}, {%0,%1,%2,%3};"
                 : "+f"(c[0]), "+f"(c[1]), "+f"(c[2]), "+f"(c[3])
                 : "r"(a[0]), "r"(a[1]), "r"(a[2]), "r"(a[3]), "r"(b[0]), "r"(b[1]));
}
// float pair -> bf16x2 hi and lo (split)
__device__ __forceinline__ void pack_hilo(float x, float y, uint32_t& hi, uint32_t& lo) {
    __nv_bfloat16 hx = __float2bfloat16(x), hy = __float2bfloat16(y);
    __nv_bfloat16 lx = __float2bfloat16(x - __bfloat162float(hx));
    __nv_bfloat16 ly = __float2bfloat16(y - __bfloat162float(hy));
    __nv_bfloat162 H(hx, hy), L(lx, ly);
    hi = *(uint32_t*)&H;
    lo = *(uint32_t*)&L;
}

// ---------------------------------------------------------------------------
// Weight prep: transpose+split all 5 weights [K,N]->[N,K] hi/lo, pack qkv bias.
// grid (16,16,5), block (32,8). z selects the weight.
// ---------------------------------------------------------------------------
__global__ void wprep_kernel(const float* __restrict__ W_w, const float* __restrict__ Wq,
                             const float* __restrict__ Wk, const float* __restrict__ Wv,
                             const float* __restrict__ Wo,
                             const float* __restrict__ bq, const float* __restrict__ bk,
                             const float* __restrict__ bv,
                             __nv_bfloat16* __restrict__ hi, __nv_bfloat16* __restrict__ lo,
                             float* __restrict__ b3)
{
    __shared__ float t[32][33];
    const float* Ws[5] = {W_w, Wq, Wk, Wv, Wo};
    const int z = blockIdx.z;
    const float* W = Ws[z];
    __nv_bfloat16* ho = hi + (size_t)z * DD;
    __nv_bfloat16* lop = lo + (size_t)z * DD;

    const int bx = blockIdx.x * 32;
    const int by = blockIdx.y * 32;
    const int tx = threadIdx.x, ty = threadIdx.y;

    if (z == 0 && blockIdx.x == 0 && blockIdx.y == 0) {
        int tt = ty * 32 + tx;
        for (int i = tt; i < QKV_LD; i += 256)
            b3[i] = (i < Dc) ? bq[i] : (i < 2 * Dc) ? bk[i - Dc] : bv[i - 2 * Dc];
    }

    #pragma unroll
    for (int j = 0; j < 32; j += 8)
        t[ty + j][tx] = W[(size_t)(by + ty + j) * Dc + bx + tx];
    __syncthreads();
    #pragma unroll
    for (int j = 0; j < 32; j += 8) {
        float v = t[tx][ty + j];
        __nv_bfloat16 h = __float2bfloat16(v);
        size_t o = (size_t)(bx + ty + j) * Dc + by + tx;
        ho[o] = h;
        lop[o] = __float2bfloat16(v - __bfloat162float(h));
    }
}

// ---------------------------------------------------------------------------
// mma.sync bf16 split GEMM. If F32A, A operand is fp32 and is hi/lo-split
// on the fly while staging to smem (eliminates the separate split kernel).
// CTA tile 128x128, BK=32, 8 warps (2x4), warp tile 64x32.
// ---------------------------------------------------------------------------
constexpr int GPAD = 40;
constexpr int GTILE_B = 128 * GPAD * 2;
constexpr int GSTAGE_B = 4 * GTILE_B;
constexpr int GEMM_SMEM = 2 * GSTAGE_B;           // 81920

template<bool RELU, bool F32A>
__global__ void __launch_bounds__(256, 1) mma_gemm_kernel(
    const void* __restrict__ Asrc, const __nv_bfloat16* __restrict__ Alo_,
    const __nv_bfloat16* __restrict__ Bhi, const __nv_bfloat16* __restrict__ Blo,
    const float* __restrict__ bias, float* __restrict__ C, int ldc)
{
    extern __shared__ char smem[];
    const uint32_t sbase = smem_u32(smem);
    const int tid = threadIdx.x, wid = tid >> 5, lane = tid & 31;
    const int m0 = blockIdx.y * 128, n0 = blockIdx.x * 128;
    const int wm = wid & 1, wn = wid >> 1;

    const __nv_bfloat16* Ahi_ = (const __nv_bfloat16*)Asrc;
    const float* Af = (const float*)Asrc;

    // ldmatrix addressing
    const uint32_t aRow = wm * 64 + (lane & 15);
    const uint32_t aCol = (lane < 16) ? 0 : 8;
    const uint32_t aOffB = (aRow * GPAD + aCol) * 2;
    const uint32_t bRow4 = ((lane >> 4) & 1) * 8 + (lane & 7);
    const uint32_t bCol4 = ((lane >> 3) & 1) * 8;

    const int ldRow = tid >> 2, ldSeg = tid & 3;   // global<->smem staging map

    float acc[4][4][4] = {};
    uint4 pf[4][2];          // !F32A: Ahi,Alo,Bhi,Blo ; F32A: [2..3] = Bhi,Blo
    float4 pfAf[2][2];       // F32A only

    // ---- prefetch chunk 0 ----
    #pragma unroll
    for (int j = 0; j < 2; j++) {
        int row = ldRow + j * 64;
        if constexpr (F32A) {
            const float* ap = Af + (size_t)(m0 + row) * Dc + ldSeg * 8;
            pfAf[j][0] = *(const float4*)ap;
            pfAf[j][1] = *(const float4*)(ap + 4);
        } else {
            pf[0][j] = *(const uint4*)(Ahi_ + (size_t)(m0 + row) * Dc + ldSeg * 8);
            pf[1][j] = *(const uint4*)(Alo_ + (size_t)(m0 + row) * Dc + ldSeg * 8);
        }
        pf[2][j] = *(const uint4*)(Bhi + (size_t)(n0 + row) * Dc + ldSeg * 8);
        pf[3][j] = *(const uint4*)(Blo + (size_t)(n0 + row) * Dc + ldSeg * 8);
    }

    constexpr int NCH = Dc / 32;
    for (int c = 0; c < NCH; c++) {
        const int stage = c & 1;
        const uint32_t stOff = stage * GSTAGE_B;

        // ---- store prefetched chunk to smem ----
        #pragma unroll
        for (int j = 0; j < 2; j++) {
            int row = ldRow + j * 64;
            uint32_t so = stOff + (row * GPAD + ldSeg * 8) * 2;
            if constexpr (F32A) {
                uint32_t h0, l0, h1, l1, h2, l2, h3, l3;
                pack_hilo(pfAf[j][0].x, pfAf[j][0].y, h0, l0);
                pack_hilo(pfAf[j][0].z, pfAf[j][0].w, h1, l1);
                pack_hilo(pfAf[j][1].x, pfAf[j][1].y, h2, l2);
                pack_hilo(pfAf[j][1].z, pfAf[j][1].w, h3, l3);
                *(uint4*)(smem + so + 0 * GTILE_B) = make_uint4(h0, h1, h2, h3);
                *(uint4*)(smem + so + 1 * GTILE_B) = make_uint4(l0, l1, l2, l3);
            } else {
                *(uint4*)(smem + so + 0 * GTILE_B) = pf[0][j];
                *(uint4*)(smem + so + 1 * GTILE_B) = pf[1][j];
            }
            *(uint4*)(smem + so + 2 * GTILE_B) = pf[2][j];
            *(uint4*)(smem + so + 3 * GTILE_B) = pf[3][j];
        }
        __syncthreads();

        // ---- prefetch next chunk ----
        if (c + 1 < NCH) {
            const int k0 = (c + 1) * 32;
            #pragma unroll
            for (int j = 0; j < 2; j++) {
                int row = ldRow + j * 64;
                if constexpr (F32A) {
                    const float* ap = Af + (size_t)(m0 + row) * Dc + k0 + ldSeg * 8;
                    pfAf[j][0] = *(const float4*)ap;
                    pfAf[j][1] = *(const float4*)(ap + 4);
                } else {
                    pf[0][j] = *(const uint4*)(Ahi_ + (size_t)(m0 + row) * Dc + k0 + ldSeg * 8);
                    pf[1][j] = *(const uint4*)(Alo_ + (size_t)(m0 + row) * Dc + k0 + ldSeg * 8);
                }
                pf[2][j] = *(const uint4*)(Bhi + (size_t)(n0 + row) * Dc + k0 + ldSeg * 8);
                pf[3][j] = *(const uint4*)(Blo + (size_t)(n0 + row) * Dc + k0 + ldSeg * 8);
            }
        }

        const uint32_t sAhi = sbase + stOff + 0 * GTILE_B;
        const uint32_t sAlo = sbase + stOff + 1 * GTILE_B;
        const uint32_t sBhi = sbase + stOff + 2 * GTILE_B;
        const uint32_t sBlo = sbase + stOff + 3 * GTILE_B;

        #pragma unroll
        for (int ks = 0; ks < 2; ks++) {
            const uint32_t kOffB = ks * 16 * 2;
            uint32_t ahi[4][4], alo[4][4], bhi[2][4], blo[2][4];
            #pragma unroll
            for (int i = 0; i < 4; i++) {
                uint32_t ao = aOffB + kOffB + i * 16 * GPAD * 2;
                ldmx4(ahi[i], sAhi + ao);
                ldmx4(alo[i], sAlo + ao);
            }
            #pragma unroll
            for (int jp = 0; jp < 2; jp++) {
                uint32_t bo = ((wn * 32 + jp * 16 + bRow4) * GPAD + bCol4) * 2 + kOffB;
                ldmx4(bhi[jp], sBhi + bo);
                ldmx4(blo[jp], sBlo + bo);
            }
            #pragma unroll
            for (int i = 0; i < 4; i++)
                #pragma unroll
                for (int j = 0; j < 4; j++) {
                    const int jp = j >> 1, hf = (j & 1) * 2;
                    mma16816(acc[i][j], ahi[i], &bhi[jp][hf]);
                    mma16816(acc[i][j], ahi[i], &blo[jp][hf]);
                    mma16816(acc[i][j], alo[i], &bhi[jp][hf]);
                }
        }
        __syncthreads();
    }

    const int lr = lane >> 2, lc = (lane & 3) * 2;
    #pragma unroll
    for (int i = 0; i < 4; i++) {
        const int row0 = m0 + wm * 64 + i * 16 + lr;
        #pragma unroll
        for (int j = 0; j < 4; j++) {
            const int col = n0 + wn * 32 + j * 8 + lc;
            float b0 = bias[col], b1 = bias[col + 1];
            float2 o0 = make_float2(acc[i][j][0] + b0, acc[i][j][1] + b1);
            float2 o1 = make_float2(acc[i][j][2] + b0, acc[i][j][3] + b1);
            if (RELU) {
                o0.x = fmaxf(o0.x, 0.f); o0.y = fmaxf(o0.y, 0.f);
                o1.x = fmaxf(o1.x, 0.f); o1.y = fmaxf(o1.y, 0.f);
            }
            *(float2*)(C + (size_t)row0 * ldc + col) = o0;
            *(float2*)(C + (size_t)(row0 + 8) * ldc + col) = o1;
        }
    }
}

// ---------------------------------------------------------------------------
// LayerNorm over rows of 512, writing bf16 hi/lo split directly.
// ---------------------------------------------------------------------------
__global__ void ln_split_kernel(const float* __restrict__ hsrc,
                                const float* __restrict__ g, const float* __restrict__ b,
                                __nv_bfloat16* __restrict__ hi, __nv_bfloat16* __restrict__ lo)
{
    int warp = (blockIdx.x * blockDim.x + threadIdx.x) >> 5;
    int lane = threadIdx.x & 31;
    if (warp >= Mrows) return;
    const float* row = hsrc + (size_t)warp * Dc;

    float vals[16];
    float s = 0.f;
    #pragma unroll
    for (int i = 0; i < 16; i++) { vals[i] = row[lane + i * 32]; s += vals[i]; }
    #pragma unroll
    for (int o = 16; o > 0; o >>= 1) s += __shfl_xor_sync(0xffffffffu, s, o);
    float mu = s * (1.f / 512.f);

    float vsum = 0.f;
    #pragma unroll
    for (int i = 0; i < 16; i++) { float d = vals[i] - mu; vsum += d * d; }
    #pragma unroll
    for (int o = 16; o > 0; o >>= 1) vsum += __shfl_xor_sync(0xffffffffu, vsum, o);
    float inv = rsqrtf(vsum * (1.f / 512.f) + LN_EPS);

    #pragma unroll
    for (int i = 0; i < 16; i++) {
        int c = lane + i * 32;
        float v = (vals[i] - mu) * inv * g[c] + b[c];
        __nv_bfloat16 h = __float2bfloat16(v);
        hi[(size_t)warp * Dc + c] = h;
        lo[(size_t)warp * Dc + c] = __float2bfloat16(v - __bfloat162float(h));
    }
}

// ---------------------------------------------------------------------------
// mma.sync flash attention (R4 structure + ldmx4 B-loads + pre-scaled Q).
// CTA = (128-row q tile, head, batch); 8 warps, warp = 16 q-rows.
// Masked logit = exactly 0.0 (reference: where(adj>0,s,NEG)*adj).
// ---------------------------------------------------------------------------
constexpr int APAD = 72;      // Q/K smem row stride (bf16)
constexpr int VPAD = 136;     // Vt smem row stride (bf16)
constexpr int ATTN_SMEM = (4 * 128 * APAD + 2 * 64 * VPAD) * 2;   // 108544 B

__global__ void __launch_bounds__(256, 1) attn_mma_kernel(
    const float* __restrict__ qkv, const float* __restrict__ adj,
    const int* __restrict__ use_adj_p,
    __nv_bfloat16* __restrict__ chi, __nv_bfloat16* __restrict__ clo)
{
    extern __shared__ __nv_bfloat16 smb[];
    __nv_bfloat16* Qhi = smb;
    __nv_bfloat16* Qlo = smb + 128 * APAD;
    __nv_bfloat16* Khi = smb + 2 * 128 * APAD;
    __nv_bfloat16* Klo = smb + 3 * 128 * APAD;
    __nv_bfloat16* Vthi = smb + 4 * 128 * APAD;
    __nv_bfloat16* Vtlo = Vthi + 64 * VPAD;

    const uint32_t sQhi = smem_u32(Qhi), sQlo = smem_u32(Qlo);
    const uint32_t sKhi = smem_u32(Khi), sKlo = smem_u32(Klo);
    const uint32_t sVthi = smem_u32(Vthi), sVtlo = smem_u32(Vtlo);

    const int b = blockIdx.z, h = blockIdx.y;
    const int q0 = blockIdx.x * 128;
    const int tid = threadIdx.x, wid = tid >> 5, lane = tid & 31;
    const bool mask = (*use_adj_p) != 0;

    const float* qp = qkv + h * DKc;
    const float* kp = qkv + Dc + h * DKc;
    const float* vp = qkv + 2 * Dc + h * DKc;

    // ---- load Q tile [128 x 64], pre-scaled by SCALE (exact 2^-3) ----
    #pragma unroll
    for (int i = 0; i < 8; i++) {
        int lin = tid + i * 256;
        int r = lin >> 4, c4 = (lin & 15) * 4;
        float4 t = *(const float4*)(qp + (size_t)(b * Nc + q0 + r) * QKV_LD + c4);
        uint32_t h0, l0, h1, l1;
        pack_hilo(t.x * SCALE, t.y * SCALE, h0, l0);
        pack_hilo(t.z * SCALE, t.w * SCALE, h1, l1);
        uint32_t o = r * APAD + c4;
        *(uint32_t*)(Qhi + o) = h0; *(uint32_t*)(Qhi + o + 2) = h1;
        *(uint32_t*)(Qlo + o) = l0; *(uint32_t*)(Qlo + o + 2) = l1;
    }

    // fragment addressing
    const uint32_t aRow = wid * 16 + (lane & 15);
    const uint32_t aCol = (lane < 16) ? 0 : 8;
    const uint32_t aOff = (aRow * APAD + aCol) * 2;
    const uint32_t bRow4 = ((lane >> 4) & 1) * 8 + (lane & 7);
    const uint32_t bCol4 = ((lane >> 3) & 1) * 8;

    const int lr = lane >> 2, lc2 = (lane & 3) * 2;
    const int grow0 = q0 + wid * 16 + lr;

    float O[8][4] = {};
    float m0r = -INFINITY, m1r = -INFINITY, l0r = 0.f, l1r = 0.f;

    for (int kt = 0; kt < 4; kt++) {
        const int k0 = kt * 128;
        __syncthreads();   // protect K/V smem from previous iteration's readers

        // ---- load K tile [128 x 64] -> hi/lo smem ----
        #pragma unroll
        for (int i = 0; i < 8; i++) {
            int lin = tid + i * 256;
            int r = lin >> 4, c4 = (lin & 15) * 4;
            float4 t = *(const float4*)(kp + (size_t)(b * Nc + k0 + r) * QKV_LD + c4);
            uint32_t h0, l0, h1, l1;
            pack_hilo(t.x, t.y, h0, l0);
            pack_hilo(t.z, t.w, h1, l1);
            uint32_t o = r * APAD + c4;
            *(uint32_t*)(Khi + o) = h0; *(uint32_t*)(Khi + o + 2) = h1;
            *(uint32_t*)(Klo + o) = l0; *(uint32_t*)(Klo + o + 2) = l1;
        }
        // ---- load V tile [128 x 64] -> TRANSPOSED hi/lo smem [64 x 128] ----
        #pragma unroll
        for (int i = 0; i < 8; i++) {
            int lin = tid + i * 256;
            int r = lin >> 4, c4 = (lin & 15) * 4;
            float4 t = *(const float4*)(vp + (size_t)(b * Nc + k0 + r) * QKV_LD + c4);
            float vv[4] = {t.x, t.y, t.z, t.w};
            #pragma unroll
            for (int u = 0; u < 4; u++) {
                __nv_bfloat16 hv = __float2bfloat16(vv[u]);
                Vthi[(c4 + u) * VPAD + r] = hv;
                Vtlo[(c4 + u) * VPAD + r] = __float2bfloat16(vv[u] - __bfloat162float(hv));
            }
        }
        __syncthreads();

        // ---- S = Q @ K^T : warp computes [16 x 128] ----
        float s[16][4];
        #pragma unroll
        for (int j = 0; j < 16; j++)
            #pragma unroll
            for (int u = 0; u < 4; u++) s[j][u] = 0.f;

        #pragma unroll
        for (int ks = 0; ks < 4; ks++) {
            const uint32_t kOff = ks * 32;
            uint32_t ahi[4], alo[4];
            ldmx4(ahi, sQhi + aOff + kOff);
            ldmx4(alo, sQlo + aOff + kOff);
            #pragma unroll
            for (int jp = 0; jp < 8; jp++) {
                uint32_t bo = ((jp * 16 + bRow4) * APAD + bCol4) * 2 + kOff;
                uint32_t bh[4], bl[4];
                ldmx4(bh, sKhi + bo);
                ldmx4(bl, sKlo + bo);
                mma16816(s[2 * jp],     ahi, &bh[0]);
                mma16816(s[2 * jp],     ahi, &bl[0]);
                mma16816(s[2 * jp],     alo, &bh[0]);
                mma16816(s[2 * jp + 1], ahi, &bh[2]);
                mma16816(s[2 * jp + 1], ahi, &bl[2]);
                mma16816(s[2 * jp + 1], alo, &bh[2]);
            }
        }

        // ---- mask (Q pre-scaled; masked logit = 0.0) ----
        if (mask) {
            const float* arow0 = adj + ((size_t)(b * Nc + grow0)) * Nc + k0 + lc2;
            const float* arow1 = arow0 + 8 * Nc;
            #pragma unroll
            for (int j = 0; j < 16; j++) {
                float2 a0 = *(const float2*)(arow0 + j * 8);
                float2 a1 = *(const float2*)(arow1 + j * 8);
                s[j][0] = (a0.x > 0.f) ? s[j][0] : 0.f;
                s[j][1] = (a0.y > 0.f) ? s[j][1] : 0.f;
                s[j][2] = (a1.x > 0.f) ? s[j][2] : 0.f;
                s[j][3] = (a1.y > 0.f) ? s[j][3] : 0.f;
            }
        }

        // ---- online softmax (rows lr and lr+8, reduce over quad lanes) ----
        float rm0 = -INFINITY, rm1 = -INFINITY;
        #pragma unroll
        for (int j = 0; j < 16; j++) {
            rm0 = fmaxf(rm0, fmaxf(s[j][0], s[j][1]));
            rm1 = fmaxf(rm1, fmaxf(s[j][2], s[j][3]));
        }
        rm0 = fmaxf(rm0, __shfl_xor_sync(0xffffffffu, rm0, 1));
        rm0 = fmaxf(rm0, __shfl_xor_sync(0xffffffffu, rm0, 2));
        rm1 = fmaxf(rm1, __shfl_xor_sync(0xffffffffu, rm1, 1));
        rm1 = fmaxf(rm1, __shfl_xor_sync(0xffffffffu, rm1, 2));

        float mn0 = fmaxf(m0r, rm0), mn1 = fmaxf(m1r, rm1);
        float al0 = __expf(m0r - mn0), al1 = __expf(m1r - mn1);
        m0r = mn0; m1r = mn1;

        float ps0 = 0.f, ps1 = 0.f;
        #pragma unroll
        for (int j = 0; j < 16; j++) {
            s[j][0] = __expf(s[j][0] - mn0);
            s[j][1] = __expf(s[j][1] - mn0);
            s[j][2] = __expf(s[j][2] - mn1);
            s[j][3] = __expf(s[j][3] - mn1);
            ps0 += s[j][0] + s[j][1];
            ps1 += s[j][2] + s[j][3];
        }
        ps0 += __shfl_xor_sync(0xffffffffu, ps0, 1);
        ps0 += __shfl_xor_sync(0xffffffffu, ps0, 2);
        ps1 += __shfl_xor_sync(0xffffffffu, ps1, 1);
        ps1 += __shfl_xor_sync(0xffffffffu, ps1, 2);
        l0r = l0r * al0 + ps0;
        l1r = l1r * al1 + ps1;

        #pragma unroll
        for (int jd = 0; jd < 8; jd++) {
            O[jd][0] *= al0; O[jd][1] *= al0;
            O[jd][2] *= al1; O[jd][3] *= al1;
        }

        // ---- O += P @ V  (P from s regs, V^T in smem as B operand) ----
        #pragma unroll
        for (int kk = 0; kk < 8; kk++) {
            uint32_t aHi[4], aLo[4];
            pack_hilo(s[2 * kk][0],     s[2 * kk][1],     aHi[0], aLo[0]);
            pack_hilo(s[2 * kk][2],     s[2 * kk][3],     aHi[1], aLo[1]);
            pack_hilo(s[2 * kk + 1][0], s[2 * kk + 1][1], aHi[2], aLo[2]);
            pack_hilo(s[2 * kk + 1][2], s[2 * kk + 1][3], aHi[3], aLo[3]);
            const uint32_t kOff = kk * 32;
            #pragma unroll
            for (int jdp = 0; jdp < 4; jdp++) {
                uint32_t bo = ((jdp * 16 + bRow4) * VPAD + bCol4) * 2 + kOff;
                uint32_t bh[4], bl[4];
                ldmx4(bh, sVthi + bo);
                ldmx4(bl, sVtlo + bo);
                mma16816(O[2 * jdp],     aHi, &bh[0]);
                mma16816(O[2 * jdp],     aHi, &bl[0]);
                mma16816(O[2 * jdp],     aLo, &bh[0]);
                mma16816(O[2 * jdp + 1], aHi, &bh[2]);
                mma16816(O[2 * jdp + 1], aHi, &bl[2]);
                mma16816(O[2 * jdp + 1], aLo, &bh[2]);
            }
        }
    }

    // ---- epilogue: normalize, split to bf16 hi/lo, store ctx ----
    const float inv0 = 1.f / l0r, inv1 = 1.f / l1r;
    #pragma unroll
    for (int jd = 0; jd < 8; jd++) {
        size_t o0 = ((size_t)(b * Nc + grow0)) * Dc + h * DKc + jd * 8 + lc2;
        size_t o1 = o0 + 8 * (size_t)Dc;
        uint32_t h0, l0, h1, l1;
        pack_hilo(O[jd][0] * inv0, O[jd][1] * inv0, h0, l0);
        pack_hilo(O[jd][2] * inv1, O[jd][3] * inv1, h1, l1);
        *(uint32_t*)(chi + o0) = h0;
        *(uint32_t*)(clo + o0) = l0;
        *(uint32_t*)(chi + o1) = h1;
        *(uint32_t*)(clo + o1) = l1;
    }
}

// ---------------------------------------------------------------------------
// Gate: coeff = sigmoid([x,h2] . gate_w + gate_b); out = c*x + (1-c)*h2.
// ---------------------------------------------------------------------------
__global__ void gate_kernel(const float* __restrict__ x, const float* __restrict__ h2,
                            const float* __restrict__ gw, const float* __restrict__ gb,
                            float* __restrict__ out)
{
    int warp = (blockIdx.x * blockDim.x + threadIdx.x) >> 5;
    int lane = threadIdx.x & 31;
    if (warp >= Mrows) return;
    const float* xr = x + (size_t)warp * Dc;
    const float* hr = h2 + (size_t)warp * Dc;

    float dot = 0.f;
    #pragma unroll
    for (int i = 0; i < 16; i++) {
        int c = lane + i * 32;
        dot += xr[c] * gw[c] + hr[c] * gw[Dc + c];
    }
    #pragma unroll
    for (int o = 16; o > 0; o >>= 1) dot += __shfl_xor_sync(0xffffffffu, dot, o);

    float z = dot + gb[0];
    float cf = 1.f / (1.f + __expf(-z));
    #pragma unroll
    for (int i = 0; i < 16; i++) {
        int c = lane + i * 32;
        out[(size_t)warp * Dc + c] = cf * xr[c] + (1.f - cf) * hr[c];
    }
}

// ---------------------------------------------------------------------------
extern "C" void kernel_launch(void* const* d_in, const int* in_sizes, int n_in,
                              void* d_out, int out_size)
{
    const float* x    = (const float*)d_in[0];
    const float* adj  = (const float*)d_in[1];
    const float* W_w  = (const float*)d_in[2];
    const float* W_b  = (const float*)d_in[3];
    const float* ln_g = (const float*)d_in[4];
    const float* ln_b = (const float*)d_in[5];
    const float* Wq   = (const float*)d_in[6];
    const float* bq   = (const float*)d_in[7];
    const float* Wk   = (const float*)d_in[8];
    const float* bk   = (const float*)d_in[9];
    const float* Wv   = (const float*)d_in[10];
    const float* bv   = (const float*)d_in[11];
    const float* Wo   = (const float*)d_in[12];
    const float* bo   = (const float*)d_in[13];
    const float* gw   = (const float*)d_in[14];
    const float* gb   = (const float*)d_in[15];
    const int* use_adj = (const int*)d_in[16];
    float* out = (float*)d_out;

    float *h, *h2, *qkv, *bias3;
    __nv_bfloat16 *ahi, *alo, *whi, *wlo;
    cudaGetSymbolAddress((void**)&h,    g_h);
    cudaGetSymbolAddress((void**)&h2,   g_h2);
    cudaGetSymbolAddress((void**)&qkv,  g_qkv);
    cudaGetSymbolAddress((void**)&ahi,  g_ahi);
    cudaGetSymbolAddress((void**)&alo,  g_alo);
    cudaGetSymbolAddress((void**)&whi,  g_whi);
    cudaGetSymbolAddress((void**)&wlo,  g_wlo);
    cudaGetSymbolAddress((void**)&bias3, g_bias3);

    cudaFuncSetAttribute(attn_mma_kernel, cudaFuncAttributeMaxDynamicSharedMemorySize, ATTN_SMEM);
    cudaFuncSetAttribute((const void*)mma_gemm_kernel<false, true>,
                         cudaFuncAttributeMaxDynamicSharedMemorySize, GEMM_SMEM);
    cudaFuncSetAttribute((const void*)mma_gemm_kernel<false, false>,
                         cudaFuncAttributeMaxDynamicSharedMemorySize, GEMM_SMEM);
    cudaFuncSetAttribute((const void*)mma_gemm_kernel<true, false>,
                         cudaFuncAttributeMaxDynamicSharedMemorySize, GEMM_SMEM);

    dim3 wgrid(16, 16, 5), wblk(32, 8);
    dim3 g1(Dc / 128, Mrows / 128);        // (4, 64)
    dim3 gq(QKV_LD / 128, Mrows / 128);    // (12, 64)
    dim3 agrid(Nc / 128, Hc, Bc);          // (4, 8, 16)

    // 1) weight prep (all 5 transpose+splits + qkv bias pack)
    wprep_kernel<<<wgrid, wblk>>>(W_w, Wq, Wk, Wv, Wo, bq, bk, bv, whi, wlo, bias3);
    // 2) h = x @ W_w + W_b   (fp32 A split on the fly)
    mma_gemm_kernel<false, true><<<g1, 256, GEMM_SMEM>>>(x, nullptr, whi, wlo, W_b, h, Dc);
    // 3) LN(h) -> hi/lo split
    ln_split_kernel<<<Mrows / 8, 256>>>(h, ln_g, ln_b, ahi, alo);
    // 4) fused QKV GEMM
    mma_gemm_kernel<false, false><<<gq, 256, GEMM_SMEM>>>(ahi, alo, whi + DD, wlo + DD, bias3, qkv, QKV_LD);
    // 5) mma flash attention -> ctx hi/lo (overwrites ahi/alo)
    attn_mma_kernel<<<agrid, 256, ATTN_SMEM>>>(qkv, adj, use_adj, ahi, alo);
    // 6) h2 = relu(ctx @ Wo + bo)
    mma_gemm_kernel<true, false><<<g1, 256, GEMM_SMEM>>>(ahi, alo, whi + 4 * DD, wlo + 4 * DD, bo, h2, Dc);
    // 7) gated residual output
    gate_kernel<<<Mrows / 8, 256>>>(x, h2, gw, gb, out);
}

// round 6
// speedup vs baseline: 2.2281x; 1.0789x over previous
#include <cuda_runtime.h>
#include <cuda_bf16.h>
#include <math.h>
#include <cstdint>

// Problem constants
constexpr int Bc = 16, Nc = 512, Dc = 512, Hc = 8, DKc = 64;
constexpr int Mrows = Bc * Nc;          // 8192
constexpr int QKV_LD = 3 * Dc;          // 1536
constexpr float SCALE = 0.125f;         // DK^-0.5 (exact power of 2)
constexpr float LN_EPS = 1e-5f;
constexpr int DD = Dc * Dc;

// ---------------------------------------------------------------------------
// Scratch (static device arrays; no allocation allowed)
// ---------------------------------------------------------------------------
__device__ float g_h[Mrows * Dc];
__device__ float g_h2[Mrows * Dc];
__device__ float g_qkv[Mrows * QKV_LD];
__device__ __nv_bfloat16 g_ahi[Mrows * Dc];
__device__ __nv_bfloat16 g_alo[Mrows * Dc];
__device__ __nv_bfloat16 g_whi[5 * DD];   // transposed weights [N][K], 5 slots
__device__ __nv_bfloat16 g_wlo[5 * DD];
__device__ float g_bias3[QKV_LD];

// ---------------------------------------------------------------------------
// PTX helpers
// ---------------------------------------------------------------------------
__device__ __forceinline__ uint32_t smem_u32(const void* p) {
    uint32_t a;
    asm("{ .reg .u64 t; cvta.to.shared.u64 t, %1; cvt.u32.u64 %0, t; }" : "=r"(a) : "l"(p));
    return a;
}
__device__ __forceinline__ void ldmx4(uint32_t* r, uint32_t addr) {
    asm volatile("ldmatrix.sync.aligned.m8n8.x4.shared.b16 {%0,%1,%2,%3}, [%4];"
                 : "=r"(r[0]), "=r"(r[1]), "=r"(r[2]), "=r"(r[3]) : "r"(addr));
}
__device__ __forceinline__ void mma16816(float* c, const uint32_t* a, const uint32_t* b) {
    asm volatile("mma.sync.aligned.m16n8k16.row.col.f32.bf16.bf16.f32 "
                 "{%0,%1,%2,%3}, {%4,%5,%6,%7}, {%8,%9}, {%0,%1,%2,%3};"
                 : "+f"(c[0]), "+f"(c[1]), "+f"(c[2]), "+f"(c[3])
                 : "r"(a[0]), "r"(a[1]), "r"(a[2]), "r"(a[3]), "r"(b[0]), "r"(b[1]));
}
__device__ __forceinline__ void cpasync16(uint32_t dst, const void* src) {
    asm volatile("cp.async.cg.shared.global [%0], [%1], 16;" :: "r"(dst), "l"(src));
}
#define CP_COMMIT() asm volatile("cp.async.commit_group;" ::: "memory")
#define CP_WAIT(N)  asm volatile("cp.async.wait_group %0;" :: "n"(N) : "memory")

// float pair -> bf16x2 hi and lo (split)
__device__ __forceinline__ void pack_hilo(float x, float y, uint32_t& hi, uint32_t& lo) {
    __nv_bfloat16 hx = __float2bfloat16(x), hy = __float2bfloat16(y);
    __nv_bfloat16 lx = __float2bfloat16(x - __bfloat162float(hx));
    __nv_bfloat16 ly = __float2bfloat16(y - __bfloat162float(hy));
    __nv_bfloat162 H(hx, hy), L(lx, ly);
    hi = *(uint32_t*)&H;
    lo = *(uint32_t*)&L;
}

// ---------------------------------------------------------------------------
// fp32 -> bf16 hi/lo split (elementwise)
// ---------------------------------------------------------------------------
__global__ void split_kernel(const float* __restrict__ x,
                             __nv_bfloat16* __restrict__ hi, __nv_bfloat16* __restrict__ lo,
                             int n4) {
    int i = blockIdx.x * blockDim.x + threadIdx.x;
    if (i >= n4) return;
    float4 v = ((const float4*)x)[i];
    uint32_t h0, l0, h1, l1;
    pack_hilo(v.x, v.y, h0, l0);
    pack_hilo(v.z, v.w, h1, l1);
    ((uint32_t*)hi)[2 * i] = h0; ((uint32_t*)hi)[2 * i + 1] = h1;
    ((uint32_t*)lo)[2 * i] = l0; ((uint32_t*)lo)[2 * i + 1] = l1;
}

// ---------------------------------------------------------------------------
// Weight prep: transpose+split all 5 weights [K,N]->[N,K] hi/lo, pack qkv bias.
// ---------------------------------------------------------------------------
__global__ void wprep_kernel(const float* __restrict__ W_w, const float* __restrict__ Wq,
                             const float* __restrict__ Wk, const float* __restrict__ Wv,
                             const float* __restrict__ Wo,
                             const float* __restrict__ bq, const float* __restrict__ bk,
                             const float* __restrict__ bv,
                             __nv_bfloat16* __restrict__ hi, __nv_bfloat16* __restrict__ lo,
                             float* __restrict__ b3)
{
    __shared__ float t[32][33];
    const float* Ws[5] = {W_w, Wq, Wk, Wv, Wo};
    const int z = blockIdx.z;
    const float* W = Ws[z];
    __nv_bfloat16* ho = hi + (size_t)z * DD;
    __nv_bfloat16* lop = lo + (size_t)z * DD;

    const int bx = blockIdx.x * 32;
    const int by = blockIdx.y * 32;
    const int tx = threadIdx.x, ty = threadIdx.y;

    if (z == 0 && blockIdx.x == 0 && blockIdx.y == 0) {
        int tt = ty * 32 + tx;
        for (int i = tt; i < QKV_LD; i += 256)
            b3[i] = (i < Dc) ? bq[i] : (i < 2 * Dc) ? bk[i - Dc] : bv[i - 2 * Dc];
    }

    #pragma unroll
    for (int j = 0; j < 32; j += 8)
        t[ty + j][tx] = W[(size_t)(by + ty + j) * Dc + bx + tx];
    __syncthreads();
    #pragma unroll
    for (int j = 0; j < 32; j += 8) {
        float v = t[tx][ty + j];
        __nv_bfloat16 h = __float2bfloat16(v);
        size_t o = (size_t)(bx + ty + j) * Dc + by + tx;
        ho[o] = h;
        lop[o] = __float2bfloat16(v - __bfloat162float(h));
    }
}

// ---------------------------------------------------------------------------
// cp.async pipelined mma.sync bf16 split GEMM.
// CTA tile 128x128, BK=32, 8 warps (2x4), warp tile 64x32, 2 CTAs/SM.
// 2-stage cp.async pipeline: loads fully async, no register roundtrip.
// ---------------------------------------------------------------------------
constexpr int GPAD = 40;                  // bf16 elems per smem row (80B, 16B-mult)
constexpr int GTILE_B = 128 * GPAD * 2;   // 10240
constexpr int GSTAGE_B = 4 * GTILE_B;     // 40960
constexpr int GEMM_SMEM = 2 * GSTAGE_B;   // 81920 -> 2 CTAs/SM

template<bool RELU>
__global__ void __launch_bounds__(256, 2) mma_gemm_kernel(
    const __nv_bfloat16* __restrict__ Ahi, const __nv_bfloat16* __restrict__ Alo,
    const __nv_bfloat16* __restrict__ Bhi, const __nv_bfloat16* __restrict__ Blo,
    const float* __restrict__ bias, float* __restrict__ C, int ldc)
{
    extern __shared__ char smem[];
    const uint32_t sbase = smem_u32(smem);
    const int tid = threadIdx.x, wid = tid >> 5, lane = tid & 31;
    const int m0 = blockIdx.y * 128, n0 = blockIdx.x * 128;
    const int wm = wid & 1, wn = wid >> 1;

    // ldmatrix addressing
    const uint32_t aRow = wm * 64 + (lane & 15);
    const uint32_t aCol = (lane < 16) ? 0 : 8;
    const uint32_t aOffB = (aRow * GPAD + aCol) * 2;
    const uint32_t bRow4 = ((lane >> 4) & 1) * 8 + (lane & 7);
    const uint32_t bCol4 = ((lane >> 3) & 1) * 8;

    // cp.async staging map: thread -> (row, 16B seg); rows ldRow, ldRow+64
    const int ldRow = tid >> 2, ldSeg = tid & 3;
    const __nv_bfloat16* srcA[4] = {Ahi, Alo, Bhi, Blo};

    auto issue_stage = [&](int c, uint32_t stOff) {
        const int k0 = c * 32;
        #pragma unroll
        for (int t = 0; t < 4; t++) {
            const __nv_bfloat16* src = srcA[t];
            const int base = (t < 2) ? m0 : n0;
            #pragma unroll
            for (int j = 0; j < 2; j++) {
                int row = ldRow + j * 64;
                uint32_t dst = sbase + stOff + t * GTILE_B + (row * GPAD + ldSeg * 8) * 2;
                cpasync16(dst, src + (size_t)(base + row) * Dc + k0 + ldSeg * 8);
            }
        }
        CP_COMMIT();
    };

    float acc[4][4][4] = {};

    constexpr int NCH = Dc / 32;    // 16
    issue_stage(0, 0);
    issue_stage(1, GSTAGE_B);

    for (int c = 0; c < NCH; c++) {
        const uint32_t stOff = (c & 1) * GSTAGE_B;
        CP_WAIT(1);
        __syncthreads();

        const uint32_t sAhi = sbase + stOff + 0 * GTILE_B;
        const uint32_t sAlo = sbase + stOff + 1 * GTILE_B;
        const uint32_t sBhi = sbase + stOff + 2 * GTILE_B;
        const uint32_t sBlo = sbase + stOff + 3 * GTILE_B;

        #pragma unroll
        for (int ks = 0; ks < 2; ks++) {
            const uint32_t kOffB = ks * 32;
            uint32_t ahi[4][4], alo[4][4], bhi[2][4], blo[2][4];
            #pragma unroll
            for (int i = 0; i < 4; i++) {
                uint32_t ao = aOffB + kOffB + i * 16 * GPAD * 2;
                ldmx4(ahi[i], sAhi + ao);
                ldmx4(alo[i], sAlo + ao);
            }
            #pragma unroll
            for (int jp = 0; jp < 2; jp++) {
                uint32_t bo = ((wn * 32 + jp * 16 + bRow4) * GPAD + bCol4) * 2 + kOffB;
                ldmx4(bhi[jp], sBhi + bo);
                ldmx4(blo[jp], sBlo + bo);
            }
            #pragma unroll
            for (int i = 0; i < 4; i++)
                #pragma unroll
                for (int j = 0; j < 4; j++) {
                    const int jp = j >> 1, hf = (j & 1) * 2;
                    mma16816(acc[i][j], ahi[i], &bhi[jp][hf]);
                    mma16816(acc[i][j], ahi[i], &blo[jp][hf]);
                    mma16816(acc[i][j], alo[i], &bhi[jp][hf]);
                }
        }
        __syncthreads();
        if (c + 2 < NCH) issue_stage(c + 2, stOff);
    }

    const int lr = lane >> 2, lc = (lane & 3) * 2;
    #pragma unroll
    for (int i = 0; i < 4; i++) {
        const int row0 = m0 + wm * 64 + i * 16 + lr;
        #pragma unroll
        for (int j = 0; j < 4; j++) {
            const int col = n0 + wn * 32 + j * 8 + lc;
            float b0 = bias[col], b1 = bias[col + 1];
            float2 o0 = make_float2(acc[i][j][0] + b0, acc[i][j][1] + b1);
            float2 o1 = make_float2(acc[i][j][2] + b0, acc[i][j][3] + b1);
            if (RELU) {
                o0.x = fmaxf(o0.x, 0.f); o0.y = fmaxf(o0.y, 0.f);
                o1.x = fmaxf(o1.x, 0.f); o1.y = fmaxf(o1.y, 0.f);
            }
            *(float2*)(C + (size_t)row0 * ldc + col) = o0;
            *(float2*)(C + (size_t)(row0 + 8) * ldc + col) = o1;
        }
    }
}

// ---------------------------------------------------------------------------
// LayerNorm over rows of 512, writing bf16 hi/lo split directly.
// ---------------------------------------------------------------------------
__global__ void ln_split_kernel(const float* __restrict__ hsrc,
                                const float* __restrict__ g, const float* __restrict__ b,
                                __nv_bfloat16* __restrict__ hi, __nv_bfloat16* __restrict__ lo)
{
    int warp = (blockIdx.x * blockDim.x + threadIdx.x) >> 5;
    int lane = threadIdx.x & 31;
    if (warp >= Mrows) return;
    const float* row = hsrc + (size_t)warp * Dc;

    float vals[16];
    float s = 0.f;
    #pragma unroll
    for (int i = 0; i < 16; i++) { vals[i] = row[lane + i * 32]; s += vals[i]; }
    #pragma unroll
    for (int o = 16; o > 0; o >>= 1) s += __shfl_xor_sync(0xffffffffu, s, o);
    float mu = s * (1.f / 512.f);

    float vsum = 0.f;
    #pragma unroll
    for (int i = 0; i < 16; i++) { float d = vals[i] - mu; vsum += d * d; }
    #pragma unroll
    for (int o = 16; o > 0; o >>= 1) vsum += __shfl_xor_sync(0xffffffffu, vsum, o);
    float inv = rsqrtf(vsum * (1.f / 512.f) + LN_EPS);

    #pragma unroll
    for (int i = 0; i < 16; i++) {
        int c = lane + i * 32;
        float v = (vals[i] - mu) * inv * g[c] + b[c];
        __nv_bfloat16 h = __float2bfloat16(v);
        hi[(size_t)warp * Dc + c] = h;
        lo[(size_t)warp * Dc + c] = __float2bfloat16(v - __bfloat162float(h));
    }
}

// ---------------------------------------------------------------------------
// mma.sync flash attention (unchanged from R5, validated).
// ---------------------------------------------------------------------------
constexpr int APAD = 72;
constexpr int VPAD = 136;
constexpr int ATTN_SMEM = (4 * 128 * APAD + 2 * 64 * VPAD) * 2;   // 108544 B

__global__ void __launch_bounds__(256, 1) attn_mma_kernel(
    const float* __restrict__ qkv, const float* __restrict__ adj,
    const int* __restrict__ use_adj_p,
    __nv_bfloat16* __restrict__ chi, __nv_bfloat16* __restrict__ clo)
{
    extern __shared__ __nv_bfloat16 smb[];
    __nv_bfloat16* Qhi = smb;
    __nv_bfloat16* Qlo = smb + 128 * APAD;
    __nv_bfloat16* Khi = smb + 2 * 128 * APAD;
    __nv_bfloat16* Klo = smb + 3 * 128 * APAD;
    __nv_bfloat16* Vthi = smb + 4 * 128 * APAD;
    __nv_bfloat16* Vtlo = Vthi + 64 * VPAD;

    const uint32_t sQhi = smem_u32(Qhi), sQlo = smem_u32(Qlo);
    const uint32_t sKhi = smem_u32(Khi), sKlo = smem_u32(Klo);
    const uint32_t sVthi = smem_u32(Vthi), sVtlo = smem_u32(Vtlo);

    const int b = blockIdx.z, h = blockIdx.y;
    const int q0 = blockIdx.x * 128;
    const int tid = threadIdx.x, wid = tid >> 5, lane = tid & 31;
    const bool mask = (*use_adj_p) != 0;

    const float* qp = qkv + h * DKc;
    const float* kp = qkv + Dc + h * DKc;
    const float* vp = qkv + 2 * Dc + h * DKc;

    #pragma unroll
    for (int i = 0; i < 8; i++) {
        int lin = tid + i * 256;
        int r = lin >> 4, c4 = (lin & 15) * 4;
        float4 t = *(const float4*)(qp + (size_t)(b * Nc + q0 + r) * QKV_LD + c4);
        uint32_t h0, l0, h1, l1;
        pack_hilo(t.x * SCALE, t.y * SCALE, h0, l0);
        pack_hilo(t.z * SCALE, t.w * SCALE, h1, l1);
        uint32_t o = r * APAD + c4;
        *(uint32_t*)(Qhi + o) = h0; *(uint32_t*)(Qhi + o + 2) = h1;
        *(uint32_t*)(Qlo + o) = l0; *(uint32_t*)(Qlo + o + 2) = l1;
    }

    const uint32_t aRow = wid * 16 + (lane & 15);
    const uint32_t aCol = (lane < 16) ? 0 : 8;
    const uint32_t aOff = (aRow * APAD + aCol) * 2;
    const uint32_t bRow4 = ((lane >> 4) & 1) * 8 + (lane & 7);
    const uint32_t bCol4 = ((lane >> 3) & 1) * 8;

    const int lr = lane >> 2, lc2 = (lane & 3) * 2;
    const int grow0 = q0 + wid * 16 + lr;

    float O[8][4] = {};
    float m0r = -INFINITY, m1r = -INFINITY, l0r = 0.f, l1r = 0.f;

    for (int kt = 0; kt < 4; kt++) {
        const int k0 = kt * 128;
        __syncthreads();

        #pragma unroll
        for (int i = 0; i < 8; i++) {
            int lin = tid + i * 256;
            int r = lin >> 4, c4 = (lin & 15) * 4;
            float4 t = *(const float4*)(kp + (size_t)(b * Nc + k0 + r) * QKV_LD + c4);
            uint32_t h0, l0, h1, l1;
            pack_hilo(t.x, t.y, h0, l0);
            pack_hilo(t.z, t.w, h1, l1);
            uint32_t o = r * APAD + c4;
            *(uint32_t*)(Khi + o) = h0; *(uint32_t*)(Khi + o + 2) = h1;
            *(uint32_t*)(Klo + o) = l0; *(uint32_t*)(Klo + o + 2) = l1;
        }
        #pragma unroll
        for (int i = 0; i < 8; i++) {
            int lin = tid + i * 256;
            int r = lin >> 4, c4 = (lin & 15) * 4;
            float4 t = *(const float4*)(vp + (size_t)(b * Nc + k0 + r) * QKV_LD + c4);
            float vv[4] = {t.x, t.y, t.z, t.w};
            #pragma unroll
            for (int u = 0; u < 4; u++) {
                __nv_bfloat16 hv = __float2bfloat16(vv[u]);
                Vthi[(c4 + u) * VPAD + r] = hv;
                Vtlo[(c4 + u) * VPAD + r] = __float2bfloat16(vv[u] - __bfloat162float(hv));
            }
        }
        __syncthreads();

        float s[16][4];
        #pragma unroll
        for (int j = 0; j < 16; j++)
            #pragma unroll
            for (int u = 0; u < 4; u++) s[j][u] = 0.f;

        #pragma unroll
        for (int ks = 0; ks < 4; ks++) {
            const uint32_t kOff = ks * 32;
            uint32_t ahi[4], alo[4];
            ldmx4(ahi, sQhi + aOff + kOff);
            ldmx4(alo, sQlo + aOff + kOff);
            #pragma unroll
            for (int jp = 0; jp < 8; jp++) {
                uint32_t bo = ((jp * 16 + bRow4) * APAD + bCol4) * 2 + kOff;
                uint32_t bh[4], bl[4];
                ldmx4(bh, sKhi + bo);
                ldmx4(bl, sKlo + bo);
                mma16816(s[2 * jp],     ahi, &bh[0]);
                mma16816(s[2 * jp],     ahi, &bl[0]);
                mma16816(s[2 * jp],     alo, &bh[0]);
                mma16816(s[2 * jp + 1], ahi, &bh[2]);
                mma16816(s[2 * jp + 1], ahi, &bl[2]);
                mma16816(s[2 * jp + 1], alo, &bh[2]);
            }
        }

        if (mask) {
            const float* arow0 = adj + ((size_t)(b * Nc + grow0)) * Nc + k0 + lc2;
            const float* arow1 = arow0 + 8 * Nc;
            #pragma unroll
            for (int j = 0; j < 16; j++) {
                float2 a0 = *(const float2*)(arow0 + j * 8);
                float2 a1 = *(const float2*)(arow1 + j * 8);
                s[j][0] = (a0.x > 0.f) ? s[j][0] : 0.f;
                s[j][1] = (a0.y > 0.f) ? s[j][1] : 0.f;
                s[j][2] = (a1.x > 0.f) ? s[j][2] : 0.f;
                s[j][3] = (a1.y > 0.f) ? s[j][3] : 0.f;
            }
        }

        float rm0 = -INFINITY, rm1 = -INFINITY;
        #pragma unroll
        for (int j = 0; j < 16; j++) {
            rm0 = fmaxf(rm0, fmaxf(s[j][0], s[j][1]));
            rm1 = fmaxf(rm1, fmaxf(s[j][2], s[j][3]));
        }
        rm0 = fmaxf(rm0, __shfl_xor_sync(0xffffffffu, rm0, 1));
        rm0 = fmaxf(rm0, __shfl_xor_sync(0xffffffffu, rm0, 2));
        rm1 = fmaxf(rm1, __shfl_xor_sync(0xffffffffu, rm1, 1));
        rm1 = fmaxf(rm1, __shfl_xor_sync(0xffffffffu, rm1, 2));

        float mn0 = fmaxf(m0r, rm0), mn1 = fmaxf(m1r, rm1);
        float al0 = __expf(m0r - mn0), al1 = __expf(m1r - mn1);
        m0r = mn0; m1r = mn1;

        float ps0 = 0.f, ps1 = 0.f;
        #pragma unroll
        for (int j = 0; j < 16; j++) {
            s[j][0] = __expf(s[j][0] - mn0);
            s[j][1] = __expf(s[j][1] - mn0);
            s[j][2] = __expf(s[j][2] - mn1);
            s[j][3] = __expf(s[j][3] - mn1);
            ps0 += s[j][0] + s[j][1];
            ps1 += s[j][2] + s[j][3];
        }
        ps0 += __shfl_xor_sync(0xffffffffu, ps0, 1);
        ps0 += __shfl_xor_sync(0xffffffffu, ps0, 2);
        ps1 += __shfl_xor_sync(0xffffffffu, ps1, 1);
        ps1 += __shfl_xor_sync(0xffffffffu, ps1, 2);
        l0r = l0r * al0 + ps0;
        l1r = l1r * al1 + ps1;

        #pragma unroll
        for (int jd = 0; jd < 8; jd++) {
            O[jd][0] *= al0; O[jd][1] *= al0;
            O[jd][2] *= al1; O[jd][3] *= al1;
        }

        #pragma unroll
        for (int kk = 0; kk < 8; kk++) {
            uint32_t aHi[4], aLo[4];
            pack_hilo(s[2 * kk][0],     s[2 * kk][1],     aHi[0], aLo[0]);
            pack_hilo(s[2 * kk][2],     s[2 * kk][3],     aHi[1], aLo[1]);
            pack_hilo(s[2 * kk + 1][0], s[2 * kk + 1][1], aHi[2], aLo[2]);
            pack_hilo(s[2 * kk + 1][2], s[2 * kk + 1][3], aHi[3], aLo[3]);
            const uint32_t kOff = kk * 32;
            #pragma unroll
            for (int jdp = 0; jdp < 4; jdp++) {
                uint32_t bo = ((jdp * 16 + bRow4) * VPAD + bCol4) * 2 + kOff;
                uint32_t bh[4], bl[4];
                ldmx4(bh, sVthi + bo);
                ldmx4(bl, sVtlo + bo);
                mma16816(O[2 * jdp],     aHi, &bh[0]);
                mma16816(O[2 * jdp],     aHi, &bl[0]);
                mma16816(O[2 * jdp],     aLo, &bh[0]);
                mma16816(O[2 * jdp + 1], aHi, &bh[2]);
                mma16816(O[2 * jdp + 1], aHi, &bl[2]);
                mma16816(O[2 * jdp + 1], aLo, &bh[2]);
            }
        }
    }

    const float inv0 = 1.f / l0r, inv1 = 1.f / l1r;
    #pragma unroll
    for (int jd = 0; jd < 8; jd++) {
        size_t o0 = ((size_t)(b * Nc + grow0)) * Dc + h * DKc + jd * 8 + lc2;
        size_t o1 = o0 + 8 * (size_t)Dc;
        uint32_t h0, l0, h1, l1;
        pack_hilo(O[jd][0] * inv0, O[jd][1] * inv0, h0, l0);
        pack_hilo(O[jd][2] * inv1, O[jd][3] * inv1, h1, l1);
        *(uint32_t*)(chi + o0) = h0;
        *(uint32_t*)(clo + o0) = l0;
        *(uint32_t*)(chi + o1) = h1;
        *(uint32_t*)(clo + o1) = l1;
    }
}

// ---------------------------------------------------------------------------
// Gate: coeff = sigmoid([x,h2] . gate_w + gate_b); out = c*x + (1-c)*h2.
// ---------------------------------------------------------------------------
__global__ void gate_kernel(const float* __restrict__ x, const float* __restrict__ h2,
                            const float* __restrict__ gw, const float* __restrict__ gb,
                            float* __restrict__ out)
{
    int warp = (blockIdx.x * blockDim.x + threadIdx.x) >> 5;
    int lane = threadIdx.x & 31;
    if (warp >= Mrows) return;
    const float* xr = x + (size_t)warp * Dc;
    const float* hr = h2 + (size_t)warp * Dc;

    float dot = 0.f;
    #pragma unroll
    for (int i = 0; i < 16; i++) {
        int c = lane + i * 32;
        dot += xr[c] * gw[c] + hr[c] * gw[Dc + c];
    }
    #pragma unroll
    for (int o = 16; o > 0; o >>= 1) dot += __shfl_xor_sync(0xffffffffu, dot, o);

    float z = dot + gb[0];
    float cf = 1.f / (1.f + __expf(-z));
    #pragma unroll
    for (int i = 0; i < 16; i++) {
        int c = lane + i * 32;
        out[(size_t)warp * Dc + c] = cf * xr[c] + (1.f - cf) * hr[c];
    }
}

// ---------------------------------------------------------------------------
extern "C" void kernel_launch(void* const* d_in, const int* in_sizes, int n_in,
                              void* d_out, int out_size)
{
    const float* x    = (const float*)d_in[0];
    const float* adj  = (const float*)d_in[1];
    const float* W_w  = (const float*)d_in[2];
    const float* W_b  = (const float*)d_in[3];
    const float* ln_g = (const float*)d_in[4];
    const float* ln_b = (const float*)d_in[5];
    const float* Wq   = (const float*)d_in[6];
    const float* bq   = (const float*)d_in[7];
    const float* Wk   = (const float*)d_in[8];
    const float* bk   = (const float*)d_in[9];
    const float* Wv   = (const float*)d_in[10];
    const float* bv   = (const float*)d_in[11];
    const float* Wo   = (const float*)d_in[12];
    const float* bo   = (const float*)d_in[13];
    const float* gw   = (const float*)d_in[14];
    const float* gb   = (const float*)d_in[15];
    const int* use_adj = (const int*)d_in[16];
    float* out = (float*)d_out;

    float *h, *h2, *qkv, *bias3;
    __nv_bfloat16 *ahi, *alo, *whi, *wlo;
    cudaGetSymbolAddress((void**)&h,    g_h);
    cudaGetSymbolAddress((void**)&h2,   g_h2);
    cudaGetSymbolAddress((void**)&qkv,  g_qkv);
    cudaGetSymbolAddress((void**)&ahi,  g_ahi);
    cudaGetSymbolAddress((void**)&alo,  g_alo);
    cudaGetSymbolAddress((void**)&whi,  g_whi);
    cudaGetSymbolAddress((void**)&wlo,  g_wlo);
    cudaGetSymbolAddress((void**)&bias3, g_bias3);

    cudaFuncSetAttribute(attn_mma_kernel, cudaFuncAttributeMaxDynamicSharedMemorySize, ATTN_SMEM);
    cudaFuncSetAttribute((const void*)mma_gemm_kernel<false>,
                         cudaFuncAttributeMaxDynamicSharedMemorySize, GEMM_SMEM);
    cudaFuncSetAttribute((const void*)mma_gemm_kernel<true>,
                         cudaFuncAttributeMaxDynamicSharedMemorySize, GEMM_SMEM);

    const int n4 = Mrows * Dc / 4;
    dim3 wgrid(16, 16, 5), wblk(32, 8);
    dim3 g1(Dc / 128, Mrows / 128);        // (4, 64)
    dim3 gq(QKV_LD / 128, Mrows / 128);    // (12, 64)
    dim3 agrid(Nc / 128, Hc, Bc);          // (4, 8, 16)

    // 1) weight prep + x split
    wprep_kernel<<<wgrid, wblk>>>(W_w, Wq, Wk, Wv, Wo, bq, bk, bv, whi, wlo, bias3);
    split_kernel<<<n4 / 256, 256>>>(x, ahi, alo, n4);
    // 2) h = x @ W_w + W_b
    mma_gemm_kernel<false><<<g1, 256, GEMM_SMEM>>>(ahi, alo, whi, wlo, W_b, h, Dc);
    // 3) LN(h) -> hi/lo split
    ln_split_kernel<<<Mrows / 8, 256>>>(h, ln_g, ln_b, ahi, alo);
    // 4) fused QKV GEMM
    mma_gemm_kernel<false><<<gq, 256, GEMM_SMEM>>>(ahi, alo, whi + DD, wlo + DD, bias3, qkv, QKV_LD);
    // 5) mma flash attention -> ctx hi/lo (overwrites ahi/alo)
    attn_mma_kernel<<<agrid, 256, ATTN_SMEM>>>(qkv, adj, use_adj, ahi, alo);
    // 6) h2 = relu(ctx @ Wo + bo)
    mma_gemm_kernel<true><<<g1, 256, GEMM_SMEM>>>(ahi, alo, whi + 4 * DD, wlo + 4 * DD, bo, h2, Dc);
    // 7) gated residual output
    gate_kernel<<<Mrows / 8, 256>>>(x, h2, gw, gb, out);
}

// round 7
// speedup vs baseline: 2.3046x; 1.0344x over previous
#include <cuda_runtime.h>
#include <cuda_bf16.h>
#include <math.h>
#include <cstdint>

// Problem constants
constexpr int Bc = 16, Nc = 512, Dc = 512, Hc = 8, DKc = 64;
constexpr int Mrows = Bc * Nc;          // 8192
constexpr int QKV_LD = 3 * Dc;          // 1536
constexpr float SCALE = 0.125f;         // DK^-0.5 (exact power of 2)
constexpr float LN_EPS = 1e-5f;
constexpr int DD = Dc * Dc;

// ---------------------------------------------------------------------------
// Scratch (static device arrays; no allocation allowed)
// ---------------------------------------------------------------------------
__device__ float g_h[Mrows * Dc];
__device__ float g_h2[Mrows * Dc];
__device__ float g_vbuf[Mrows * Dc];
__device__ __nv_bfloat16 g_ahi[Mrows * Dc];
__device__ __nv_bfloat16 g_alo[Mrows * Dc];
__device__ __nv_bfloat16 g_qhi[Mrows * Dc];
__device__ __nv_bfloat16 g_qlo[Mrows * Dc];
__device__ __nv_bfloat16 g_khi[Mrows * Dc];
__device__ __nv_bfloat16 g_klo[Mrows * Dc];
__device__ __nv_bfloat16 g_whi[5 * DD];   // transposed weights [N][K], 5 slots
__device__ __nv_bfloat16 g_wlo[5 * DD];
__device__ float g_bias3[QKV_LD];

// ---------------------------------------------------------------------------
// PTX helpers
// ---------------------------------------------------------------------------
__device__ __forceinline__ uint32_t smem_u32(const void* p) {
    uint32_t a;
    asm("{ .reg .u64 t; cvta.to.shared.u64 t, %1; cvt.u32.u64 %0, t; }" : "=r"(a) : "l"(p));
    return a;
}
__device__ __forceinline__ void ldmx4(uint32_t* r, uint32_t addr) {
    asm volatile("ldmatrix.sync.aligned.m8n8.x4.shared.b16 {%0,%1,%2,%3}, [%4];"
                 : "=r"(r[0]), "=r"(r[1]), "=r"(r[2]), "=r"(r[3]) : "r"(addr));
}
__device__ __forceinline__ void mma16816(float* c, const uint32_t* a, const uint32_t* b) {
    asm volatile("mma.sync.aligned.m16n8k16.row.col.f32.bf16.bf16.f32 "
                 "{%0,%1,%2,%3}, {%4,%5,%6,%7}, {%8,%9}, {%0,%1,%2,%3};"
                 : "+f"(c[0]), "+f"(c[1]), "+f"(c[2]), "+f"(c[3])
                 : "r"(a[0]), "r"(a[1]), "r"(a[2]), "r"(a[3]), "r"(b[0]), "r"(b[1]));
}
__device__ __forceinline__ void cpasync16(uint32_t dst, const void* src) {
    asm volatile("cp.async.cg.shared.global [%0], [%1], 16;" :: "r"(dst), "l"(src));
}
#define CP_COMMIT() asm volatile("cp.async.commit_group;" ::: "memory")
#define CP_WAIT(N)  asm volatile("cp.async.wait_group %0;" :: "n"(N) : "memory")

// float pair -> bf16x2 hi and lo (split)
__device__ __forceinline__ void pack_hilo(float x, float y, uint32_t& hi, uint32_t& lo) {
    __nv_bfloat16 hx = __float2bfloat16(x), hy = __float2bfloat16(y);
    __nv_bfloat16 lx = __float2bfloat16(x - __bfloat162float(hx));
    __nv_bfloat16 ly = __float2bfloat16(y - __bfloat162float(hy));
    __nv_bfloat162 H(hx, hy), L(lx, ly);
    hi = *(uint32_t*)&H;
    lo = *(uint32_t*)&L;
}

// ---------------------------------------------------------------------------
// fp32 -> bf16 hi/lo split (elementwise)
// ---------------------------------------------------------------------------
__global__ void split_kernel(const float* __restrict__ x,
                             __nv_bfloat16* __restrict__ hi, __nv_bfloat16* __restrict__ lo,
                             int n4) {
    int i = blockIdx.x * blockDim.x + threadIdx.x;
    if (i >= n4) return;
    float4 v = ((const float4*)x)[i];
    uint32_t h0, l0, h1, l1;
    pack_hilo(v.x, v.y, h0, l0);
    pack_hilo(v.z, v.w, h1, l1);
    ((uint32_t*)hi)[2 * i] = h0; ((uint32_t*)hi)[2 * i + 1] = h1;
    ((uint32_t*)lo)[2 * i] = l0; ((uint32_t*)lo)[2 * i + 1] = l1;
}

// ---------------------------------------------------------------------------
// Weight prep: transpose+split all 5 weights [K,N]->[N,K] hi/lo, pack qkv bias.
// ---------------------------------------------------------------------------
__global__ void wprep_kernel(const float* __restrict__ W_w, const float* __restrict__ Wq,
                             const float* __restrict__ Wk, const float* __restrict__ Wv,
                             const float* __restrict__ Wo,
                             const float* __restrict__ bq, const float* __restrict__ bk,
                             const float* __restrict__ bv,
                             __nv_bfloat16* __restrict__ hi, __nv_bfloat16* __restrict__ lo,
                             float* __restrict__ b3)
{
    __shared__ float t[32][33];
    const float* Ws[5] = {W_w, Wq, Wk, Wv, Wo};
    const int z = blockIdx.z;
    const float* W = Ws[z];
    __nv_bfloat16* ho = hi + (size_t)z * DD;
    __nv_bfloat16* lop = lo + (size_t)z * DD;

    const int bx = blockIdx.x * 32;
    const int by = blockIdx.y * 32;
    const int tx = threadIdx.x, ty = threadIdx.y;

    if (z == 0 && blockIdx.x == 0 && blockIdx.y == 0) {
        int tt = ty * 32 + tx;
        for (int i = tt; i < QKV_LD; i += 256)
            b3[i] = (i < Dc) ? bq[i] : (i < 2 * Dc) ? bk[i - Dc] : bv[i - 2 * Dc];
    }

    #pragma unroll
    for (int j = 0; j < 32; j += 8)
        t[ty + j][tx] = W[(size_t)(by + ty + j) * Dc + bx + tx];
    __syncthreads();
    #pragma unroll
    for (int j = 0; j < 32; j += 8) {
        float v = t[tx][ty + j];
        __nv_bfloat16 h = __float2bfloat16(v);
        size_t o = (size_t)(bx + ty + j) * Dc + by + tx;
        ho[o] = h;
        lop[o] = __float2bfloat16(v - __bfloat162float(h));
    }
}

// ---------------------------------------------------------------------------
// cp.async pipelined mma.sync bf16 split GEMM.
// MODE 0: fp32 C + bias. MODE 1: relu(fp32 C + bias). MODE 2: qkv epilogue
// (q -> pre-scaled bf16 hi/lo, k -> bf16 hi/lo, v -> fp32), uniform per CTA.
// ---------------------------------------------------------------------------
constexpr int GPAD = 40;
constexpr int GTILE_B = 128 * GPAD * 2;   // 10240
constexpr int GSTAGE_B = 4 * GTILE_B;     // 40960
constexpr int GEMM_SMEM = 2 * GSTAGE_B;   // 81920 -> 2 CTAs/SM

template<int MODE>
__global__ void __launch_bounds__(256, 2) mma_gemm_kernel(
    const __nv_bfloat16* __restrict__ Ahi, const __nv_bfloat16* __restrict__ Alo,
    const __nv_bfloat16* __restrict__ Bhi, const __nv_bfloat16* __restrict__ Blo,
    const float* __restrict__ bias, float* __restrict__ C, int ldc,
    __nv_bfloat16* __restrict__ qhi, __nv_bfloat16* __restrict__ qlo,
    __nv_bfloat16* __restrict__ khi, __nv_bfloat16* __restrict__ klo,
    float* __restrict__ vbuf)
{
    extern __shared__ char smem[];
    const uint32_t sbase = smem_u32(smem);
    const int tid = threadIdx.x, wid = tid >> 5, lane = tid & 31;
    const int m0 = blockIdx.y * 128, n0 = blockIdx.x * 128;
    const int wm = wid & 1, wn = wid >> 1;

    const uint32_t aRow = wm * 64 + (lane & 15);
    const uint32_t aCol = (lane < 16) ? 0 : 8;
    const uint32_t aOffB = (aRow * GPAD + aCol) * 2;
    const uint32_t bRow4 = ((lane >> 4) & 1) * 8 + (lane & 7);
    const uint32_t bCol4 = ((lane >> 3) & 1) * 8;

    const int ldRow = tid >> 2, ldSeg = tid & 3;
    const __nv_bfloat16* srcA[4] = {Ahi, Alo, Bhi, Blo};

    auto issue_stage = [&](int c, uint32_t stOff) {
        const int k0 = c * 32;
        #pragma unroll
        for (int t = 0; t < 4; t++) {
            const __nv_bfloat16* src = srcA[t];
            const int base = (t < 2) ? m0 : n0;
            #pragma unroll
            for (int j = 0; j < 2; j++) {
                int row = ldRow + j * 64;
                uint32_t dst = sbase + stOff + t * GTILE_B + (row * GPAD + ldSeg * 8) * 2;
                cpasync16(dst, src + (size_t)(base + row) * Dc + k0 + ldSeg * 8);
            }
        }
        CP_COMMIT();
    };

    float acc[4][4][4] = {};

    constexpr int NCH = Dc / 32;
    issue_stage(0, 0);
    issue_stage(1, GSTAGE_B);

    for (int c = 0; c < NCH; c++) {
        const uint32_t stOff = (c & 1) * GSTAGE_B;
        CP_WAIT(1);
        __syncthreads();

        const uint32_t sAhi = sbase + stOff + 0 * GTILE_B;
        const uint32_t sAlo = sbase + stOff + 1 * GTILE_B;
        const uint32_t sBhi = sbase + stOff + 2 * GTILE_B;
        const uint32_t sBlo = sbase + stOff + 3 * GTILE_B;

        #pragma unroll
        for (int ks = 0; ks < 2; ks++) {
            const uint32_t kOffB = ks * 32;
            uint32_t ahi[4][4], alo[4][4], bhi[2][4], blo[2][4];
            #pragma unroll
            for (int i = 0; i < 4; i++) {
                uint32_t ao = aOffB + kOffB + i * 16 * GPAD * 2;
                ldmx4(ahi[i], sAhi + ao);
                ldmx4(alo[i], sAlo + ao);
            }
            #pragma unroll
            for (int jp = 0; jp < 2; jp++) {
                uint32_t bo = ((wn * 32 + jp * 16 + bRow4) * GPAD + bCol4) * 2 + kOffB;
                ldmx4(bhi[jp], sBhi + bo);
                ldmx4(blo[jp], sBlo + bo);
            }
            #pragma unroll
            for (int i = 0; i < 4; i++)
                #pragma unroll
                for (int j = 0; j < 4; j++) {
                    const int jp = j >> 1, hf = (j & 1) * 2;
                    mma16816(acc[i][j], ahi[i], &bhi[jp][hf]);
                    mma16816(acc[i][j], ahi[i], &blo[jp][hf]);
                    mma16816(acc[i][j], alo[i], &bhi[jp][hf]);
                }
        }
        __syncthreads();
        if (c + 2 < NCH) issue_stage(c + 2, stOff);
    }

    const int lr = lane >> 2, lc = (lane & 3) * 2;
    #pragma unroll
    for (int i = 0; i < 4; i++) {
        const int row0 = m0 + wm * 64 + i * 16 + lr;
        #pragma unroll
        for (int j = 0; j < 4; j++) {
            const int col = n0 + wn * 32 + j * 8 + lc;
            float b0 = bias[col], b1 = bias[col + 1];
            float v0 = acc[i][j][0] + b0, v1 = acc[i][j][1] + b1;   // row0
            float v2 = acc[i][j][2] + b0, v3 = acc[i][j][3] + b1;   // row0+8
            if (MODE == 2) {
                // segment is uniform per CTA (n0 is 128-aligned, segments 512-aligned)
                if (n0 < Dc) {           // q: pre-scaled hi/lo bf16
                    size_t o0 = (size_t)row0 * Dc + col;
                    size_t o1 = o0 + 8 * (size_t)Dc;
                    uint32_t h0, l0, h1, l1;
                    pack_hilo(v0 * SCALE, v1 * SCALE, h0, l0);
                    pack_hilo(v2 * SCALE, v3 * SCALE, h1, l1);
                    *(uint32_t*)(qhi + o0) = h0; *(uint32_t*)(qlo + o0) = l0;
                    *(uint32_t*)(qhi + o1) = h1; *(uint32_t*)(qlo + o1) = l1;
                } else if (n0 < 2 * Dc) { // k: hi/lo bf16
                    size_t o0 = (size_t)row0 * Dc + col - Dc;
                    size_t o1 = o0 + 8 * (size_t)Dc;
                    uint32_t h0, l0, h1, l1;
                    pack_hilo(v0, v1, h0, l0);
                    pack_hilo(v2, v3, h1, l1);
                    *(uint32_t*)(khi + o0) = h0; *(uint32_t*)(klo + o0) = l0;
                    *(uint32_t*)(khi + o1) = h1; *(uint32_t*)(klo + o1) = l1;
                } else {                  // v: fp32
                    size_t o0 = (size_t)row0 * Dc + col - 2 * Dc;
                    size_t o1 = o0 + 8 * (size_t)Dc;
                    *(float2*)(vbuf + o0) = make_float2(v0, v1);
                    *(float2*)(vbuf + o1) = make_float2(v2, v3);
                }
            } else {
                if (MODE == 1) {
                    v0 = fmaxf(v0, 0.f); v1 = fmaxf(v1, 0.f);
                    v2 = fmaxf(v2, 0.f); v3 = fmaxf(v3, 0.f);
                }
                *(float2*)(C + (size_t)row0 * ldc + col) = make_float2(v0, v1);
                *(float2*)(C + (size_t)(row0 + 8) * ldc + col) = make_float2(v2, v3);
            }
        }
    }
}

// ---------------------------------------------------------------------------
// LayerNorm over rows of 512, writing bf16 hi/lo split directly.
// ---------------------------------------------------------------------------
__global__ void ln_split_kernel(const float* __restrict__ hsrc,
                                const float* __restrict__ g, const float* __restrict__ b,
                                __nv_bfloat16* __restrict__ hi, __nv_bfloat16* __restrict__ lo)
{
    int warp = (blockIdx.x * blockDim.x + threadIdx.x) >> 5;
    int lane = threadIdx.x & 31;
    if (warp >= Mrows) return;
    const float* row = hsrc + (size_t)warp * Dc;

    float vals[16];
    float s = 0.f;
    #pragma unroll
    for (int i = 0; i < 16; i++) { vals[i] = row[lane + i * 32]; s += vals[i]; }
    #pragma unroll
    for (int o = 16; o > 0; o >>= 1) s += __shfl_xor_sync(0xffffffffu, s, o);
    float mu = s * (1.f / 512.f);

    float vsum = 0.f;
    #pragma unroll
    for (int i = 0; i < 16; i++) { float d = vals[i] - mu; vsum += d * d; }
    #pragma unroll
    for (int o = 16; o > 0; o >>= 1) vsum += __shfl_xor_sync(0xffffffffu, vsum, o);
    float inv = rsqrtf(vsum * (1.f / 512.f) + LN_EPS);

    #pragma unroll
    for (int i = 0; i < 16; i++) {
        int c = lane + i * 32;
        float v = (vals[i] - mu) * inv * g[c] + b[c];
        __nv_bfloat16 h = __float2bfloat16(v);
        hi[(size_t)warp * Dc + c] = h;
        lo[(size_t)warp * Dc + c] = __float2bfloat16(v - __bfloat162float(h));
    }
}

// ---------------------------------------------------------------------------
// mma.sync flash attention, occ-2 variant.
// Q/K pre-split bf16 in gmem (Q pre-scaled) -> cp.async straight into smem.
// V fp32 -> transposed hi/lo convert in-kernel. kv tile = 64.
// Masked logit = exactly 0.0 (reference: where(adj>0,s,NEG)*adj).
// ---------------------------------------------------------------------------
constexpr int APAD = 72;      // smem row stride (bf16) for Q/K/Vt
constexpr int ATTN_SMEM = (2 * 128 * APAD + 4 * 64 * APAD) * 2;   // 73728 B

__global__ void __launch_bounds__(256, 2) attn_mma_kernel(
    const __nv_bfloat16* __restrict__ qhi, const __nv_bfloat16* __restrict__ qlo,
    const __nv_bfloat16* __restrict__ khi, const __nv_bfloat16* __restrict__ klo,
    const float* __restrict__ vbuf, const float* __restrict__ adj,
    const int* __restrict__ use_adj_p,
    __nv_bfloat16* __restrict__ chi, __nv_bfloat16* __restrict__ clo)
{
    extern __shared__ __nv_bfloat16 smb[];
    __nv_bfloat16* Qhi = smb;
    __nv_bfloat16* Qlo = smb + 128 * APAD;
    __nv_bfloat16* Khi = smb + 2 * 128 * APAD;
    __nv_bfloat16* Klo = Khi + 64 * APAD;
    __nv_bfloat16* Vthi = Klo + 64 * APAD;
    __nv_bfloat16* Vtlo = Vthi + 64 * APAD;

    const uint32_t sQhi = smem_u32(Qhi), sQlo = smem_u32(Qlo);
    const uint32_t sKhi = smem_u32(Khi), sKlo = smem_u32(Klo);
    const uint32_t sVthi = smem_u32(Vthi), sVtlo = smem_u32(Vtlo);

    const int b = blockIdx.z, h = blockIdx.y;
    const int q0 = blockIdx.x * 128;
    const int tid = threadIdx.x, wid = tid >> 5, lane = tid & 31;
    const bool mask = (*use_adj_p) != 0;

    // ---- Q tile [128 x 64] bf16 hi/lo via cp.async ----
    #pragma unroll
    for (int i = 0; i < 4; i++) {
        int ch = tid + i * 256;          // 1024 chunks of 16B per buffer
        int r = ch >> 3, seg = ch & 7;
        size_t gs = (size_t)(b * Nc + q0 + r) * Dc + h * DKc + seg * 8;
        uint32_t so = (r * APAD + seg * 8) * 2;
        cpasync16(sQhi + so, qhi + gs);
        cpasync16(sQlo + so, qlo + gs);
    }
    CP_COMMIT();

    const uint32_t aRow = wid * 16 + (lane & 15);
    const uint32_t aCol = (lane < 16) ? 0 : 8;
    const uint32_t aOff = (aRow * APAD + aCol) * 2;
    const uint32_t bRow4 = ((lane >> 4) & 1) * 8 + (lane & 7);
    const uint32_t bCol4 = ((lane >> 3) & 1) * 8;

    const int lr = lane >> 2, lc2 = (lane & 3) * 2;
    const int grow0 = q0 + wid * 16 + lr;

    float O[8][4] = {};
    float m0r = -INFINITY, m1r = -INFINITY, l0r = 0.f, l1r = 0.f;

    for (int kt = 0; kt < 8; kt++) {
        const int k0 = kt * 64;
        __syncthreads();   // previous tile's consumers done

        // ---- K tile [64 x 64] bf16 hi/lo via cp.async ----
        #pragma unroll
        for (int i = 0; i < 2; i++) {
            int ch = tid + i * 256;      // 512 chunks per buffer
            int r = ch >> 3, seg = ch & 7;
            size_t gs = (size_t)(b * Nc + k0 + r) * Dc + h * DKc + seg * 8;
            uint32_t so = (r * APAD + seg * 8) * 2;
            cpasync16(sKhi + so, khi + gs);
            cpasync16(sKlo + so, klo + gs);
        }
        CP_COMMIT();

        // ---- V tile [64 tok x 64 d] fp32 -> transposed hi/lo [d][tok] ----
        #pragma unroll
        for (int i = 0; i < 4; i++) {
            int ch = tid + i * 256;      // 1024 float4 chunks
            int r = ch >> 4, c4 = (ch & 15) * 4;
            float4 t = *(const float4*)(vbuf + (size_t)(b * Nc + k0 + r) * Dc + h * DKc + c4);
            float vv[4] = {t.x, t.y, t.z, t.w};
            #pragma unroll
            for (int u = 0; u < 4; u++) {
                __nv_bfloat16 hv = __float2bfloat16(vv[u]);
                Vthi[(c4 + u) * APAD + r] = hv;
                Vtlo[(c4 + u) * APAD + r] = __float2bfloat16(vv[u] - __bfloat162float(hv));
            }
        }
        CP_WAIT(0);
        __syncthreads();

        // ---- S = Q @ K^T : warp computes [16 x 64] ----
        float s[8][4];
        #pragma unroll
        for (int j = 0; j < 8; j++)
            #pragma unroll
            for (int u = 0; u < 4; u++) s[j][u] = 0.f;

        #pragma unroll
        for (int ks = 0; ks < 4; ks++) {
            const uint32_t kOff = ks * 32;
            uint32_t ahi[4], alo[4];
            ldmx4(ahi, sQhi + aOff + kOff);
            ldmx4(alo, sQlo + aOff + kOff);
            #pragma unroll
            for (int jp = 0; jp < 4; jp++) {
                uint32_t bo = ((jp * 16 + bRow4) * APAD + bCol4) * 2 + kOff;
                uint32_t bh[4], bl[4];
                ldmx4(bh, sKhi + bo);
                ldmx4(bl, sKlo + bo);
                mma16816(s[2 * jp],     ahi, &bh[0]);
                mma16816(s[2 * jp],     ahi, &bl[0]);
                mma16816(s[2 * jp],     alo, &bh[0]);
                mma16816(s[2 * jp + 1], ahi, &bh[2]);
                mma16816(s[2 * jp + 1], ahi, &bl[2]);
                mma16816(s[2 * jp + 1], alo, &bh[2]);
            }
        }

        // ---- mask (Q pre-scaled; masked logit = 0.0) ----
        if (mask) {
            const float* arow0 = adj + ((size_t)(b * Nc + grow0)) * Nc + k0 + lc2;
            const float* arow1 = arow0 + 8 * Nc;
            #pragma unroll
            for (int j = 0; j < 8; j++) {
                float2 a0 = *(const float2*)(arow0 + j * 8);
                float2 a1 = *(const float2*)(arow1 + j * 8);
                s[j][0] = (a0.x > 0.f) ? s[j][0] : 0.f;
                s[j][1] = (a0.y > 0.f) ? s[j][1] : 0.f;
                s[j][2] = (a1.x > 0.f) ? s[j][2] : 0.f;
                s[j][3] = (a1.y > 0.f) ? s[j][3] : 0.f;
            }
        }

        // ---- online softmax (rows lr, lr+8; reduce over quad lanes) ----
        float rm0 = -INFINITY, rm1 = -INFINITY;
        #pragma unroll
        for (int j = 0; j < 8; j++) {
            rm0 = fmaxf(rm0, fmaxf(s[j][0], s[j][1]));
            rm1 = fmaxf(rm1, fmaxf(s[j][2], s[j][3]));
        }
        rm0 = fmaxf(rm0, __shfl_xor_sync(0xffffffffu, rm0, 1));
        rm0 = fmaxf(rm0, __shfl_xor_sync(0xffffffffu, rm0, 2));
        rm1 = fmaxf(rm1, __shfl_xor_sync(0xffffffffu, rm1, 1));
        rm1 = fmaxf(rm1, __shfl_xor_sync(0xffffffffu, rm1, 2));

        float mn0 = fmaxf(m0r, rm0), mn1 = fmaxf(m1r, rm1);
        float al0 = __expf(m0r - mn0), al1 = __expf(m1r - mn1);
        m0r = mn0; m1r = mn1;

        float ps0 = 0.f, ps1 = 0.f;
        #pragma unroll
        for (int j = 0; j < 8; j++) {
            s[j][0] = __expf(s[j][0] - mn0);
            s[j][1] = __expf(s[j][1] - mn0);
            s[j][2] = __expf(s[j][2] - mn1);
            s[j][3] = __expf(s[j][3] - mn1);
            ps0 += s[j][0] + s[j][1];
            ps1 += s[j][2] + s[j][3];
        }
        ps0 += __shfl_xor_sync(0xffffffffu, ps0, 1);
        ps0 += __shfl_xor_sync(0xffffffffu, ps0, 2);
        ps1 += __shfl_xor_sync(0xffffffffu, ps1, 1);
        ps1 += __shfl_xor_sync(0xffffffffu, ps1, 2);
        l0r = l0r * al0 + ps0;
        l1r = l1r * al1 + ps1;

        #pragma unroll
        for (int jd = 0; jd < 8; jd++) {
            O[jd][0] *= al0; O[jd][1] *= al0;
            O[jd][2] *= al1; O[jd][3] *= al1;
        }

        // ---- O += P @ V ----
        #pragma unroll
        for (int kk = 0; kk < 4; kk++) {
            uint32_t aHi[4], aLo[4];
            pack_hilo(s[2 * kk][0],     s[2 * kk][1],     aHi[0], aLo[0]);
            pack_hilo(s[2 * kk][2],     s[2 * kk][3],     aHi[1], aLo[1]);
            pack_hilo(s[2 * kk + 1][0], s[2 * kk + 1][1], aHi[2], aLo[2]);
            pack_hilo(s[2 * kk + 1][2], s[2 * kk + 1][3], aHi[3], aLo[3]);
            const uint32_t kOff = kk * 32;
            #pragma unroll
            for (int jdp = 0; jdp < 4; jdp++) {
                uint32_t bo = ((jdp * 16 + bRow4) * APAD + bCol4) * 2 + kOff;
                uint32_t bh[4], bl[4];
                ldmx4(bh, sVthi + bo);
                ldmx4(bl, sVtlo + bo);
                mma16816(O[2 * jdp],     aHi, &bh[0]);
                mma16816(O[2 * jdp],     aHi, &bl[0]);
                mma16816(O[2 * jdp],     aLo, &bh[0]);
                mma16816(O[2 * jdp + 1], aHi, &bh[2]);
                mma16816(O[2 * jdp + 1], aHi, &bl[2]);
                mma16816(O[2 * jdp + 1], aLo, &bh[2]);
            }
        }
    }

    // ---- epilogue: normalize, split to bf16 hi/lo, store ctx ----
    const float inv0 = 1.f / l0r, inv1 = 1.f / l1r;
    #pragma unroll
    for (int jd = 0; jd < 8; jd++) {
        size_t o0 = ((size_t)(b * Nc + grow0)) * Dc + h * DKc + jd * 8 + lc2;
        size_t o1 = o0 + 8 * (size_t)Dc;
        uint32_t h0, l0, h1, l1;
        pack_hilo(O[jd][0] * inv0, O[jd][1] * inv0, h0, l0);
        pack_hilo(O[jd][2] * inv1, O[jd][3] * inv1, h1, l1);
        *(uint32_t*)(chi + o0) = h0;
        *(uint32_t*)(clo + o0) = l0;
        *(uint32_t*)(chi + o1) = h1;
        *(uint32_t*)(clo + o1) = l1;
    }
}

// ---------------------------------------------------------------------------
// Gate: coeff = sigmoid([x,h2] . gate_w + gate_b); out = c*x + (1-c)*h2.
// ---------------------------------------------------------------------------
__global__ void gate_kernel(const float* __restrict__ x, const float* __restrict__ h2,
                            const float* __restrict__ gw, const float* __restrict__ gb,
                            float* __restrict__ out)
{
    int warp = (blockIdx.x * blockDim.x + threadIdx.x) >> 5;
    int lane = threadIdx.x & 31;
    if (warp >= Mrows) return;
    const float* xr = x + (size_t)warp * Dc;
    const float* hr = h2 + (size_t)warp * Dc;

    float dot = 0.f;
    #pragma unroll
    for (int i = 0; i < 16; i++) {
        int c = lane + i * 32;
        dot += xr[c] * gw[c] + hr[c] * gw[Dc + c];
    }
    #pragma unroll
    for (int o = 16; o > 0; o >>= 1) dot += __shfl_xor_sync(0xffffffffu, dot, o);

    float z = dot + gb[0];
    float cf = 1.f / (1.f + __expf(-z));
    #pragma unroll
    for (int i = 0; i < 16; i++) {
        int c = lane + i * 32;
        out[(size_t)warp * Dc + c] = cf * xr[c] + (1.f - cf) * hr[c];
    }
}

// ---------------------------------------------------------------------------
extern "C" void kernel_launch(void* const* d_in, const int* in_sizes, int n_in,
                              void* d_out, int out_size)
{
    const float* x    = (const float*)d_in[0];
    const float* adj  = (const float*)d_in[1];
    const float* W_w  = (const float*)d_in[2];
    const float* W_b  = (const float*)d_in[3];
    const float* ln_g = (const float*)d_in[4];
    const float* ln_b = (const float*)d_in[5];
    const float* Wq   = (const float*)d_in[6];
    const float* bq   = (const float*)d_in[7];
    const float* Wk   = (const float*)d_in[8];
    const float* bk   = (const float*)d_in[9];
    const float* Wv   = (const float*)d_in[10];
    const float* bv   = (const float*)d_in[11];
    const float* Wo   = (const float*)d_in[12];
    const float* bo   = (const float*)d_in[13];
    const float* gw   = (const float*)d_in[14];
    const float* gb   = (const float*)d_in[15];
    const int* use_adj = (const int*)d_in[16];
    float* out = (float*)d_out;

    float *h, *h2, *vbuf, *bias3;
    __nv_bfloat16 *ahi, *alo, *whi, *wlo, *qhi, *qlo, *khi, *klo;
    cudaGetSymbolAddress((void**)&h,    g_h);
    cudaGetSymbolAddress((void**)&h2,   g_h2);
    cudaGetSymbolAddress((void**)&vbuf, g_vbuf);
    cudaGetSymbolAddress((void**)&ahi,  g_ahi);
    cudaGetSymbolAddress((void**)&alo,  g_alo);
    cudaGetSymbolAddress((void**)&qhi,  g_qhi);
    cudaGetSymbolAddress((void**)&qlo,  g_qlo);
    cudaGetSymbolAddress((void**)&khi,  g_khi);
    cudaGetSymbolAddress((void**)&klo,  g_klo);
    cudaGetSymbolAddress((void**)&whi,  g_whi);
    cudaGetSymbolAddress((void**)&wlo,  g_wlo);
    cudaGetSymbolAddress((void**)&bias3, g_bias3);

    cudaFuncSetAttribute(attn_mma_kernel, cudaFuncAttributeMaxDynamicSharedMemorySize, ATTN_SMEM);
    cudaFuncSetAttribute((const void*)mma_gemm_kernel<0>,
                         cudaFuncAttributeMaxDynamicSharedMemorySize, GEMM_SMEM);
    cudaFuncSetAttribute((const void*)mma_gemm_kernel<1>,
                         cudaFuncAttributeMaxDynamicSharedMemorySize, GEMM_SMEM);
    cudaFuncSetAttribute((const void*)mma_gemm_kernel<2>,
                         cudaFuncAttributeMaxDynamicSharedMemorySize, GEMM_SMEM);

    const int n4 = Mrows * Dc / 4;
    dim3 wgrid(16, 16, 5), wblk(32, 8);
    dim3 g1(Dc / 128, Mrows / 128);        // (4, 64)
    dim3 gq(QKV_LD / 128, Mrows / 128);    // (12, 64)
    dim3 agrid(Nc / 128, Hc, Bc);          // (4, 8, 16)

    // 1) weight prep + x split
    wprep_kernel<<<wgrid, wblk>>>(W_w, Wq, Wk, Wv, Wo, bq, bk, bv, whi, wlo, bias3);
    split_kernel<<<n4 / 256, 256>>>(x, ahi, alo, n4);
    // 2) h = x @ W_w + W_b
    mma_gemm_kernel<0><<<g1, 256, GEMM_SMEM>>>(ahi, alo, whi, wlo, W_b, h, Dc,
                                               nullptr, nullptr, nullptr, nullptr, nullptr);
    // 3) LN(h) -> hi/lo split
    ln_split_kernel<<<Mrows / 8, 256>>>(h, ln_g, ln_b, ahi, alo);
    // 4) fused QKV GEMM -> q hi/lo (pre-scaled), k hi/lo, v fp32
    mma_gemm_kernel<2><<<gq, 256, GEMM_SMEM>>>(ahi, alo, whi + DD, wlo + DD, bias3,
                                               nullptr, 0, qhi, qlo, khi, klo, vbuf);
    // 5) mma flash attention -> ctx hi/lo (overwrites ahi/alo)
    attn_mma_kernel<<<agrid, 256, ATTN_SMEM>>>(qhi, qlo, khi, klo, vbuf, adj, use_adj, ahi, alo);
    // 6) h2 = relu(ctx @ Wo + bo)
    mma_gemm_kernel<1><<<g1, 256, GEMM_SMEM>>>(ahi, alo, whi + 4 * DD, wlo + 4 * DD, bo, h2, Dc,
                                               nullptr, nullptr, nullptr, nullptr, nullptr);
    // 7) gated residual output
    gate_kernel<<<Mrows / 8, 256>>>(x, h2, gw, gb, out);
}

// round 8
// speedup vs baseline: 2.4687x; 1.0712x over previous
#include <cuda_runtime.h>
#include <cuda_bf16.h>
#include <math.h>
#include <cstdint>

// Problem constants
constexpr int Bc = 16, Nc = 512, Dc = 512, Hc = 8, DKc = 64;
constexpr int Mrows = Bc * Nc;          // 8192
constexpr int QKV_LD = 3 * Dc;          // 1536
constexpr float SCALE = 0.125f;         // DK^-0.5 (exact power of 2)
constexpr float LN_EPS = 1e-5f;
constexpr int DD = Dc * Dc;

// ---------------------------------------------------------------------------
// Scratch (static device arrays; no allocation allowed)
// ---------------------------------------------------------------------------
__device__ float g_h[Mrows * Dc];
__device__ float g_h2[Mrows * Dc];
__device__ __nv_bfloat16 g_ahi[Mrows * Dc];
__device__ __nv_bfloat16 g_alo[Mrows * Dc];
__device__ __nv_bfloat16 g_qhi[Mrows * Dc];
__device__ __nv_bfloat16 g_qlo[Mrows * Dc];
__device__ __nv_bfloat16 g_khi[Mrows * Dc];
__device__ __nv_bfloat16 g_klo[Mrows * Dc];
__device__ __nv_bfloat16 g_vhi[Mrows * Dc];   // [tok][d] per batch
__device__ __nv_bfloat16 g_vlo[Mrows * Dc];
__device__ __nv_bfloat16 g_vthi[Mrows * Dc];  // [b,h][d][tok]
__device__ __nv_bfloat16 g_vtlo[Mrows * Dc];
__device__ __nv_bfloat16 g_whi[5 * DD];
__device__ __nv_bfloat16 g_wlo[5 * DD];
__device__ float g_bias3[QKV_LD];

// ---------------------------------------------------------------------------
// PTX helpers
// ---------------------------------------------------------------------------
__device__ __forceinline__ uint32_t smem_u32(const void* p) {
    uint32_t a;
    asm("{ .reg .u64 t; cvta.to.shared.u64 t, %1; cvt.u32.u64 %0, t; }" : "=r"(a) : "l"(p));
    return a;
}
__device__ __forceinline__ void ldmx4(uint32_t* r, uint32_t addr) {
    asm volatile("ldmatrix.sync.aligned.m8n8.x4.shared.b16 {%0,%1,%2,%3}, [%4];"
                 : "=r"(r[0]), "=r"(r[1]), "=r"(r[2]), "=r"(r[3]) : "r"(addr));
}
__device__ __forceinline__ void mma16816(float* c, const uint32_t* a, const uint32_t* b) {
    asm volatile("mma.sync.aligned.m16n8k16.row.col.f32.bf16.bf16.f32 "
                 "{%0,%1,%2,%3}, {%4,%5,%6,%7}, {%8,%9}, {%0,%1,%2,%3};"
                 : "+f"(c[0]), "+f"(c[1]), "+f"(c[2]), "+f"(c[3])
                 : "r"(a[0]), "r"(a[1]), "r"(a[2]), "r"(a[3]), "r"(b[0]), "r"(b[1]));
}
__device__ __forceinline__ void cpasync16(uint32_t dst, const void* src) {
    asm volatile("cp.async.cg.shared.global [%0], [%1], 16;" :: "r"(dst), "l"(src));
}
#define CP_COMMIT() asm volatile("cp.async.commit_group;" ::: "memory")
#define CP_WAIT(N)  asm volatile("cp.async.wait_group %0;" :: "n"(N) : "memory")

__device__ __forceinline__ void pack_hilo(float x, float y, uint32_t& hi, uint32_t& lo) {
    __nv_bfloat16 hx = __float2bfloat16(x), hy = __float2bfloat16(y);
    __nv_bfloat16 lx = __float2bfloat16(x - __bfloat162float(hx));
    __nv_bfloat16 ly = __float2bfloat16(y - __bfloat162float(hy));
    __nv_bfloat162 H(hx, hy), L(lx, ly);
    hi = *(uint32_t*)&H;
    lo = *(uint32_t*)&L;
}

// ---------------------------------------------------------------------------
// Weight prep + x split. z<5: weight transpose+split. z>=5: x split slice.
// grid (16,16,21), block (32,8).
// ---------------------------------------------------------------------------
__global__ void wprep_kernel(const float* __restrict__ W_w, const float* __restrict__ Wq,
                             const float* __restrict__ Wk, const float* __restrict__ Wv,
                             const float* __restrict__ Wo, const float* __restrict__ x,
                             const float* __restrict__ bq, const float* __restrict__ bk,
                             const float* __restrict__ bv,
                             __nv_bfloat16* __restrict__ whi, __nv_bfloat16* __restrict__ wlo,
                             __nv_bfloat16* __restrict__ xhi, __nv_bfloat16* __restrict__ xlo,
                             float* __restrict__ b3)
{
    const int z = blockIdx.z;
    const int tx = threadIdx.x, ty = threadIdx.y;

    if (z >= 5) {
        // x split: slice (z-5) covers rows [(z-5)*512, +512); block covers 32x32
        size_t base = (size_t)(z - 5) * 512 * Dc + (size_t)blockIdx.y * 32 * Dc + blockIdx.x * 32;
        #pragma unroll
        for (int j = 0; j < 32; j += 8) {
            size_t o = base + (size_t)(ty + j) * Dc + tx;
            float v = x[o];
            __nv_bfloat16 h = __float2bfloat16(v);
            xhi[o] = h;
            xlo[o] = __float2bfloat16(v - __bfloat162float(h));
        }
        return;
    }

    __shared__ float t[32][33];
    const float* Ws[5] = {W_w, Wq, Wk, Wv, Wo};
    const float* W = Ws[z];
    __nv_bfloat16* ho = whi + (size_t)z * DD;
    __nv_bfloat16* lop = wlo + (size_t)z * DD;

    const int bx = blockIdx.x * 32;
    const int by = blockIdx.y * 32;

    if (z == 0 && blockIdx.x == 0 && blockIdx.y == 0) {
        int tt = ty * 32 + tx;
        for (int i = tt; i < QKV_LD; i += 256)
            b3[i] = (i < Dc) ? bq[i] : (i < 2 * Dc) ? bk[i - Dc] : bv[i - 2 * Dc];
    }

    #pragma unroll
    for (int j = 0; j < 32; j += 8)
        t[ty + j][tx] = W[(size_t)(by + ty + j) * Dc + bx + tx];
    __syncthreads();
    #pragma unroll
    for (int j = 0; j < 32; j += 8) {
        float v = t[tx][ty + j];
        __nv_bfloat16 h = __float2bfloat16(v);
        size_t o = (size_t)(bx + ty + j) * Dc + by + tx;
        ho[o] = h;
        lop[o] = __float2bfloat16(v - __bfloat162float(h));
    }
}

// ---------------------------------------------------------------------------
// V transpose: [b][tok][h][d] hi/lo -> [b,h][d][tok] hi/lo.
// grid (8 tok-tiles, Hc, Bc), block (32,8).
// ---------------------------------------------------------------------------
__global__ void vtprep_kernel(const __nv_bfloat16* __restrict__ vhi,
                              const __nv_bfloat16* __restrict__ vlo,
                              __nv_bfloat16* __restrict__ vthi,
                              __nv_bfloat16* __restrict__ vtlo)
{
    __shared__ __nv_bfloat16 t[64][72];
    const int t0 = blockIdx.x * 64, h = blockIdx.y, b = blockIdx.z;
    const int tid = threadIdx.y * 32 + threadIdx.x;

    const __nv_bfloat16* srcs[2] = {vhi, vlo};
    __nv_bfloat16* dsts[2] = {vthi, vtlo};

    #pragma unroll
    for (int p = 0; p < 2; p++) {
        const __nv_bfloat16* src = srcs[p];
        __nv_bfloat16* dst = dsts[p];
        #pragma unroll
        for (int i = 0; i < 8; i++) {
            int lin = tid + i * 256;
            int tok = lin >> 5, dp = lin & 31;
            uint32_t v = *(const uint32_t*)(src + (size_t)(b * Nc + t0 + tok) * Dc + h * DKc + dp * 2);
            t[tok][dp * 2] = ((__nv_bfloat162*)&v)->x;
            t[tok][dp * 2 + 1] = ((__nv_bfloat162*)&v)->y;
        }
        __syncthreads();
        #pragma unroll
        for (int i = 0; i < 8; i++) {
            int lin = tid + i * 256;
            int d = lin >> 5, tp = lin & 31;
            __nv_bfloat162 o(t[2 * tp][d], t[2 * tp + 1][d]);
            *(uint32_t*)(dst + ((size_t)(b * Hc + h) * DKc + d) * Nc + t0 + 2 * tp) = *(uint32_t*)&o;
        }
        __syncthreads();
    }
}

// ---------------------------------------------------------------------------
// cp.async pipelined mma.sync bf16 split GEMM, single-sync pipeline.
// MODE 0: fp32 C + bias. MODE 1: relu. MODE 2: qkv epilogue
// (q -> pre-scaled bf16 hi/lo, k -> bf16 hi/lo, v -> bf16 hi/lo), uniform/CTA.
// ---------------------------------------------------------------------------
constexpr int GPAD = 40;
constexpr int GTILE_B = 128 * GPAD * 2;   // 10240
constexpr int GSTAGE_B = 4 * GTILE_B;     // 40960
constexpr int GEMM_SMEM = 2 * GSTAGE_B;   // 81920 -> 2 CTAs/SM

template<int MODE>
__global__ void __launch_bounds__(256, 2) mma_gemm_kernel(
    const __nv_bfloat16* __restrict__ Ahi, const __nv_bfloat16* __restrict__ Alo,
    const __nv_bfloat16* __restrict__ Bhi, const __nv_bfloat16* __restrict__ Blo,
    const float* __restrict__ bias, float* __restrict__ C, int ldc,
    __nv_bfloat16* __restrict__ qhi, __nv_bfloat16* __restrict__ qlo,
    __nv_bfloat16* __restrict__ khi, __nv_bfloat16* __restrict__ klo,
    __nv_bfloat16* __restrict__ vhi, __nv_bfloat16* __restrict__ vlo)
{
    extern __shared__ char smem[];
    const uint32_t sbase = smem_u32(smem);
    const int tid = threadIdx.x, wid = tid >> 5, lane = tid & 31;
    const int m0 = blockIdx.y * 128, n0 = blockIdx.x * 128;
    const int wm = wid & 1, wn = wid >> 1;

    const uint32_t aRow = wm * 64 + (lane & 15);
    const uint32_t aCol = (lane < 16) ? 0 : 8;
    const uint32_t aOffB = (aRow * GPAD + aCol) * 2;
    const uint32_t bRow4 = ((lane >> 4) & 1) * 8 + (lane & 7);
    const uint32_t bCol4 = ((lane >> 3) & 1) * 8;

    const int ldRow = tid >> 2, ldSeg = tid & 3;
    const __nv_bfloat16* srcA[4] = {Ahi, Alo, Bhi, Blo};

    auto issue_stage = [&](int c, uint32_t stOff) {
        const int k0 = c * 32;
        #pragma unroll
        for (int t = 0; t < 4; t++) {
            const __nv_bfloat16* src = srcA[t];
            const int base = (t < 2) ? m0 : n0;
            #pragma unroll
            for (int j = 0; j < 2; j++) {
                int row = ldRow + j * 64;
                uint32_t dst = sbase + stOff + t * GTILE_B + (row * GPAD + ldSeg * 8) * 2;
                cpasync16(dst, src + (size_t)(base + row) * Dc + k0 + ldSeg * 8);
            }
        }
        CP_COMMIT();
    };

    float acc[4][4][4] = {};

    constexpr int NCH = Dc / 32;
    issue_stage(0, 0);

    for (int c = 0; c < NCH; c++) {
        const uint32_t stOff = (c & 1) * GSTAGE_B;
        CP_WAIT(0);
        __syncthreads();
        // issue next into the other buffer (consumed at iteration c-1, all
        // warps are past this barrier, so it is free)
        if (c + 1 < NCH) issue_stage(c + 1, (~c & 1) * GSTAGE_B);

        const uint32_t sAhi = sbase + stOff + 0 * GTILE_B;
        const uint32_t sAlo = sbase + stOff + 1 * GTILE_B;
        const uint32_t sBhi = sbase + stOff + 2 * GTILE_B;
        const uint32_t sBlo = sbase + stOff + 3 * GTILE_B;

        #pragma unroll
        for (int ks = 0; ks < 2; ks++) {
            const uint32_t kOffB = ks * 32;
            uint32_t ahi[4][4], alo[4][4], bhi[2][4], blo[2][4];
            #pragma unroll
            for (int i = 0; i < 4; i++) {
                uint32_t ao = aOffB + kOffB + i * 16 * GPAD * 2;
                ldmx4(ahi[i], sAhi + ao);
                ldmx4(alo[i], sAlo + ao);
            }
            #pragma unroll
            for (int jp = 0; jp < 2; jp++) {
                uint32_t bo = ((wn * 32 + jp * 16 + bRow4) * GPAD + bCol4) * 2 + kOffB;
                ldmx4(bhi[jp], sBhi + bo);
                ldmx4(blo[jp], sBlo + bo);
            }
            #pragma unroll
            for (int i = 0; i < 4; i++)
                #pragma unroll
                for (int j = 0; j < 4; j++) {
                    const int jp = j >> 1, hf = (j & 1) * 2;
                    mma16816(acc[i][j], ahi[i], &bhi[jp][hf]);
                    mma16816(acc[i][j], ahi[i], &blo[jp][hf]);
                    mma16816(acc[i][j], alo[i], &bhi[jp][hf]);
                }
        }
    }

    const int lr = lane >> 2, lc = (lane & 3) * 2;
    #pragma unroll
    for (int i = 0; i < 4; i++) {
        const int row0 = m0 + wm * 64 + i * 16 + lr;
        #pragma unroll
        for (int j = 0; j < 4; j++) {
            const int col = n0 + wn * 32 + j * 8 + lc;
            float b0 = bias[col], b1 = bias[col + 1];
            float v0 = acc[i][j][0] + b0, v1 = acc[i][j][1] + b1;
            float v2 = acc[i][j][2] + b0, v3 = acc[i][j][3] + b1;
            if (MODE == 2) {
                uint32_t h0, l0, h1, l1;
                if (n0 < Dc) {            // q: pre-scaled hi/lo
                    size_t o0 = (size_t)row0 * Dc + col;
                    size_t o1 = o0 + 8 * (size_t)Dc;
                    pack_hilo(v0 * SCALE, v1 * SCALE, h0, l0);
                    pack_hilo(v2 * SCALE, v3 * SCALE, h1, l1);
                    *(uint32_t*)(qhi + o0) = h0; *(uint32_t*)(qlo + o0) = l0;
                    *(uint32_t*)(qhi + o1) = h1; *(uint32_t*)(qlo + o1) = l1;
                } else if (n0 < 2 * Dc) { // k: hi/lo
                    size_t o0 = (size_t)row0 * Dc + col - Dc;
                    size_t o1 = o0 + 8 * (size_t)Dc;
                    pack_hilo(v0, v1, h0, l0);
                    pack_hilo(v2, v3, h1, l1);
                    *(uint32_t*)(khi + o0) = h0; *(uint32_t*)(klo + o0) = l0;
                    *(uint32_t*)(khi + o1) = h1; *(uint32_t*)(klo + o1) = l1;
                } else {                  // v: hi/lo (untransposed)
                    size_t o0 = (size_t)row0 * Dc + col - 2 * Dc;
                    size_t o1 = o0 + 8 * (size_t)Dc;
                    pack_hilo(v0, v1, h0, l0);
                    pack_hilo(v2, v3, h1, l1);
                    *(uint32_t*)(vhi + o0) = h0; *(uint32_t*)(vlo + o0) = l0;
                    *(uint32_t*)(vhi + o1) = h1; *(uint32_t*)(vlo + o1) = l1;
                }
            } else {
                if (MODE == 1) {
                    v0 = fmaxf(v0, 0.f); v1 = fmaxf(v1, 0.f);
                    v2 = fmaxf(v2, 0.f); v3 = fmaxf(v3, 0.f);
                }
                *(float2*)(C + (size_t)row0 * ldc + col) = make_float2(v0, v1);
                *(float2*)(C + (size_t)(row0 + 8) * ldc + col) = make_float2(v2, v3);
            }
        }
    }
}

// ---------------------------------------------------------------------------
// LayerNorm over rows of 512, writing bf16 hi/lo split directly.
// ---------------------------------------------------------------------------
__global__ void ln_split_kernel(const float* __restrict__ hsrc,
                                const float* __restrict__ g, const float* __restrict__ b,
                                __nv_bfloat16* __restrict__ hi, __nv_bfloat16* __restrict__ lo)
{
    int warp = (blockIdx.x * blockDim.x + threadIdx.x) >> 5;
    int lane = threadIdx.x & 31;
    if (warp >= Mrows) return;
    const float* row = hsrc + (size_t)warp * Dc;

    float vals[16];
    float s = 0.f;
    #pragma unroll
    for (int i = 0; i < 16; i++) { vals[i] = row[lane + i * 32]; s += vals[i]; }
    #pragma unroll
    for (int o = 16; o > 0; o >>= 1) s += __shfl_xor_sync(0xffffffffu, s, o);
    float mu = s * (1.f / 512.f);

    float vsum = 0.f;
    #pragma unroll
    for (int i = 0; i < 16; i++) { float d = vals[i] - mu; vsum += d * d; }
    #pragma unroll
    for (int o = 16; o > 0; o >>= 1) vsum += __shfl_xor_sync(0xffffffffu, vsum, o);
    float inv = rsqrtf(vsum * (1.f / 512.f) + LN_EPS);

    #pragma unroll
    for (int i = 0; i < 16; i++) {
        int c = lane + i * 32;
        float v = (vals[i] - mu) * inv * g[c] + b[c];
        __nv_bfloat16 h = __float2bfloat16(v);
        hi[(size_t)warp * Dc + c] = h;
        lo[(size_t)warp * Dc + c] = __float2bfloat16(v - __bfloat162float(h));
    }
}

// ---------------------------------------------------------------------------
// mma.sync flash attention; all operands pre-split bf16 in gmem.
// K/V double-buffered cp.async stages, single sync per kv tile.
// Masked logit = exactly 0.0 (reference: where(adj>0,s,NEG)*adj).
// ---------------------------------------------------------------------------
constexpr int APAD = 72;
// bytes: Q hi/lo (2 x 128x72x2 = 36864), 2 stages x 4 tiles x 64x72x2
constexpr int AQ_B = 128 * APAD * 2;            // 18432 per Q buffer
constexpr int ATILE_B = 64 * APAD * 2;          // 9216 per K/V buffer
constexpr int ASTAGE_B = 4 * ATILE_B;           // 36864
constexpr int ATTN_SMEM = 2 * AQ_B + 2 * ASTAGE_B;   // 110592

__global__ void __launch_bounds__(256, 2) attn_mma_kernel(
    const __nv_bfloat16* __restrict__ qhi, const __nv_bfloat16* __restrict__ qlo,
    const __nv_bfloat16* __restrict__ khi, const __nv_bfloat16* __restrict__ klo,
    const __nv_bfloat16* __restrict__ vthi, const __nv_bfloat16* __restrict__ vtlo,
    const float* __restrict__ adj, const int* __restrict__ use_adj_p,
    __nv_bfloat16* __restrict__ chi, __nv_bfloat16* __restrict__ clo)
{
    extern __shared__ char smemc[];
    const uint32_t sbase = smem_u32(smemc);
    const uint32_t sQhi = sbase, sQlo = sbase + AQ_B;
    const uint32_t sStage = sbase + 2 * AQ_B;

    const int b = blockIdx.z, h = blockIdx.y;
    const int q0 = blockIdx.x * 128;
    const int tid = threadIdx.x, wid = tid >> 5, lane = tid & 31;
    const bool mask = (*use_adj_p) != 0;

    // base pointers
    const __nv_bfloat16* vth = vthi + (size_t)(b * Hc + h) * DKc * Nc;
    const __nv_bfloat16* vtl = vtlo + (size_t)(b * Hc + h) * DKc * Nc;

    auto issue_stage = [&](int kt, uint32_t stOff) {
        const int k0 = kt * 64;
        #pragma unroll
        for (int i = 0; i < 2; i++) {
            int ch = tid + i * 256;              // 512 chunks per buffer
            int r = ch >> 3, seg = ch & 7;
            uint32_t so = (r * APAD + seg * 8) * 2;
            size_t gk = (size_t)(b * Nc + k0 + r) * Dc + h * DKc + seg * 8;
            size_t gv = (size_t)r * Nc + k0 + seg * 8;   // r = d row in vt
            cpasync16(stOff + 0 * ATILE_B + so, khi + gk);
            cpasync16(stOff + 1 * ATILE_B + so, klo + gk);
            cpasync16(stOff + 2 * ATILE_B + so, vth + gv);
            cpasync16(stOff + 3 * ATILE_B + so, vtl + gv);
        }
        CP_COMMIT();
    };

    // ---- prologue: Q (hi/lo) + stage 0, one group ----
    #pragma unroll
    for (int i = 0; i < 4; i++) {
        int ch = tid + i * 256;                  // 1024 chunks per buffer
        int r = ch >> 3, seg = ch & 7;
        size_t gs = (size_t)(b * Nc + q0 + r) * Dc + h * DKc + seg * 8;
        uint32_t so = (r * APAD + seg * 8) * 2;
        cpasync16(sQhi + so, qhi + gs);
        cpasync16(sQlo + so, qlo + gs);
    }
    issue_stage(0, sStage);

    const uint32_t aRow = wid * 16 + (lane & 15);
    const uint32_t aCol = (lane < 16) ? 0 : 8;
    const uint32_t aOff = (aRow * APAD + aCol) * 2;
    const uint32_t bRow4 = ((lane >> 4) & 1) * 8 + (lane & 7);
    const uint32_t bCol4 = ((lane >> 3) & 1) * 8;

    const int lr = lane >> 2, lc2 = (lane & 3) * 2;
    const int grow0 = q0 + wid * 16 + lr;

    float O[8][4] = {};
    float m0r = -INFINITY, m1r = -INFINITY, l0r = 0.f, l1r = 0.f;

    for (int kt = 0; kt < 8; kt++) {
        const int k0 = kt * 64;
        const uint32_t stOff = sStage + (kt & 1) * ASTAGE_B;
        CP_WAIT(0);
        __syncthreads();
        if (kt + 1 < 8) issue_stage(kt + 1, sStage + (~kt & 1) * ASTAGE_B);

        const uint32_t sKhi = stOff, sKlo = stOff + ATILE_B;
        const uint32_t sVthi = stOff + 2 * ATILE_B, sVtlo = stOff + 3 * ATILE_B;

        // ---- S = Q @ K^T : warp computes [16 x 64] ----
        float s[8][4];
        #pragma unroll
        for (int j = 0; j < 8; j++)
            #pragma unroll
            for (int u = 0; u < 4; u++) s[j][u] = 0.f;

        #pragma unroll
        for (int ks = 0; ks < 4; ks++) {
            const uint32_t kOff = ks * 32;
            uint32_t ahi[4], alo[4];
            ldmx4(ahi, sQhi + aOff + kOff);
            ldmx4(alo, sQlo + aOff + kOff);
            #pragma unroll
            for (int jp = 0; jp < 4; jp++) {
                uint32_t bo = ((jp * 16 + bRow4) * APAD + bCol4) * 2 + kOff;
                uint32_t bh[4], bl[4];
                ldmx4(bh, sKhi + bo);
                ldmx4(bl, sKlo + bo);
                mma16816(s[2 * jp],     ahi, &bh[0]);
                mma16816(s[2 * jp],     ahi, &bl[0]);
                mma16816(s[2 * jp],     alo, &bh[0]);
                mma16816(s[2 * jp + 1], ahi, &bh[2]);
                mma16816(s[2 * jp + 1], ahi, &bl[2]);
                mma16816(s[2 * jp + 1], alo, &bh[2]);
            }
        }

        // ---- mask (Q pre-scaled; masked logit = 0.0) ----
        if (mask) {
            const float* arow0 = adj + ((size_t)(b * Nc + grow0)) * Nc + k0 + lc2;
            const float* arow1 = arow0 + 8 * Nc;
            #pragma unroll
            for (int j = 0; j < 8; j++) {
                float2 a0 = *(const float2*)(arow0 + j * 8);
                float2 a1 = *(const float2*)(arow1 + j * 8);
                s[j][0] = (a0.x > 0.f) ? s[j][0] : 0.f;
                s[j][1] = (a0.y > 0.f) ? s[j][1] : 0.f;
                s[j][2] = (a1.x > 0.f) ? s[j][2] : 0.f;
                s[j][3] = (a1.y > 0.f) ? s[j][3] : 0.f;
            }
        }

        // ---- online softmax ----
        float rm0 = -INFINITY, rm1 = -INFINITY;
        #pragma unroll
        for (int j = 0; j < 8; j++) {
            rm0 = fmaxf(rm0, fmaxf(s[j][0], s[j][1]));
            rm1 = fmaxf(rm1, fmaxf(s[j][2], s[j][3]));
        }
        rm0 = fmaxf(rm0, __shfl_xor_sync(0xffffffffu, rm0, 1));
        rm0 = fmaxf(rm0, __shfl_xor_sync(0xffffffffu, rm0, 2));
        rm1 = fmaxf(rm1, __shfl_xor_sync(0xffffffffu, rm1, 1));
        rm1 = fmaxf(rm1, __shfl_xor_sync(0xffffffffu, rm1, 2));

        float mn0 = fmaxf(m0r, rm0), mn1 = fmaxf(m1r, rm1);
        float al0 = __expf(m0r - mn0), al1 = __expf(m1r - mn1);
        m0r = mn0; m1r = mn1;

        float ps0 = 0.f, ps1 = 0.f;
        #pragma unroll
        for (int j = 0; j < 8; j++) {
            s[j][0] = __expf(s[j][0] - mn0);
            s[j][1] = __expf(s[j][1] - mn0);
            s[j][2] = __expf(s[j][2] - mn1);
            s[j][3] = __expf(s[j][3] - mn1);
            ps0 += s[j][0] + s[j][1];
            ps1 += s[j][2] + s[j][3];
        }
        ps0 += __shfl_xor_sync(0xffffffffu, ps0, 1);
        ps0 += __shfl_xor_sync(0xffffffffu, ps0, 2);
        ps1 += __shfl_xor_sync(0xffffffffu, ps1, 1);
        ps1 += __shfl_xor_sync(0xffffffffu, ps1, 2);
        l0r = l0r * al0 + ps0;
        l1r = l1r * al1 + ps1;

        #pragma unroll
        for (int jd = 0; jd < 8; jd++) {
            O[jd][0] *= al0; O[jd][1] *= al0;
            O[jd][2] *= al1; O[jd][3] *= al1;
        }

        // ---- O += P @ V ----
        #pragma unroll
        for (int kk = 0; kk < 4; kk++) {
            uint32_t aHi[4], aLo[4];
            pack_hilo(s[2 * kk][0],     s[2 * kk][1],     aHi[0], aLo[0]);
            pack_hilo(s[2 * kk][2],     s[2 * kk][3],     aHi[1], aLo[1]);
            pack_hilo(s[2 * kk + 1][0], s[2 * kk + 1][1], aHi[2], aLo[2]);
            pack_hilo(s[2 * kk + 1][2], s[2 * kk + 1][3], aHi[3], aLo[3]);
            const uint32_t kOff = kk * 32;
            #pragma unroll
            for (int jdp = 0; jdp < 4; jdp++) {
                uint32_t bo = ((jdp * 16 + bRow4) * APAD + bCol4) * 2 + kOff;
                uint32_t bh[4], bl[4];
                ldmx4(bh, sVthi + bo);
                ldmx4(bl, sVtlo + bo);
                mma16816(O[2 * jdp],     aHi, &bh[0]);
                mma16816(O[2 * jdp],     aHi, &bl[0]);
                mma16816(O[2 * jdp],     aLo, &bh[0]);
                mma16816(O[2 * jdp + 1], aHi, &bh[2]);
                mma16816(O[2 * jdp + 1], aHi, &bl[2]);
                mma16816(O[2 * jdp + 1], aLo, &bh[2]);
            }
        }
    }

    // ---- epilogue: normalize, split to bf16 hi/lo, store ctx ----
    const float inv0 = 1.f / l0r, inv1 = 1.f / l1r;
    #pragma unroll
    for (int jd = 0; jd < 8; jd++) {
        size_t o0 = ((size_t)(b * Nc + grow0)) * Dc + h * DKc + jd * 8 + lc2;
        size_t o1 = o0 + 8 * (size_t)Dc;
        uint32_t h0, l0, h1, l1;
        pack_hilo(O[jd][0] * inv0, O[jd][1] * inv0, h0, l0);
        pack_hilo(O[jd][2] * inv1, O[jd][3] * inv1, h1, l1);
        *(uint32_t*)(chi + o0) = h0;
        *(uint32_t*)(clo + o0) = l0;
        *(uint32_t*)(chi + o1) = h1;
        *(uint32_t*)(clo + o1) = l1;
    }
}

// ---------------------------------------------------------------------------
// Gate: coeff = sigmoid([x,h2] . gate_w + gate_b); out = c*x + (1-c)*h2.
// ---------------------------------------------------------------------------
__global__ void gate_kernel(const float* __restrict__ x, const float* __restrict__ h2,
                            const float* __restrict__ gw, const float* __restrict__ gb,
                            float* __restrict__ out)
{
    int warp = (blockIdx.x * blockDim.x + threadIdx.x) >> 5;
    int lane = threadIdx.x & 31;
    if (warp >= Mrows) return;
    const float* xr = x + (size_t)warp * Dc;
    const float* hr = h2 + (size_t)warp * Dc;

    float dot = 0.f;
    #pragma unroll
    for (int i = 0; i < 16; i++) {
        int c = lane + i * 32;
        dot += xr[c] * gw[c] + hr[c] * gw[Dc + c];
    }
    #pragma unroll
    for (int o = 16; o > 0; o >>= 1) dot += __shfl_xor_sync(0xffffffffu, dot, o);

    float z = dot + gb[0];
    float cf = 1.f / (1.f + __expf(-z));
    #pragma unroll
    for (int i = 0; i < 16; i++) {
        int c = lane + i * 32;
        out[(size_t)warp * Dc + c] = cf * xr[c] + (1.f - cf) * hr[c];
    }
}

// ---------------------------------------------------------------------------
extern "C" void kernel_launch(void* const* d_in, const int* in_sizes, int n_in,
                              void* d_out, int out_size)
{
    const float* x    = (const float*)d_in[0];
    const float* adj  = (const float*)d_in[1];
    const float* W_w  = (const float*)d_in[2];
    const float* W_b  = (const float*)d_in[3];
    const float* ln_g = (const float*)d_in[4];
    const float* ln_b = (const float*)d_in[5];
    const float* Wq   = (const float*)d_in[6];
    const float* bq   = (const float*)d_in[7];
    const float* Wk   = (const float*)d_in[8];
    const float* bk   = (const float*)d_in[9];
    const float* Wv   = (const float*)d_in[10];
    const float* bv   = (const float*)d_in[11];
    const float* Wo   = (const float*)d_in[12];
    const float* bo   = (const float*)d_in[13];
    const float* gw   = (const float*)d_in[14];
    const float* gb   = (const float*)d_in[15];
    const int* use_adj = (const int*)d_in[16];
    float* out = (float*)d_out;

    float *h, *h2, *bias3;
    __nv_bfloat16 *ahi, *alo, *whi, *wlo, *qhi, *qlo, *khi, *klo, *vhi, *vlo, *vthi, *vtlo;
    cudaGetSymbolAddress((void**)&h,    g_h);
    cudaGetSymbolAddress((void**)&h2,   g_h2);
    cudaGetSymbolAddress((void**)&ahi,  g_ahi);
    cudaGetSymbolAddress((void**)&alo,  g_alo);
    cudaGetSymbolAddress((void**)&qhi,  g_qhi);
    cudaGetSymbolAddress((void**)&qlo,  g_qlo);
    cudaGetSymbolAddress((void**)&khi,  g_khi);
    cudaGetSymbolAddress((void**)&klo,  g_klo);
    cudaGetSymbolAddress((void**)&vhi,  g_vhi);
    cudaGetSymbolAddress((void**)&vlo,  g_vlo);
    cudaGetSymbolAddress((void**)&vthi, g_vthi);
    cudaGetSymbolAddress((void**)&vtlo, g_vtlo);
    cudaGetSymbolAddress((void**)&whi,  g_whi);
    cudaGetSymbolAddress((void**)&wlo,  g_wlo);
    cudaGetSymbolAddress((void**)&bias3, g_bias3);

    cudaFuncSetAttribute(attn_mma_kernel, cudaFuncAttributeMaxDynamicSharedMemorySize, ATTN_SMEM);
    cudaFuncSetAttribute((const void*)mma_gemm_kernel<0>,
                         cudaFuncAttributeMaxDynamicSharedMemorySize, GEMM_SMEM);
    cudaFuncSetAttribute((const void*)mma_gemm_kernel<1>,
                         cudaFuncAttributeMaxDynamicSharedMemorySize, GEMM_SMEM);
    cudaFuncSetAttribute((const void*)mma_gemm_kernel<2>,
                         cudaFuncAttributeMaxDynamicSharedMemorySize, GEMM_SMEM);

    dim3 wgrid(16, 16, 21), wblk(32, 8);
    dim3 g1(Dc / 128, Mrows / 128);        // (4, 64)
    dim3 gq(QKV_LD / 128, Mrows / 128);    // (12, 64)
    dim3 agrid(Nc / 128, Hc, Bc);          // (4, 8, 16)
    dim3 vgrid(Nc / 64, Hc, Bc);           // (8, 8, 16)

    // 1) weight prep + x split (single kernel)
    wprep_kernel<<<wgrid, wblk>>>(W_w, Wq, Wk, Wv, Wo, x, bq, bk, bv,
                                  whi, wlo, ahi, alo, bias3);
    // 2) h = x @ W_w + W_b
    mma_gemm_kernel<0><<<g1, 256, GEMM_SMEM>>>(ahi, alo, whi, wlo, W_b, h, Dc,
        nullptr, nullptr, nullptr, nullptr, nullptr, nullptr);
    // 3) LN(h) -> hi/lo split
    ln_split_kernel<<<Mrows / 8, 256>>>(h, ln_g, ln_b, ahi, alo);
    // 4) fused QKV GEMM -> q hi/lo (pre-scaled), k hi/lo, v hi/lo
    mma_gemm_kernel<2><<<gq, 256, GEMM_SMEM>>>(ahi, alo, whi + DD, wlo + DD, bias3,
        nullptr, 0, qhi, qlo, khi, klo, vhi, vlo);
    // 5) V transpose per (b,h)
    vtprep_kernel<<<vgrid, wblk>>>(vhi, vlo, vthi, vtlo);
    // 6) mma flash attention -> ctx hi/lo (overwrites ahi/alo)
    attn_mma_kernel<<<agrid, 256, ATTN_SMEM>>>(qhi, qlo, khi, klo, vthi, vtlo,
                                               adj, use_adj, ahi, alo);
    // 7) h2 = relu(ctx @ Wo + bo)
    mma_gemm_kernel<1><<<g1, 256, GEMM_SMEM>>>(ahi, alo, whi + 4 * DD, wlo + 4 * DD, bo, h2, Dc,
        nullptr, nullptr, nullptr, nullptr, nullptr, nullptr);
    // 8) gated residual output
    gate_kernel<<<Mrows / 8, 256>>>(x, h2, gw, gb, out);
}